// round 6
// baseline (speedup 1.0000x reference)
#include <cuda_runtime.h>
#include <cuda_bf16.h>
#include <math.h>
#include <stdint.h>

// ---------------- problem constants ----------------
#define S_LEN 2048
#define BATCH 2
#define NTOK  (S_LEN*BATCH)     // 4096
#define NH    16
#define DIM   2048
#define NOPE  128
#define ROPE  64
#define RHALF 32
#define VDIM  128
#define KVR   512
#define QD    (NOPE+ROPE)       // 192
#define QOUT  (NH*QD)           // 3072
#define KVOUT (KVR+ROPE)        // 576
#define DEFF  576
#define LOG2E 1.4426950408889634

typedef long long ll;
typedef __nv_bfloat16 bf16;
typedef __nv_bfloat162 bf162;

// ---------------- scratch: bf16 hi/lo planes + fp32 scores ----------------
__device__ __align__(16) bf16 g_xs_h [(size_t)NTOK*DIM],    g_xs_l [(size_t)NTOK*DIM];
__device__ __align__(16) bf16 g_wqs_h[(size_t)QOUT*DIM],    g_wqs_l[(size_t)QOUT*DIM];
__device__ __align__(16) bf16 g_was_h[(size_t)KVOUT*DIM],   g_was_l[(size_t)KVOUT*DIM];
__device__ __align__(16) bf16 g_wbs_h[(size_t)NH*(NOPE+VDIM)*KVR], g_wbs_l[(size_t)NH*(NOPE+VDIM)*KVR];
__device__ __align__(16) bf16 g_wbT_h[(size_t)NH*KVR*NOPE], g_wbT_l[(size_t)NH*KVR*NOPE];
__device__ __align__(16) bf16 g_wos_h[(size_t)DIM*NH*VDIM], g_wos_l[(size_t)DIM*NH*VDIM];
__device__ __align__(16) bf16 g_qs_h [(size_t)NTOK*QOUT],   g_qs_l [(size_t)NTOK*QOUT];
__device__ __align__(16) bf16 g_kvs_h[(size_t)NTOK*KVOUT],  g_kvs_l[(size_t)NTOK*KVOUT];
__device__ __align__(16) bf16 g_ke_h [(size_t)NTOK*DEFF],   g_ke_l [(size_t)NTOK*DEFF];
__device__ __align__(16) bf16 g_keT_h[(size_t)BATCH*DEFF*S_LEN], g_keT_l[(size_t)BATCH*DEFF*S_LEN];
__device__ __align__(16) bf16 g_qe_h [(size_t)BATCH*NH*S_LEN*DEFF], g_qe_l [(size_t)BATCH*NH*S_LEN*DEFF];
__device__ float g_scores[(size_t)BATCH*NH*S_LEN*S_LEN];
__device__ __align__(16) bf16 g_pr_h [(size_t)BATCH*NH*S_LEN*S_LEN], g_pr_l [(size_t)BATCH*NH*S_LEN*S_LEN];
__device__ __align__(16) bf16 g_ol_h [(size_t)BATCH*NH*S_LEN*KVR],  g_ol_l [(size_t)BATCH*NH*S_LEN*KVR];
__device__ __align__(16) bf16 g_os_h [(size_t)NTOK*NH*VDIM], g_os_l [(size_t)NTOK*NH*VDIM];
__device__ float g_cos[S_LEN*RHALF];
__device__ float g_sin[S_LEN*RHALF];

// ---------------- helpers ----------------
__device__ __forceinline__ float warpMax(float v){
    #pragma unroll
    for (int o=16;o;o>>=1) v = fmaxf(v, __shfl_xor_sync(0xffffffffu, v, o));
    return v;
}
__device__ __forceinline__ float warpSum(float v){
    #pragma unroll
    for (int o=16;o;o>>=1) v += __shfl_xor_sync(0xffffffffu, v, o);
    return v;
}
__device__ __forceinline__ uint32_t smem_u32(const void* p){
    uint32_t a;
    asm("{ .reg .u64 t; cvta.to.shared.u64 t, %1; cvt.u32.u64 %0, t; }" : "=r"(a) : "l"(p));
    return a;
}
__device__ __forceinline__ void split2(float f, bf16& h, bf16& l){
    h = __float2bfloat16_rn(f);
    l = __float2bfloat16_rn(f - __bfloat162float(h));
}
__device__ __forceinline__ float rejoin(bf16 h, bf16 l){
    return __bfloat162float(h) + __bfloat162float(l);
}
__device__ __forceinline__ void mma_bf16(float* d, const uint32_t* a, const uint32_t* b){
    asm volatile(
        "mma.sync.aligned.m16n8k16.row.col.f32.bf16.bf16.f32 "
        "{%0,%1,%2,%3}, {%4,%5,%6,%7}, {%8,%9}, {%0,%1,%2,%3};"
        : "+f"(d[0]), "+f"(d[1]), "+f"(d[2]), "+f"(d[3])
        : "r"(a[0]), "r"(a[1]), "r"(a[2]), "r"(a[3]), "r"(b[0]), "r"(b[1]));
}
__device__ __forceinline__ void ldsm4(uint32_t* r, uint32_t a){
    asm volatile("ldmatrix.sync.aligned.m8n8.x4.shared.b16 {%0,%1,%2,%3}, [%4];"
        : "=r"(r[0]), "=r"(r[1]), "=r"(r[2]), "=r"(r[3]) : "r"(a));
}
__device__ __forceinline__ void cp16(uint32_t dst, const void* src){
    asm volatile("cp.async.cg.shared.global [%0], [%1], 16;\n" :: "r"(dst), "l"(src) : "memory");
}
__device__ __forceinline__ void cp_commit(){ asm volatile("cp.async.commit_group;\n" ::: "memory"); }
template<int N>
__device__ __forceinline__ void cp_wait(){ asm volatile("cp.async.wait_group %0;\n" :: "n"(N) : "memory"); }

// swizzle for 64B rows: XOR bits[5:4] with bits[8:7]
__device__ __forceinline__ uint32_t swz(uint32_t o){ return o ^ ((o>>3)&0x30u); }

// ---------------- split kernels ----------------
__global__ void split_arr(const float4* __restrict__ src, bf16* __restrict__ h, bf16* __restrict__ l, int n4){
    int i = blockIdx.x*blockDim.x + threadIdx.x;
    if (i >= n4) return;
    float4 v = src[i];
    bf16 h0,l0,h1,l1,h2,l2,h3,l3;
    split2(v.x,h0,l0); split2(v.y,h1,l1); split2(v.z,h2,l2); split2(v.w,h3,l3);
    bf162* hp = (bf162*)(h + 4*(size_t)i);
    bf162* lp = (bf162*)(l + 4*(size_t)i);
    bf162 a; a.x=h0; a.y=h1; hp[0]=a;
    bf162 b; b.x=h2; b.y=h3; hp[1]=b;
    bf162 c; c.x=l0; c.y=l1; lp[0]=c;
    bf162 d; d.x=l2; d.y=l3; lp[1]=d;
}
__global__ void splitT_wkvb(const float* __restrict__ wb){
    int i = blockIdx.x*blockDim.x + threadIdx.x;
    if (i >= NH*KVR*NOPE) return;
    int d = i % NOPE, c = (i/NOPE) % KVR, h = i/(NOPE*KVR);
    float v = wb[((size_t)h*(NOPE+VDIM) + d)*KVR + c];
    split2(v, g_wbT_h[i], g_wbT_l[i]);
}

// ---------------- prep kernels ----------------
__global__ void rope_prep_kernel(const float* __restrict__ ang){
    int i = blockIdx.x*blockDim.x + threadIdx.x;
    if (i < S_LEN*RHALF){
        float a = ang[i];
        g_cos[i] = cosf(a);
        g_sin[i] = sinf(a);
    }
}

__global__ void prep_keff_kernel(const float* __restrict__ kvw){
    int t = blockIdx.x;
    int b = t / S_LEN, s = t % S_LEN;
    int tid = threadIdx.x;
    float v[4];
    #pragma unroll
    for (int j=0;j<4;j++){
        size_t idx = (size_t)t*KVOUT + 4*tid + j;
        v[j] = rejoin(g_kvs_h[idx], g_kvs_l[idx]);
    }
    float ss = v[0]*v[0]+v[1]*v[1]+v[2]*v[2]+v[3]*v[3];
    ss = warpSum(ss);
    __shared__ float red[4];
    if ((tid&31)==0) red[tid>>5] = ss;
    __syncthreads();
    float tot = red[0]+red[1]+red[2]+red[3];
    float r = rsqrtf(tot*(1.0f/KVR) + 1e-6f);
    #pragma unroll
    for (int j=0;j<4;j++){
        int c = 4*tid + j;
        float o = v[j]*r*kvw[c];
        bf16 h,l; split2(o,h,l);
        size_t di = (size_t)t*DEFF + c;
        g_ke_h[di]=h; g_ke_l[di]=l;
        size_t ti = ((size_t)b*DEFF + c)*S_LEN + s;
        g_keT_h[ti]=h; g_keT_l[ti]=l;
    }
    if (tid < RHALF){
        size_t pi = (size_t)t*KVOUT + KVR + 2*tid;
        float xr = rejoin(g_kvs_h[pi],   g_kvs_l[pi]);
        float xi = rejoin(g_kvs_h[pi+1], g_kvs_l[pi+1]);
        float c  = g_cos[s*RHALF+tid], sn = g_sin[s*RHALF+tid];
        float yr = xr*c - xi*sn, yi = xr*sn + xi*c;
        bf16 hr,lr,hi2,li; split2(yr,hr,lr); split2(yi,hi2,li);
        size_t di = (size_t)t*DEFF + KVR + 2*tid;
        g_ke_h[di]=hr; g_ke_l[di]=lr; g_ke_h[di+1]=hi2; g_ke_l[di+1]=li;
        size_t t0 = ((size_t)b*DEFF + KVR + 2*tid)*S_LEN + s;
        size_t t1 = ((size_t)b*DEFF + KVR + 2*tid + 1)*S_LEN + s;
        g_keT_h[t0]=hr; g_keT_l[t0]=lr; g_keT_h[t1]=hi2; g_keT_l[t1]=li;
    }
}

__global__ void prep_qpe_kernel(){
    int t = blockIdx.x, h = blockIdx.y;
    int b = t / S_LEN, s = t % S_LEN;
    int i = threadIdx.x;   // 0..31
    size_t si = (size_t)t*QOUT + h*QD + NOPE + 2*i;
    float xr = rejoin(g_qs_h[si],   g_qs_l[si]);
    float xi = rejoin(g_qs_h[si+1], g_qs_l[si+1]);
    float c  = g_cos[s*RHALF+i], sn = g_sin[s*RHALF+i];
    float yr = xr*c - xi*sn, yi = xr*sn + xi*c;
    size_t di = ((size_t)(b*NH+h)*S_LEN + s)*DEFF + KVR + 2*i;
    bf16 hh,ll_; split2(yr,hh,ll_); g_qe_h[di]=hh;   g_qe_l[di]=ll_;
    split2(yi,hh,ll_);              g_qe_h[di+1]=hh; g_qe_l[di+1]=ll_;
}

// ---------------- bf16x3 split GEMM with ldmatrix ----------------
// C = alpha * (Ah+Al)[M,K] @ (Bh+Bl)[N,K]^T   (operands K-contiguous)
// BN=256: 64x64 warp tiles, 4 stages, 1 CTA/SM.  BN=128/64: legacy config, 2 CTA/SM.
template<int BN_T, bool SPLIT_OUT>
__global__ __launch_bounds__(256, (BN_T==256)?1:2) void mma_gemm(
    const bf16* __restrict__ Ah, const bf16* __restrict__ Al,
    const bf16* __restrict__ Bh, const bf16* __restrict__ Bl,
    float* __restrict__ Cf, bf16* __restrict__ Ch, bf16* __restrict__ Cl,
    int K, int lda, int ldb, int ldc, int zdiv,
    ll zA1, ll zA2, ll zB1, ll zB2, ll zC1, ll zC2,
    float alpha, int causal, int klimit)
{
    if (causal && (ll)blockIdx.x*BN_T > (ll)blockIdx.y*128 + 127) return;
    constexpr int NST = (BN_T==256)?4:3;
    constexpr int WN  = (BN_T==256)?4:(BN_T/32);
    constexpr int WM  = 8/WN;
    constexpr int WTM = 128/WM;
    constexpr int WTN = BN_T/WN;
    constexpr int MF  = WTM/16;
    constexpr int NF  = WTN/8;
    constexpr int SA  = 128*64;        // 8KB per A plane per stage
    constexpr int SB  = BN_T*64;
    constexpr int STG = 2*SA + 2*SB;

    extern __shared__ char smc[];
    const uint32_t sbase = smem_u32(smc);

    const int tid = threadIdx.x, lane = tid & 31, wid = tid >> 5;
    const int wm = wid / WN, wn = wid % WN;
    const int grp = lane >> 2, tig = lane & 3;
    const int lrow = lane & 7, sub = lane >> 3;
    const int zl = blockIdx.z % zdiv, zh = blockIdx.z / zdiv;
    const ll n0 = (ll)blockIdx.x * BN_T;

    // ldmatrix lane address components
    const int aRowB = wm*WTM + ((sub&1)<<3) + lrow;  // + mf*16
    const int aKo   = (sub>>1)<<4;                   // + ck
    const int bRowB = wn*WTN + ((sub>>1)<<3) + lrow; // + nfp*16
    const int bKo   = (sub&1)<<4;                    // + ck

    const ll aoff = zl*zA1 + zh*zA2 + (ll)blockIdx.y*128*lda;
    const bf16* Ahb = Ah + aoff;
    const bf16* Alb = Al + aoff;
    const ll boff = zl*zB1 + zh*zB2 + n0*ldb;
    const bf16* Bhb = Bh + boff;
    const bf16* Blb = Bl + boff;

    int kEnd = K;
    if (klimit){ int kl = ((int)blockIdx.y + 1)*128; if (kl < kEnd) kEnd = kl; }
    const int nk = kEnd >> 5;

    float acc[MF][NF][4];
    #pragma unroll
    for (int i=0;i<MF;i++)
        #pragma unroll
        for (int j=0;j<NF;j++)
            #pragma unroll
            for (int c=0;c<4;c++) acc[i][j][c] = 0.f;

    const int row = tid >> 2, g = tid & 3;

    auto LOAD = [&](int kb){
        const int s = kb % NST;
        const uint32_t ub = sbase + (uint32_t)(s*STG);
        const ll koff = ((ll)kb << 5) + g*8;
        #pragma unroll
        for (int i=0;i<2;i++){
            int r = row + i*64;
            uint32_t o = swz((uint32_t)(r*64 + g*16));
            cp16(ub + o,      Ahb + (ll)r*lda + koff);
            cp16(ub + SA + o, Alb + (ll)r*lda + koff);
        }
        #pragma unroll
        for (int i=0;i<BN_T/64;i++){
            int r = row + i*64;
            uint32_t o = swz((uint32_t)(r*64 + g*16));
            cp16(ub + 2*SA + o,      Bhb + (ll)r*ldb + koff);
            cp16(ub + 2*SA + SB + o, Blb + (ll)r*ldb + koff);
        }
        cp_commit();
    };

    #pragma unroll
    for (int kb=0; kb<NST-1; kb++) if (kb < nk) LOAD(kb);

    for (int k=0; k<nk; k++){
        cp_wait<NST-2>();
        __syncthreads();
        if (k + NST - 1 < nk) LOAD(k + NST - 1);
        else cp_commit();

        const int s = k % NST;
        const uint32_t AH = sbase + (uint32_t)(s*STG);
        const uint32_t AL = AH + SA;
        const uint32_t BH = AH + 2*SA;
        const uint32_t BL = BH + SB;

        #pragma unroll
        for (int kk=0; kk<2; kk++){
            const int ck = kk*32;
            uint32_t bh[2*NF], bl[2*NF];
            #pragma unroll
            for (int nfp=0; nfp<NF/2; nfp++){
                uint32_t bo = swz((uint32_t)((bRowB + nfp*16)*64 + ck + bKo));
                ldsm4(&bh[4*nfp], BH + bo);
                ldsm4(&bl[4*nfp], BL + bo);
            }
            #pragma unroll
            for (int mf=0; mf<MF; mf++){
                uint32_t ao = swz((uint32_t)((aRowB + mf*16)*64 + ck + aKo));
                uint32_t ah[4], al[4];
                ldsm4(ah, AH + ao);
                ldsm4(al, AL + ao);
                #pragma unroll
                for (int nf=0; nf<NF; nf++) mma_bf16(acc[mf][nf], ah, &bh[2*nf]);
                #pragma unroll
                for (int nf=0; nf<NF; nf++) mma_bf16(acc[mf][nf], ah, &bl[2*nf]);
                #pragma unroll
                for (int nf=0; nf<NF; nf++) mma_bf16(acc[mf][nf], al, &bh[2*nf]);
            }
        }
    }

    // ---- epilogue ----
    const ll cbase = zl*zC1 + zh*zC2
                   + ((ll)blockIdx.y*128 + wm*WTM)*ldc + n0 + wn*WTN;
    #pragma unroll
    for (int mf=0; mf<MF; mf++){
        int r0 = mf*16 + grp;
        #pragma unroll
        for (int nf=0; nf<NF; nf++){
            int c = nf*8 + tig*2;
            #pragma unroll
            for (int half=0; half<2; half++){
                ll off = cbase + (ll)(r0 + half*8)*ldc + c;
                float v0 = acc[mf][nf][2*half+0]*alpha;
                float v1 = acc[mf][nf][2*half+1]*alpha;
                if (SPLIT_OUT){
                    bf16 h0,l0,h1,l1;
                    split2(v0,h0,l0); split2(v1,h1,l1);
                    bf162 hp; hp.x=h0; hp.y=h1;
                    bf162 lp; lp.x=l0; lp.y=l1;
                    *(bf162*)(Ch + off) = hp;
                    *(bf162*)(Cl + off) = lp;
                } else {
                    float2 o; o.x=v0; o.y=v1;
                    *(float2*)(Cf + off) = o;
                }
            }
        }
    }
}

// ---------------- causal softmax (single global read, single exp pass) ----------------
__global__ void softmax_kernel(){
    const int s = blockIdx.x;
    const ll z = blockIdx.y;
    const float* row = g_scores + (z*S_LEN + (ll)s)*S_LEN;
    bf16* ph = g_pr_h + (z*S_LEN + (ll)s)*S_LEN;
    bf16* pl = g_pr_l + (z*S_LEN + (ll)s)*S_LEN;
    const int n = s + 1;
    const int nend = ((s>>7)+1)<<7;   // 128-aligned (PV reads whole 128-blocks)
    const int tid = threadIdx.x;

    float e[16];
    float mx = -1e30f;
    #pragma unroll
    for (int i=0;i<16;i++){
        int t = tid + i*128;
        e[i] = (t < n) ? row[t] : -1e30f;
        mx = fmaxf(mx, e[i]);
    }
    mx = warpMax(mx);
    __shared__ float redm[4], reds[4];
    if ((tid&31)==0) redm[tid>>5] = mx;
    __syncthreads();
    mx = fmaxf(fmaxf(redm[0],redm[1]), fmaxf(redm[2],redm[3]));

    float sum = 0.f;
    #pragma unroll
    for (int i=0;i<16;i++){
        int t = tid + i*128;
        float v = (t < n) ? exp2f(e[i] - mx) : 0.f;
        e[i] = v;
        sum += v;
    }
    sum = warpSum(sum);
    if ((tid&31)==0) reds[tid>>5] = sum;
    __syncthreads();
    sum = reds[0]+reds[1]+reds[2]+reds[3];
    const float inv = 1.0f / sum;

    #pragma unroll
    for (int i=0;i<16;i++){
        int t = tid + i*128;
        if (t < nend){
            float p = e[i]*inv;
            bf16 h,l; split2(p,h,l);
            ph[t]=h; pl[t]=l;
        }
    }
}

// ---------------- host side ----------------
static void launch_g(int BN, bool split,
    const bf16* Ah, const bf16* Al, const bf16* Bh, const bf16* Bl,
    float* Cf, bf16* Ch, bf16* Cl,
    int M, int N, int K, int lda, int ldb, int ldc,
    int Z, int zdiv,
    ll zA1, ll zA2, ll zB1, ll zB2, ll zC1, ll zC2,
    float alpha, bool causal, bool klimit)
{
    dim3 grid(N/BN, M/128, Z);
    int c = causal?1:0, kl = klimit?1:0;
    int nst = (BN==256)?4:3;
    size_t sm = (size_t)nst * (2*128*64 + 2*(size_t)BN*64);
    if (BN == 256){
        if (split){
            cudaFuncSetAttribute(mma_gemm<256,true>, cudaFuncAttributeMaxDynamicSharedMemorySize, (int)sm);
            mma_gemm<256,true><<<grid,256,sm>>>(Ah,Al,Bh,Bl,Cf,Ch,Cl,K,lda,ldb,ldc,zdiv,zA1,zA2,zB1,zB2,zC1,zC2,alpha,c,kl);
        } else {
            cudaFuncSetAttribute(mma_gemm<256,false>, cudaFuncAttributeMaxDynamicSharedMemorySize, (int)sm);
            mma_gemm<256,false><<<grid,256,sm>>>(Ah,Al,Bh,Bl,Cf,Ch,Cl,K,lda,ldb,ldc,zdiv,zA1,zA2,zB1,zB2,zC1,zC2,alpha,c,kl);
        }
    } else if (BN == 128){
        if (split){
            cudaFuncSetAttribute(mma_gemm<128,true>, cudaFuncAttributeMaxDynamicSharedMemorySize, (int)sm);
            mma_gemm<128,true><<<grid,256,sm>>>(Ah,Al,Bh,Bl,Cf,Ch,Cl,K,lda,ldb,ldc,zdiv,zA1,zA2,zB1,zB2,zC1,zC2,alpha,c,kl);
        } else {
            cudaFuncSetAttribute(mma_gemm<128,false>, cudaFuncAttributeMaxDynamicSharedMemorySize, (int)sm);
            mma_gemm<128,false><<<grid,256,sm>>>(Ah,Al,Bh,Bl,Cf,Ch,Cl,K,lda,ldb,ldc,zdiv,zA1,zA2,zB1,zB2,zC1,zC2,alpha,c,kl);
        }
    } else {
        cudaFuncSetAttribute(mma_gemm<64,true>, cudaFuncAttributeMaxDynamicSharedMemorySize, (int)sm);
        mma_gemm<64,true><<<grid,256,sm>>>(Ah,Al,Bh,Bl,Cf,Ch,Cl,K,lda,ldb,ldc,zdiv,zA1,zA2,zB1,zB2,zC1,zC2,alpha,c,kl);
    }
}

#define SYM(p, s) cudaGetSymbolAddress((void**)&p, s)

extern "C" void kernel_launch(void* const* d_in, const int* in_sizes, int n_in,
                              void* d_out, int out_size)
{
    (void)in_sizes; (void)n_in; (void)out_size;
    const float* x      = (const float*)d_in[0];
    const float* angles = (const float*)d_in[1];
    const float* wq     = (const float*)d_in[2];
    const float* wkv_a  = (const float*)d_in[3];
    const float* wkv_b  = (const float*)d_in[4];
    const float* wo     = (const float*)d_in[5];
    const float* kvw    = (const float*)d_in[6];
    float* out = (float*)d_out;

    bf16 *xsh,*xsl,*wqh,*wql,*wah,*wal,*wbh,*wbl,*wbTh,*wbTl,*woh,*wol;
    bf16 *qsh,*qsl,*keh,*kel,*keTh,*keTl,*qeh,*qel,*prh,*prl,*olh,*oll,*osh,*osl,*kvh,*kvl;
    float *sc;
    SYM(xsh,g_xs_h); SYM(xsl,g_xs_l); SYM(wqh,g_wqs_h); SYM(wql,g_wqs_l);
    SYM(wah,g_was_h); SYM(wal,g_was_l); SYM(wbh,g_wbs_h); SYM(wbl,g_wbs_l);
    SYM(wbTh,g_wbT_h); SYM(wbTl,g_wbT_l); SYM(woh,g_wos_h); SYM(wol,g_wos_l);
    SYM(qsh,g_qs_h); SYM(qsl,g_qs_l); SYM(kvh,g_kvs_h); SYM(kvl,g_kvs_l);
    SYM(keh,g_ke_h); SYM(kel,g_ke_l); SYM(keTh,g_keT_h); SYM(keTl,g_keT_l);
    SYM(qeh,g_qe_h); SYM(qel,g_qe_l); SYM(prh,g_pr_h); SYM(prl,g_pr_l);
    SYM(olh,g_ol_h); SYM(oll,g_ol_l); SYM(osh,g_os_h); SYM(osl,g_os_l);
    SYM(sc,g_scores);

    const double msc = 0.1*log(40.0) + 1.0;
    const float softmax_scale = (float)(pow((double)QD, -0.5)*msc*msc);
    const float score_alpha = (float)((double)softmax_scale * LOG2E);

    // 0) split inputs into bf16 hi/lo planes
    {
        int n;
        n = NTOK*DIM/4;            split_arr<<<(n+255)/256,256>>>((const float4*)x, xsh, xsl, n);
        n = QOUT*DIM/4;            split_arr<<<(n+255)/256,256>>>((const float4*)wq, wqh, wql, n);
        n = KVOUT*DIM/4;           split_arr<<<(n+255)/256,256>>>((const float4*)wkv_a, wah, wal, n);
        n = NH*(NOPE+VDIM)*KVR/4;  split_arr<<<(n+255)/256,256>>>((const float4*)wkv_b, wbh, wbl, n);
        n = DIM*NH*VDIM/4;         split_arr<<<(n+255)/256,256>>>((const float4*)wo, woh, wol, n);
        n = NH*KVR*NOPE;           splitT_wkvb<<<(n+255)/256,256>>>(wkv_b);
    }
    rope_prep_kernel<<<(S_LEN*RHALF+127)/128, 128>>>(angles);

    // 1) q = x @ wq^T  (4096x3072, K=2048)
    launch_g(256,true, xsh,xsl, wqh,wql, 0, qsh,qsl,
             NTOK, QOUT, DIM, DIM, DIM, QOUT, 1,1, 0,0,0,0,0,0, 1.f,false,false);

    // 2) kv = x @ wkv_a^T  (512 + 64)
    launch_g(256,true, xsh,xsl, wah,wal, 0, kvh,kvl,
             NTOK, 512, DIM, DIM, DIM, KVOUT, 1,1, 0,0,0,0,0,0, 1.f,false,false);
    launch_g(64,true, xsh,xsl, wah+(size_t)512*DIM, wal+(size_t)512*DIM, 0, kvh+512, kvl+512,
             NTOK, 64, DIM, DIM, DIM, KVOUT, 1,1, 0,0,0,0,0,0, 1.f,false,false);

    // 3) keff planes (+ transposed copy)
    prep_keff_kernel<<<NTOK, 128>>>(kvw);

    // 4) rope(q_pe) -> qeff[...,512:576]
    prep_qpe_kernel<<<dim3(NTOK, NH), 32>>>();

    // 5) qeff[...,0:512] = q_nope @ wkv_bT  (per (b,h), K=128)
    launch_g(256,true, qsh,qsl, wbTh,wbTl, 0, qeh,qel,
             S_LEN, KVR, NOPE, QOUT, NOPE, DEFF, BATCH*NH, NH,
             (ll)QD, (ll)S_LEN*QOUT, (ll)KVR*NOPE, 0,
             (ll)S_LEN*DEFF, (ll)NH*S_LEN*DEFF, 1.f,false,false);

    // 6) scores = scale*log2e * qeff @ keff^T  (causal block-skip)
    launch_g(256,false, qeh,qel, keh,kel, sc, 0,0,
             S_LEN, S_LEN, DEFF, DEFF, DEFF, S_LEN, BATCH*NH, NH,
             (ll)S_LEN*DEFF, (ll)NH*S_LEN*DEFF, 0, (ll)S_LEN*DEFF,
             (ll)S_LEN*S_LEN, (ll)NH*S_LEN*S_LEN, score_alpha, true, false);

    // 7) softmax -> probs planes
    softmax_kernel<<<dim3(S_LEN, BATCH*NH), 128>>>();

    // 8) olat = probs @ keffT^T  (K causally capped)
    launch_g(256,true, prh,prl, keTh,keTl, 0, olh,oll,
             S_LEN, KVR, S_LEN, S_LEN, S_LEN, KVR, BATCH*NH, NH,
             (ll)S_LEN*S_LEN, (ll)NH*S_LEN*S_LEN, 0, (ll)DEFF*S_LEN,
             (ll)S_LEN*KVR, (ll)NH*S_LEN*KVR, 1.f, false, true);

    // 9) o[:, h*128:(h+1)*128] = olat_h @ wkv_b_v^T  (per (b,h), K=512)
    launch_g(128,true, olh,oll, wbh+(size_t)NOPE*KVR, wbl+(size_t)NOPE*KVR, 0, osh,osl,
             S_LEN, VDIM, KVR, KVR, KVR, NH*VDIM, BATCH*NH, NH,
             (ll)S_LEN*KVR, (ll)NH*S_LEN*KVR, (ll)(NOPE+VDIM)*KVR, 0,
             (ll)VDIM, (ll)S_LEN*NH*VDIM, 1.f, false, false);

    // 10) out = o @ wo^T  (4096x2048, K=2048, fp32 output)
    launch_g(256,false, osh,osl, woh,wol, out, 0,0,
             NTOK, DIM, NH*VDIM, NH*VDIM, NH*VDIM, DIM, 1,1,
             0,0,0,0,0,0, 1.f,false,false);
}

// round 7
// speedup vs baseline: 1.1015x; 1.1015x over previous
#include <cuda_runtime.h>
#include <cuda_bf16.h>
#include <math.h>
#include <stdint.h>

// ---------------- problem constants ----------------
#define S_LEN 2048
#define BATCH 2
#define NTOK  (S_LEN*BATCH)     // 4096
#define NH    16
#define DIM   2048
#define NOPE  128
#define ROPE  64
#define RHALF 32
#define VDIM  128
#define KVR   512
#define QD    (NOPE+ROPE)       // 192
#define QOUT  (NH*QD)           // 3072
#define KVOUT (KVR+ROPE)        // 576
#define KVPAD 640               // kv-proj N padded to 5*128
#define DEFF  576
#define LOG2E 1.4426950408889634

typedef long long ll;
typedef __nv_bfloat16 bf16;
typedef __nv_bfloat162 bf162;

// ---------------- scratch: bf16 hi/lo planes + fp32 scores ----------------
__device__ __align__(16) bf16 g_xs_h [(size_t)NTOK*DIM],    g_xs_l [(size_t)NTOK*DIM];
__device__ __align__(16) bf16 g_wqs_h[(size_t)QOUT*DIM],    g_wqs_l[(size_t)QOUT*DIM];
__device__ __align__(16) bf16 g_was_h[(size_t)KVPAD*DIM],   g_was_l[(size_t)KVPAD*DIM];
__device__ __align__(16) bf16 g_wbs_h[(size_t)NH*(NOPE+VDIM)*KVR], g_wbs_l[(size_t)NH*(NOPE+VDIM)*KVR];
__device__ __align__(16) bf16 g_wbT_h[(size_t)NH*KVR*NOPE], g_wbT_l[(size_t)NH*KVR*NOPE];
__device__ __align__(16) bf16 g_wos_h[(size_t)DIM*NH*VDIM], g_wos_l[(size_t)DIM*NH*VDIM];
__device__ __align__(16) bf16 g_qs_h [(size_t)NTOK*QOUT],   g_qs_l [(size_t)NTOK*QOUT];
__device__ __align__(16) bf16 g_kvs_h[(size_t)NTOK*KVPAD],  g_kvs_l[(size_t)NTOK*KVPAD];
__device__ __align__(16) bf16 g_ke_h [(size_t)NTOK*DEFF],   g_ke_l [(size_t)NTOK*DEFF];
__device__ __align__(16) bf16 g_keT_h[(size_t)BATCH*DEFF*S_LEN], g_keT_l[(size_t)BATCH*DEFF*S_LEN];
__device__ __align__(16) bf16 g_qe_h [(size_t)BATCH*NH*S_LEN*DEFF], g_qe_l [(size_t)BATCH*NH*S_LEN*DEFF];
__device__ float g_scores[(size_t)BATCH*NH*S_LEN*S_LEN];
__device__ __align__(16) bf16 g_pr_h [(size_t)BATCH*NH*S_LEN*S_LEN], g_pr_l [(size_t)BATCH*NH*S_LEN*S_LEN];
__device__ __align__(16) bf16 g_ol_h [(size_t)BATCH*NH*S_LEN*KVR],  g_ol_l [(size_t)BATCH*NH*S_LEN*KVR];
__device__ __align__(16) bf16 g_os_h [(size_t)NTOK*NH*VDIM], g_os_l [(size_t)NTOK*NH*VDIM];
__device__ float g_cos[S_LEN*RHALF];
__device__ float g_sin[S_LEN*RHALF];

// ---------------- helpers ----------------
__device__ __forceinline__ float warpMax(float v){
    #pragma unroll
    for (int o=16;o;o>>=1) v = fmaxf(v, __shfl_xor_sync(0xffffffffu, v, o));
    return v;
}
__device__ __forceinline__ float warpSum(float v){
    #pragma unroll
    for (int o=16;o;o>>=1) v += __shfl_xor_sync(0xffffffffu, v, o);
    return v;
}
__device__ __forceinline__ uint32_t smem_u32(const void* p){
    uint32_t a;
    asm("{ .reg .u64 t; cvta.to.shared.u64 t, %1; cvt.u32.u64 %0, t; }" : "=r"(a) : "l"(p));
    return a;
}
__device__ __forceinline__ void split2(float f, bf16& h, bf16& l){
    h = __float2bfloat16_rn(f);
    l = __float2bfloat16_rn(f - __bfloat162float(h));
}
__device__ __forceinline__ float rejoin(bf16 h, bf16 l){
    return __bfloat162float(h) + __bfloat162float(l);
}
__device__ __forceinline__ void mma_bf16(float* d, const uint32_t* a, const uint32_t* b){
    asm volatile(
        "mma.sync.aligned.m16n8k16.row.col.f32.bf16.bf16.f32 "
        "{%0,%1,%2,%3}, {%4,%5,%6,%7}, {%8,%9}, {%0,%1,%2,%3};"
        : "+f"(d[0]), "+f"(d[1]), "+f"(d[2]), "+f"(d[3])
        : "r"(a[0]), "r"(a[1]), "r"(a[2]), "r"(a[3]), "r"(b[0]), "r"(b[1]));
}
__device__ __forceinline__ void ldsm4(uint32_t* r, uint32_t a){
    asm volatile("ldmatrix.sync.aligned.m8n8.x4.shared.b16 {%0,%1,%2,%3}, [%4];"
        : "=r"(r[0]), "=r"(r[1]), "=r"(r[2]), "=r"(r[3]) : "r"(a));
}
__device__ __forceinline__ void cp16(uint32_t dst, const void* src){
    asm volatile("cp.async.cg.shared.global [%0], [%1], 16;\n" :: "r"(dst), "l"(src) : "memory");
}
__device__ __forceinline__ void cp_commit(){ asm volatile("cp.async.commit_group;\n" ::: "memory"); }
template<int N>
__device__ __forceinline__ void cp_wait(){ asm volatile("cp.async.wait_group %0;\n" :: "n"(N) : "memory"); }

// swizzle for 64B rows: XOR bits[5:4] with bits[8:7]
__device__ __forceinline__ uint32_t swz(uint32_t o){ return o ^ ((o>>3)&0x30u); }

// ---------------- split kernels ----------------
__global__ void split_arr(const float4* __restrict__ src, bf16* __restrict__ h, bf16* __restrict__ l, int n4){
    int i = blockIdx.x*blockDim.x + threadIdx.x;
    if (i >= n4) return;
    float4 v = src[i];
    bf16 h0,l0,h1,l1,h2,l2,h3,l3;
    split2(v.x,h0,l0); split2(v.y,h1,l1); split2(v.z,h2,l2); split2(v.w,h3,l3);
    bf162* hp = (bf162*)(h + 4*(size_t)i);
    bf162* lp = (bf162*)(l + 4*(size_t)i);
    bf162 a; a.x=h0; a.y=h1; hp[0]=a;
    bf162 b; b.x=h2; b.y=h3; hp[1]=b;
    bf162 c; c.x=l0; c.y=l1; lp[0]=c;
    bf162 d; d.x=l2; d.y=l3; lp[1]=d;
}
__global__ void zero_tail_was(){
    int i = blockIdx.x*blockDim.x + threadIdx.x;
    if (i < (KVPAD-KVOUT)*DIM){
        bf16 z = __float2bfloat16_rn(0.f);
        g_was_h[(size_t)KVOUT*DIM + i] = z;
        g_was_l[(size_t)KVOUT*DIM + i] = z;
    }
}
__global__ void splitT_wkvb(const float* __restrict__ wb){
    int i = blockIdx.x*blockDim.x + threadIdx.x;
    if (i >= NH*KVR*NOPE) return;
    int d = i % NOPE, c = (i/NOPE) % KVR, h = i/(NOPE*KVR);
    float v = wb[((size_t)h*(NOPE+VDIM) + d)*KVR + c];
    split2(v, g_wbT_h[i], g_wbT_l[i]);
}

// ---------------- prep kernels ----------------
__global__ void rope_prep_kernel(const float* __restrict__ ang){
    int i = blockIdx.x*blockDim.x + threadIdx.x;
    if (i < S_LEN*RHALF){
        float a = ang[i];
        g_cos[i] = cosf(a);
        g_sin[i] = sinf(a);
    }
}

__global__ void prep_keff_kernel(const float* __restrict__ kvw){
    int t = blockIdx.x;
    int b = t / S_LEN, s = t % S_LEN;
    int tid = threadIdx.x;
    float v[4];
    #pragma unroll
    for (int j=0;j<4;j++){
        size_t idx = (size_t)t*KVPAD + 4*tid + j;
        v[j] = rejoin(g_kvs_h[idx], g_kvs_l[idx]);
    }
    float ss = v[0]*v[0]+v[1]*v[1]+v[2]*v[2]+v[3]*v[3];
    ss = warpSum(ss);
    __shared__ float red[4];
    if ((tid&31)==0) red[tid>>5] = ss;
    __syncthreads();
    float tot = red[0]+red[1]+red[2]+red[3];
    float r = rsqrtf(tot*(1.0f/KVR) + 1e-6f);
    #pragma unroll
    for (int j=0;j<4;j++){
        int c = 4*tid + j;
        float o = v[j]*r*kvw[c];
        bf16 h,l; split2(o,h,l);
        size_t di = (size_t)t*DEFF + c;
        g_ke_h[di]=h; g_ke_l[di]=l;
        size_t ti = ((size_t)b*DEFF + c)*S_LEN + s;
        g_keT_h[ti]=h; g_keT_l[ti]=l;
    }
    if (tid < RHALF){
        size_t pi = (size_t)t*KVPAD + KVR + 2*tid;
        float xr = rejoin(g_kvs_h[pi],   g_kvs_l[pi]);
        float xi = rejoin(g_kvs_h[pi+1], g_kvs_l[pi+1]);
        float c  = g_cos[s*RHALF+tid], sn = g_sin[s*RHALF+tid];
        float yr = xr*c - xi*sn, yi = xr*sn + xi*c;
        bf16 hr,lr,hi2,li; split2(yr,hr,lr); split2(yi,hi2,li);
        size_t di = (size_t)t*DEFF + KVR + 2*tid;
        g_ke_h[di]=hr; g_ke_l[di]=lr; g_ke_h[di+1]=hi2; g_ke_l[di+1]=li;
        size_t t0 = ((size_t)b*DEFF + KVR + 2*tid)*S_LEN + s;
        size_t t1 = ((size_t)b*DEFF + KVR + 2*tid + 1)*S_LEN + s;
        g_keT_h[t0]=hr; g_keT_l[t0]=lr; g_keT_h[t1]=hi2; g_keT_l[t1]=li;
    }
}

// one block per token, 512 threads = 16 heads x 32 rope pairs
__global__ void prep_qpe_kernel(){
    int t = blockIdx.x;
    int b = t / S_LEN, s = t % S_LEN;
    int h = threadIdx.x >> 5, i = threadIdx.x & 31;
    size_t si = (size_t)t*QOUT + h*QD + NOPE + 2*i;
    float xr = rejoin(g_qs_h[si],   g_qs_l[si]);
    float xi = rejoin(g_qs_h[si+1], g_qs_l[si+1]);
    float c  = g_cos[s*RHALF+i], sn = g_sin[s*RHALF+i];
    float yr = xr*c - xi*sn, yi = xr*sn + xi*c;
    size_t di = ((size_t)(b*NH+h)*S_LEN + s)*DEFF + KVR + 2*i;
    bf16 hh,ll_; split2(yr,hh,ll_); g_qe_h[di]=hh;   g_qe_l[di]=ll_;
    split2(yi,hh,ll_);              g_qe_h[di+1]=hh; g_qe_l[di+1]=ll_;
}

// ---------------- bf16x3 split GEMM with ldmatrix ----------------
// C = alpha * (Ah+Al)[M,K] @ (Bh+Bl)[N,K]^T   (operands K-contiguous)
// Proven config: BN=128, 64x32 warp tiles, 3 stages, 2 CTA/SM.
template<int BN_T, bool SPLIT_OUT>
__global__ __launch_bounds__(256,2) void mma_gemm(
    const bf16* __restrict__ Ah, const bf16* __restrict__ Al,
    const bf16* __restrict__ Bh, const bf16* __restrict__ Bl,
    float* __restrict__ Cf, bf16* __restrict__ Ch, bf16* __restrict__ Cl,
    int K, int lda, int ldb, int ldc, int zdiv,
    ll zA1, ll zA2, ll zB1, ll zB2, ll zC1, ll zC2,
    float alpha, int causal, int klimit)
{
    if (causal && blockIdx.x > blockIdx.y) return;
    constexpr int NST = 3;
    constexpr int WN  = BN_T/32;
    constexpr int WM  = 8/WN;
    constexpr int WTM = 128/WM;
    constexpr int MF  = WTM/16;
    constexpr int NF  = 4;
    constexpr int SA  = 128*64;        // 8KB per A plane per stage
    constexpr int SB  = BN_T*64;
    constexpr int STG = 2*SA + 2*SB;

    extern __shared__ char smc[];
    const uint32_t sbase = smem_u32(smc);

    const int tid = threadIdx.x, lane = tid & 31, wid = tid >> 5;
    const int wm = wid / WN, wn = wid % WN;
    const int grp = lane >> 2, tig = lane & 3;
    const int lrow = lane & 7, sub = lane >> 3;
    const int zl = blockIdx.z % zdiv, zh = blockIdx.z / zdiv;
    const ll n0 = (ll)blockIdx.x * BN_T;

    // ldmatrix lane address components
    const int aRowB = wm*WTM + ((sub&1)<<3) + lrow;  // + mf*16
    const int aKo   = (sub>>1)<<4;                   // + ck
    const int bRowB = wn*32 + ((sub>>1)<<3) + lrow;  // + nfp*16
    const int bKo   = (sub&1)<<4;                    // + ck

    const ll aoff = zl*zA1 + zh*zA2 + (ll)blockIdx.y*128*lda;
    const bf16* Ahb = Ah + aoff;
    const bf16* Alb = Al + aoff;
    const ll boff = zl*zB1 + zh*zB2 + n0*ldb;
    const bf16* Bhb = Bh + boff;
    const bf16* Blb = Bl + boff;

    int kEnd = K;
    if (klimit){ int kl = ((int)blockIdx.y + 1)*128; if (kl < kEnd) kEnd = kl; }
    const int nk = kEnd >> 5;

    float acc[MF][NF][4];
    #pragma unroll
    for (int i=0;i<MF;i++)
        #pragma unroll
        for (int j=0;j<NF;j++)
            #pragma unroll
            for (int c=0;c<4;c++) acc[i][j][c] = 0.f;

    const int row = tid >> 2, g = tid & 3;

    auto LOAD = [&](int kb){
        const int s = kb % NST;
        const uint32_t ub = sbase + (uint32_t)(s*STG);
        const ll koff = ((ll)kb << 5) + g*8;
        #pragma unroll
        for (int i=0;i<2;i++){
            int r = row + i*64;
            uint32_t o = swz((uint32_t)(r*64 + g*16));
            cp16(ub + o,      Ahb + (ll)r*lda + koff);
            cp16(ub + SA + o, Alb + (ll)r*lda + koff);
        }
        #pragma unroll
        for (int i=0;i<BN_T/64;i++){
            int r = row + i*64;
            uint32_t o = swz((uint32_t)(r*64 + g*16));
            cp16(ub + 2*SA + o,      Bhb + (ll)r*ldb + koff);
            cp16(ub + 2*SA + SB + o, Blb + (ll)r*ldb + koff);
        }
        cp_commit();
    };

    #pragma unroll
    for (int kb=0; kb<NST-1; kb++) if (kb < nk) LOAD(kb);

    for (int k=0; k<nk; k++){
        cp_wait<NST-2>();
        __syncthreads();
        if (k + NST - 1 < nk) LOAD(k + NST - 1);
        else cp_commit();

        const int s = k % NST;
        const uint32_t AH = sbase + (uint32_t)(s*STG);
        const uint32_t AL = AH + SA;
        const uint32_t BH = AH + 2*SA;
        const uint32_t BL = BH + SB;

        #pragma unroll
        for (int kk=0; kk<2; kk++){
            const int ck = kk*32;
            uint32_t bh[2*NF], bl[2*NF];
            #pragma unroll
            for (int nfp=0; nfp<NF/2; nfp++){
                uint32_t bo = swz((uint32_t)((bRowB + nfp*16)*64 + ck + bKo));
                ldsm4(&bh[4*nfp], BH + bo);
                ldsm4(&bl[4*nfp], BL + bo);
            }
            #pragma unroll
            for (int mf=0; mf<MF; mf++){
                uint32_t ao = swz((uint32_t)((aRowB + mf*16)*64 + ck + aKo));
                uint32_t ah[4], al[4];
                ldsm4(ah, AH + ao);
                ldsm4(al, AL + ao);
                #pragma unroll
                for (int nf=0; nf<NF; nf++) mma_bf16(acc[mf][nf], ah, &bh[2*nf]);
                #pragma unroll
                for (int nf=0; nf<NF; nf++) mma_bf16(acc[mf][nf], ah, &bl[2*nf]);
                #pragma unroll
                for (int nf=0; nf<NF; nf++) mma_bf16(acc[mf][nf], al, &bh[2*nf]);
            }
        }
    }

    // ---- epilogue ----
    const ll cbase = zl*zC1 + zh*zC2
                   + ((ll)blockIdx.y*128 + wm*WTM)*ldc + n0 + wn*32;
    #pragma unroll
    for (int mf=0; mf<MF; mf++){
        int r0 = mf*16 + grp;
        #pragma unroll
        for (int nf=0; nf<NF; nf++){
            int c = nf*8 + tig*2;
            #pragma unroll
            for (int half=0; half<2; half++){
                ll off = cbase + (ll)(r0 + half*8)*ldc + c;
                float v0 = acc[mf][nf][2*half+0]*alpha;
                float v1 = acc[mf][nf][2*half+1]*alpha;
                if (SPLIT_OUT){
                    bf16 h0,l0,h1,l1;
                    split2(v0,h0,l0); split2(v1,h1,l1);
                    bf162 hp; hp.x=h0; hp.y=h1;
                    bf162 lp; lp.x=l0; lp.y=l1;
                    *(bf162*)(Ch + off) = hp;
                    *(bf162*)(Cl + off) = lp;
                } else {
                    float2 o; o.x=v0; o.y=v1;
                    *(float2*)(Cf + off) = o;
                }
            }
        }
    }
}

// ---------------- causal softmax (single global read, single exp pass) ----------------
__global__ void softmax_kernel(){
    const int s = blockIdx.x;
    const ll z = blockIdx.y;
    const float* row = g_scores + (z*S_LEN + (ll)s)*S_LEN;
    bf16* ph = g_pr_h + (z*S_LEN + (ll)s)*S_LEN;
    bf16* pl = g_pr_l + (z*S_LEN + (ll)s)*S_LEN;
    const int n = s + 1;
    const int nend = ((s>>7)+1)<<7;   // 128-aligned (PV reads whole 128-blocks)
    const int tid = threadIdx.x;

    float e[16];
    float mx = -1e30f;
    #pragma unroll
    for (int i=0;i<16;i++){
        int t = tid + i*128;
        e[i] = (t < n) ? row[t] : -1e30f;
        mx = fmaxf(mx, e[i]);
    }
    mx = warpMax(mx);
    __shared__ float redm[4], reds[4];
    if ((tid&31)==0) redm[tid>>5] = mx;
    __syncthreads();
    mx = fmaxf(fmaxf(redm[0],redm[1]), fmaxf(redm[2],redm[3]));

    float sum = 0.f;
    #pragma unroll
    for (int i=0;i<16;i++){
        int t = tid + i*128;
        float v = (t < n) ? exp2f(e[i] - mx) : 0.f;
        e[i] = v;
        sum += v;
    }
    sum = warpSum(sum);
    if ((tid&31)==0) reds[tid>>5] = sum;
    __syncthreads();
    sum = reds[0]+reds[1]+reds[2]+reds[3];
    const float inv = 1.0f / sum;

    #pragma unroll
    for (int i=0;i<16;i++){
        int t = tid + i*128;
        if (t < nend){
            float p = e[i]*inv;
            bf16 h,l; split2(p,h,l);
            ph[t]=h; pl[t]=l;
        }
    }
}

// ---------------- host side ----------------
static void launch_g(int BN, bool split,
    const bf16* Ah, const bf16* Al, const bf16* Bh, const bf16* Bl,
    float* Cf, bf16* Ch, bf16* Cl,
    int M, int N, int K, int lda, int ldb, int ldc,
    int Z, int zdiv,
    ll zA1, ll zA2, ll zB1, ll zB2, ll zC1, ll zC2,
    float alpha, bool causal, bool klimit)
{
    dim3 grid(N/BN, M/128, Z);
    int c = causal?1:0, kl = klimit?1:0;
    size_t sm = (size_t)3 * (2*128*64 + 2*(size_t)BN*64);
    if (BN == 128){
        if (split){
            cudaFuncSetAttribute(mma_gemm<128,true>, cudaFuncAttributeMaxDynamicSharedMemorySize, (int)sm);
            mma_gemm<128,true><<<grid,256,sm>>>(Ah,Al,Bh,Bl,Cf,Ch,Cl,K,lda,ldb,ldc,zdiv,zA1,zA2,zB1,zB2,zC1,zC2,alpha,c,kl);
        } else {
            cudaFuncSetAttribute(mma_gemm<128,false>, cudaFuncAttributeMaxDynamicSharedMemorySize, (int)sm);
            mma_gemm<128,false><<<grid,256,sm>>>(Ah,Al,Bh,Bl,Cf,Ch,Cl,K,lda,ldb,ldc,zdiv,zA1,zA2,zB1,zB2,zC1,zC2,alpha,c,kl);
        }
    } else { // BN == 64
        cudaFuncSetAttribute(mma_gemm<64,true>, cudaFuncAttributeMaxDynamicSharedMemorySize, (int)sm);
        mma_gemm<64,true><<<grid,256,sm>>>(Ah,Al,Bh,Bl,Cf,Ch,Cl,K,lda,ldb,ldc,zdiv,zA1,zA2,zB1,zB2,zC1,zC2,alpha,c,kl);
    }
}

#define SYM(p, s) cudaGetSymbolAddress((void**)&p, s)

extern "C" void kernel_launch(void* const* d_in, const int* in_sizes, int n_in,
                              void* d_out, int out_size)
{
    (void)in_sizes; (void)n_in; (void)out_size;
    const float* x      = (const float*)d_in[0];
    const float* angles = (const float*)d_in[1];
    const float* wq     = (const float*)d_in[2];
    const float* wkv_a  = (const float*)d_in[3];
    const float* wkv_b  = (const float*)d_in[4];
    const float* wo     = (const float*)d_in[5];
    const float* kvw    = (const float*)d_in[6];
    float* out = (float*)d_out;

    bf16 *xsh,*xsl,*wqh,*wql,*wah,*wal,*wbh,*wbl,*wbTh,*wbTl,*woh,*wol;
    bf16 *qsh,*qsl,*keh,*kel,*keTh,*keTl,*qeh,*qel,*prh,*prl,*olh,*oll,*osh,*osl,*kvh,*kvl;
    float *sc;
    SYM(xsh,g_xs_h); SYM(xsl,g_xs_l); SYM(wqh,g_wqs_h); SYM(wql,g_wqs_l);
    SYM(wah,g_was_h); SYM(wal,g_was_l); SYM(wbh,g_wbs_h); SYM(wbl,g_wbs_l);
    SYM(wbTh,g_wbT_h); SYM(wbTl,g_wbT_l); SYM(woh,g_wos_h); SYM(wol,g_wos_l);
    SYM(qsh,g_qs_h); SYM(qsl,g_qs_l); SYM(kvh,g_kvs_h); SYM(kvl,g_kvs_l);
    SYM(keh,g_ke_h); SYM(kel,g_ke_l); SYM(keTh,g_keT_h); SYM(keTl,g_keT_l);
    SYM(qeh,g_qe_h); SYM(qel,g_qe_l); SYM(prh,g_pr_h); SYM(prl,g_pr_l);
    SYM(olh,g_ol_h); SYM(oll,g_ol_l); SYM(osh,g_os_h); SYM(osl,g_os_l);
    SYM(sc,g_scores);

    const double msc = 0.1*log(40.0) + 1.0;
    const float softmax_scale = (float)(pow((double)QD, -0.5)*msc*msc);
    const float score_alpha = (float)((double)softmax_scale * LOG2E);

    // 0) split inputs into bf16 hi/lo planes
    {
        int n;
        n = NTOK*DIM/4;            split_arr<<<(n+255)/256,256>>>((const float4*)x, xsh, xsl, n);
        n = QOUT*DIM/4;            split_arr<<<(n+255)/256,256>>>((const float4*)wq, wqh, wql, n);
        n = KVOUT*DIM/4;           split_arr<<<(n+255)/256,256>>>((const float4*)wkv_a, wah, wal, n);
        zero_tail_was<<<((KVPAD-KVOUT)*DIM+255)/256,256>>>();
        n = NH*(NOPE+VDIM)*KVR/4;  split_arr<<<(n+255)/256,256>>>((const float4*)wkv_b, wbh, wbl, n);
        n = DIM*NH*VDIM/4;         split_arr<<<(n+255)/256,256>>>((const float4*)wo, woh, wol, n);
        n = NH*KVR*NOPE;           splitT_wkvb<<<(n+255)/256,256>>>(wkv_b);
    }
    rope_prep_kernel<<<(S_LEN*RHALF+127)/128, 128>>>(angles);

    // 1) q = x @ wq^T  (4096x3072, K=2048)
    launch_g(128,true, xsh,xsl, wqh,wql, 0, qsh,qsl,
             NTOK, QOUT, DIM, DIM, DIM, QOUT, 1,1, 0,0,0,0,0,0, 1.f,false,false);

    // 2) kv = x @ wkv_a^T  (single launch, N padded to 640)
    launch_g(128,true, xsh,xsl, wah,wal, 0, kvh,kvl,
             NTOK, KVPAD, DIM, DIM, DIM, KVPAD, 1,1, 0,0,0,0,0,0, 1.f,false,false);

    // 3) keff planes (+ transposed copy)
    prep_keff_kernel<<<NTOK, 128>>>(kvw);

    // 4) rope(q_pe) -> qeff[...,512:576]
    prep_qpe_kernel<<<NTOK, 512>>>();

    // 5) qeff[...,0:512] = q_nope @ wkv_bT  (per (b,h), K=128)
    launch_g(128,true, qsh,qsl, wbTh,wbTl, 0, qeh,qel,
             S_LEN, KVR, NOPE, QOUT, NOPE, DEFF, BATCH*NH, NH,
             (ll)QD, (ll)S_LEN*QOUT, (ll)KVR*NOPE, 0,
             (ll)S_LEN*DEFF, (ll)NH*S_LEN*DEFF, 1.f,false,false);

    // 6) scores = scale*log2e * qeff @ keff^T  (causal block-skip)
    launch_g(128,false, qeh,qel, keh,kel, sc, 0,0,
             S_LEN, S_LEN, DEFF, DEFF, DEFF, S_LEN, BATCH*NH, NH,
             (ll)S_LEN*DEFF, (ll)NH*S_LEN*DEFF, 0, (ll)S_LEN*DEFF,
             (ll)S_LEN*S_LEN, (ll)NH*S_LEN*S_LEN, score_alpha, true, false);

    // 7) softmax -> probs planes
    softmax_kernel<<<dim3(S_LEN, BATCH*NH), 128>>>();

    // 8) olat = probs @ keffT^T  (K causally capped)
    launch_g(128,true, prh,prl, keTh,keTl, 0, olh,oll,
             S_LEN, KVR, S_LEN, S_LEN, S_LEN, KVR, BATCH*NH, NH,
             (ll)S_LEN*S_LEN, (ll)NH*S_LEN*S_LEN, 0, (ll)DEFF*S_LEN,
             (ll)S_LEN*KVR, (ll)NH*S_LEN*KVR, 1.f, false, true);

    // 9) o[:, h*128:(h+1)*128] = olat_h @ wkv_b_v^T  (per (b,h), K=512)
    launch_g(128,true, olh,oll, wbh+(size_t)NOPE*KVR, wbl+(size_t)NOPE*KVR, 0, osh,osl,
             S_LEN, VDIM, KVR, KVR, KVR, NH*VDIM, BATCH*NH, NH,
             (ll)S_LEN*KVR, (ll)NH*S_LEN*KVR, (ll)(NOPE+VDIM)*KVR, 0,
             (ll)VDIM, (ll)S_LEN*NH*VDIM, 1.f, false, false);

    // 10) out = o @ wo^T  (4096x2048, K=2048, fp32 output)
    launch_g(128,false, osh,osl, woh,wol, out, 0,0,
             NTOK, DIM, NH*VDIM, NH*VDIM, NH*VDIM, DIM, 1,1,
             0,0,0,0,0,0, 1.f,false,false);
}

// round 8
// speedup vs baseline: 1.2291x; 1.1158x over previous
#include <cuda_runtime.h>
#include <cuda_bf16.h>
#include <cuda_fp16.h>
#include <math.h>
#include <stdint.h>

// ---------------- problem constants ----------------
#define S_LEN 2048
#define BATCH 2
#define NTOK  (S_LEN*BATCH)     // 4096
#define NH    16
#define DIM   2048
#define NOPE  128
#define ROPE  64
#define RHALF 32
#define VDIM  128
#define KVR   512
#define QD    (NOPE+ROPE)       // 192
#define QOUT  (NH*QD)           // 3072
#define KVOUT (KVR+ROPE)        // 576
#define KVPAD 640               // kv-proj N padded to 5*128
#define DEFF  576
#define LOG2E 1.4426950408889634

typedef long long ll;
typedef __nv_bfloat16 bf16;
typedef __nv_bfloat162 bf162;

// ---------------- scratch ----------------
__device__ __align__(16) bf16 g_xs_h [(size_t)NTOK*DIM],    g_xs_l [(size_t)NTOK*DIM];
__device__ __align__(16) bf16 g_wqs_h[(size_t)QOUT*DIM],    g_wqs_l[(size_t)QOUT*DIM];
__device__ __align__(16) bf16 g_was_h[(size_t)KVPAD*DIM],   g_was_l[(size_t)KVPAD*DIM];
__device__ __align__(16) bf16 g_wbs_h[(size_t)NH*(NOPE+VDIM)*KVR], g_wbs_l[(size_t)NH*(NOPE+VDIM)*KVR];
__device__ __align__(16) bf16 g_wbT_h[(size_t)NH*KVR*NOPE], g_wbT_l[(size_t)NH*KVR*NOPE];
__device__ __align__(16) bf16 g_wos_h[(size_t)DIM*NH*VDIM], g_wos_l[(size_t)DIM*NH*VDIM];
__device__ __align__(16) bf16 g_qs_h [(size_t)NTOK*QOUT],   g_qs_l [(size_t)NTOK*QOUT];
__device__ __align__(16) bf16 g_kvs_h[(size_t)NTOK*KVPAD],  g_kvs_l[(size_t)NTOK*KVPAD];
__device__ __align__(16) bf16 g_ke_h [(size_t)NTOK*DEFF],   g_ke_l [(size_t)NTOK*DEFF];
__device__ __align__(16) half g_keT_h[(size_t)BATCH*DEFF*S_LEN], g_keT_l[(size_t)BATCH*DEFF*S_LEN];
__device__ __align__(16) bf16 g_qe_h [(size_t)BATCH*NH*S_LEN*DEFF], g_qe_l [(size_t)BATCH*NH*S_LEN*DEFF];
__device__ float g_scores[(size_t)BATCH*NH*S_LEN*S_LEN];
__device__ __align__(16) half g_pr   [(size_t)BATCH*NH*S_LEN*S_LEN];
__device__ __align__(16) bf16 g_ol_h [(size_t)BATCH*NH*S_LEN*KVR],  g_ol_l [(size_t)BATCH*NH*S_LEN*KVR];
__device__ __align__(16) bf16 g_os_h [(size_t)NTOK*NH*VDIM], g_os_l [(size_t)NTOK*NH*VDIM];
__device__ float g_cos[S_LEN*RHALF];
__device__ float g_sin[S_LEN*RHALF];

// ---------------- helpers ----------------
__device__ __forceinline__ float warpMax(float v){
    #pragma unroll
    for (int o=16;o;o>>=1) v = fmaxf(v, __shfl_xor_sync(0xffffffffu, v, o));
    return v;
}
__device__ __forceinline__ float warpSum(float v){
    #pragma unroll
    for (int o=16;o;o>>=1) v += __shfl_xor_sync(0xffffffffu, v, o);
    return v;
}
__device__ __forceinline__ uint32_t smem_u32(const void* p){
    uint32_t a;
    asm("{ .reg .u64 t; cvta.to.shared.u64 t, %1; cvt.u32.u64 %0, t; }" : "=r"(a) : "l"(p));
    return a;
}
__device__ __forceinline__ void split2(float f, bf16& h, bf16& l){
    h = __float2bfloat16_rn(f);
    l = __float2bfloat16_rn(f - __bfloat162float(h));
}
__device__ __forceinline__ float rejoin(bf16 h, bf16 l){
    return __bfloat162float(h) + __bfloat162float(l);
}
__device__ __forceinline__ void mma_bf16(float* d, const uint32_t* a, const uint32_t* b){
    asm volatile(
        "mma.sync.aligned.m16n8k16.row.col.f32.bf16.bf16.f32 "
        "{%0,%1,%2,%3}, {%4,%5,%6,%7}, {%8,%9}, {%0,%1,%2,%3};"
        : "+f"(d[0]), "+f"(d[1]), "+f"(d[2]), "+f"(d[3])
        : "r"(a[0]), "r"(a[1]), "r"(a[2]), "r"(a[3]), "r"(b[0]), "r"(b[1]));
}
__device__ __forceinline__ void mma_f16(float* d, const uint32_t* a, const uint32_t* b){
    asm volatile(
        "mma.sync.aligned.m16n8k16.row.col.f32.f16.f16.f32 "
        "{%0,%1,%2,%3}, {%4,%5,%6,%7}, {%8,%9}, {%0,%1,%2,%3};"
        : "+f"(d[0]), "+f"(d[1]), "+f"(d[2]), "+f"(d[3])
        : "r"(a[0]), "r"(a[1]), "r"(a[2]), "r"(a[3]), "r"(b[0]), "r"(b[1]));
}
__device__ __forceinline__ void ldsm4(uint32_t* r, uint32_t a){
    asm volatile("ldmatrix.sync.aligned.m8n8.x4.shared.b16 {%0,%1,%2,%3}, [%4];"
        : "=r"(r[0]), "=r"(r[1]), "=r"(r[2]), "=r"(r[3]) : "r"(a));
}
__device__ __forceinline__ void cp16(uint32_t dst, const void* src){
    asm volatile("cp.async.cg.shared.global [%0], [%1], 16;\n" :: "r"(dst), "l"(src) : "memory");
}
__device__ __forceinline__ void cp_commit(){ asm volatile("cp.async.commit_group;\n" ::: "memory"); }
template<int N>
__device__ __forceinline__ void cp_wait(){ asm volatile("cp.async.wait_group %0;\n" :: "n"(N) : "memory"); }

__device__ __forceinline__ uint32_t swz(uint32_t o){ return o ^ ((o>>3)&0x30u); }

// ---------------- split kernels ----------------
__global__ void split_arr(const float4* __restrict__ src, bf16* __restrict__ h, bf16* __restrict__ l, int n4){
    int i = blockIdx.x*blockDim.x + threadIdx.x;
    if (i >= n4) return;
    float4 v = src[i];
    bf16 h0,l0,h1,l1,h2,l2,h3,l3;
    split2(v.x,h0,l0); split2(v.y,h1,l1); split2(v.z,h2,l2); split2(v.w,h3,l3);
    bf162* hp = (bf162*)(h + 4*(size_t)i);
    bf162* lp = (bf162*)(l + 4*(size_t)i);
    bf162 a; a.x=h0; a.y=h1; hp[0]=a;
    bf162 b; b.x=h2; b.y=h3; hp[1]=b;
    bf162 c; c.x=l0; c.y=l1; lp[0]=c;
    bf162 d; d.x=l2; d.y=l3; lp[1]=d;
}
__global__ void zero_tail_was(){
    int i = blockIdx.x*blockDim.x + threadIdx.x;
    if (i < (KVPAD-KVOUT)*DIM){
        bf16 z = __float2bfloat16_rn(0.f);
        g_was_h[(size_t)KVOUT*DIM + i] = z;
        g_was_l[(size_t)KVOUT*DIM + i] = z;
    }
}
__global__ void splitT_wkvb(const float* __restrict__ wb){
    int i = blockIdx.x*blockDim.x + threadIdx.x;
    if (i >= NH*KVR*NOPE) return;
    int d = i % NOPE, c = (i/NOPE) % KVR, h = i/(NOPE*KVR);
    float v = wb[((size_t)h*(NOPE+VDIM) + d)*KVR + c];
    split2(v, g_wbT_h[i], g_wbT_l[i]);
}

// ---------------- prep kernels ----------------
__global__ void rope_prep_kernel(const float* __restrict__ ang){
    int i = blockIdx.x*blockDim.x + threadIdx.x;
    if (i < S_LEN*RHALF){
        float a = ang[i];
        g_cos[i] = cosf(a);
        g_sin[i] = sinf(a);
    }
}

__global__ void prep_keff_kernel(const float* __restrict__ kvw){
    int t = blockIdx.x;
    int s = t % S_LEN;
    int tid = threadIdx.x;
    float v[4];
    #pragma unroll
    for (int j=0;j<4;j++){
        size_t idx = (size_t)t*KVPAD + 4*tid + j;
        v[j] = rejoin(g_kvs_h[idx], g_kvs_l[idx]);
    }
    float ss = v[0]*v[0]+v[1]*v[1]+v[2]*v[2]+v[3]*v[3];
    ss = warpSum(ss);
    __shared__ float red[4];
    if ((tid&31)==0) red[tid>>5] = ss;
    __syncthreads();
    float tot = red[0]+red[1]+red[2]+red[3];
    float r = rsqrtf(tot*(1.0f/KVR) + 1e-6f);
    #pragma unroll
    for (int j=0;j<4;j++){
        int c = 4*tid + j;
        float o = v[j]*r*kvw[c];
        bf16 h,l; split2(o,h,l);
        size_t di = (size_t)t*DEFF + c;
        g_ke_h[di]=h; g_ke_l[di]=l;
    }
    if (tid < RHALF){
        size_t pi = (size_t)t*KVPAD + KVR + 2*tid;
        float xr = rejoin(g_kvs_h[pi],   g_kvs_l[pi]);
        float xi = rejoin(g_kvs_h[pi+1], g_kvs_l[pi+1]);
        float c  = g_cos[s*RHALF+tid], sn = g_sin[s*RHALF+tid];
        float yr = xr*c - xi*sn, yi = xr*sn + xi*c;
        bf16 hr,lr,hi2,li; split2(yr,hr,lr); split2(yi,hi2,li);
        size_t di = (size_t)t*DEFF + KVR + 2*tid;
        g_ke_h[di]=hr; g_ke_l[di]=lr; g_ke_h[di+1]=hi2; g_ke_l[di+1]=li;
    }
}

// coalesced tiled transpose: ke (bf16 planes, [tok][DEFF]) -> keT (fp16 hi/lo, [b][DEFF][S])
__global__ void transpose_keT(){
    __shared__ half th[32][33], tl[32][33];
    int b = blockIdx.z;
    int c0 = blockIdx.y*32, s0 = blockIdx.x*32;
    int tx = threadIdx.x, ty = threadIdx.y;   // 32 x 8
    #pragma unroll
    for (int i=0;i<32;i+=8){
        size_t idx = (size_t)(b*S_LEN + s0 + ty + i)*DEFF + c0 + tx;
        float f = rejoin(g_ke_h[idx], g_ke_l[idx]);
        half h = __float2half_rn(f);
        half l = __float2half_rn(f - __half2float(h));
        th[ty+i][tx] = h; tl[ty+i][tx] = l;
    }
    __syncthreads();
    #pragma unroll
    for (int i=0;i<32;i+=8){
        size_t o = ((size_t)b*DEFF + c0 + ty + i)*S_LEN + s0 + tx;
        g_keT_h[o] = th[tx][ty+i];
        g_keT_l[o] = tl[tx][ty+i];
    }
}

// one block per token, 512 threads = 16 heads x 32 rope pairs
__global__ void prep_qpe_kernel(){
    int t = blockIdx.x;
    int b = t / S_LEN, s = t % S_LEN;
    int h = threadIdx.x >> 5, i = threadIdx.x & 31;
    size_t si = (size_t)t*QOUT + h*QD + NOPE + 2*i;
    float xr = rejoin(g_qs_h[si],   g_qs_l[si]);
    float xi = rejoin(g_qs_h[si+1], g_qs_l[si+1]);
    float c  = g_cos[s*RHALF+i], sn = g_sin[s*RHALF+i];
    float yr = xr*c - xi*sn, yi = xr*sn + xi*c;
    size_t di = ((size_t)(b*NH+h)*S_LEN + s)*DEFF + KVR + 2*i;
    bf16 hh,ll_; split2(yr,hh,ll_); g_qe_h[di]=hh;   g_qe_l[di]=ll_;
    split2(yi,hh,ll_);              g_qe_h[di+1]=hh; g_qe_l[di+1]=ll_;
}

// ---------------- split GEMM with ldmatrix ----------------
// F16A=false: bf16x3, A/B hi+lo planes, 3 passes, 3 stages.
// F16A=true : A = single fp16 plane, B = fp16 hi/lo planes, 2 passes, 4 stages.
template<int BN_T, bool SPLIT_OUT, bool F16A>
__global__ __launch_bounds__(256,2) void mma_gemm(
    const bf16* __restrict__ Ah, const bf16* __restrict__ Al,
    const bf16* __restrict__ Bh, const bf16* __restrict__ Bl,
    float* __restrict__ Cf, bf16* __restrict__ Ch, bf16* __restrict__ Cl,
    int K, int lda, int ldb, int ldc, int zdiv,
    ll zA1, ll zA2, ll zB1, ll zB2, ll zC1, ll zC2,
    float alpha, int causal, int klimit)
{
    if (causal && blockIdx.x > blockIdx.y) return;
    constexpr int NST = F16A ? 4 : 3;
    constexpr int WN  = BN_T/32;
    constexpr int WM  = 8/WN;
    constexpr int WTM = 128/WM;
    constexpr int MF  = WTM/16;
    constexpr int NF  = 4;
    constexpr int SA  = 128*64;
    constexpr int SB  = BN_T*64;
    constexpr int STG = F16A ? (SA + 2*SB) : (2*SA + 2*SB);

    extern __shared__ char smc[];
    const uint32_t sbase = smem_u32(smc);

    const int tid = threadIdx.x, lane = tid & 31, wid = tid >> 5;
    const int wm = wid / WN, wn = wid % WN;
    const int grp = lane >> 2, tig = lane & 3;
    const int lrow = lane & 7, sub = lane >> 3;
    const int zl = blockIdx.z % zdiv, zh = blockIdx.z / zdiv;
    const ll n0 = (ll)blockIdx.x * BN_T;

    const int aRowB = wm*WTM + ((sub&1)<<3) + lrow;
    const int aKo   = (sub>>1)<<4;
    const int bRowB = wn*32 + ((sub>>1)<<3) + lrow;
    const int bKo   = (sub&1)<<4;

    const ll aoff = zl*zA1 + zh*zA2 + (ll)blockIdx.y*128*lda;
    const bf16* Ahb = Ah + aoff;
    const bf16* Alb = Al + aoff;
    const ll boff = zl*zB1 + zh*zB2 + n0*ldb;
    const bf16* Bhb = Bh + boff;
    const bf16* Blb = Bl + boff;

    int kEnd = K;
    if (klimit){ int kl = ((int)blockIdx.y + 1)*128; if (kl < kEnd) kEnd = kl; }
    const int nk = kEnd >> 5;

    float acc[MF][NF][4];
    #pragma unroll
    for (int i=0;i<MF;i++)
        #pragma unroll
        for (int j=0;j<NF;j++)
            #pragma unroll
            for (int c=0;c<4;c++) acc[i][j][c] = 0.f;

    const int row = tid >> 2, g = tid & 3;

    auto LOAD = [&](int kb){
        const int s = kb % NST;
        const uint32_t ub = sbase + (uint32_t)(s*STG);
        const ll koff = ((ll)kb << 5) + g*8;
        #pragma unroll
        for (int i=0;i<2;i++){
            int r = row + i*64;
            uint32_t o = swz((uint32_t)(r*64 + g*16));
            cp16(ub + o, Ahb + (ll)r*lda + koff);
            if (!F16A) cp16(ub + SA + o, Alb + (ll)r*lda + koff);
        }
        const uint32_t bb = ub + (F16A ? SA : 2*SA);
        #pragma unroll
        for (int i=0;i<BN_T/64;i++){
            int r = row + i*64;
            uint32_t o = swz((uint32_t)(r*64 + g*16));
            cp16(bb + o,      Bhb + (ll)r*ldb + koff);
            cp16(bb + SB + o, Blb + (ll)r*ldb + koff);
        }
        cp_commit();
    };

    #pragma unroll
    for (int kb=0; kb<NST-1; kb++) if (kb < nk) LOAD(kb);

    for (int k=0; k<nk; k++){
        cp_wait<NST-2>();
        __syncthreads();
        if (k + NST - 1 < nk) LOAD(k + NST - 1);
        else cp_commit();

        const int s = k % NST;
        const uint32_t AH = sbase + (uint32_t)(s*STG);
        const uint32_t BH = AH + (F16A ? SA : 2*SA);
        const uint32_t AL = AH + SA;        // unused in F16A
        const uint32_t BL = BH + SB;

        #pragma unroll
        for (int kk=0; kk<2; kk++){
            const int ck = kk*32;
            uint32_t bh[2*NF], bl[2*NF];
            #pragma unroll
            for (int nfp=0; nfp<NF/2; nfp++){
                uint32_t bo = swz((uint32_t)((bRowB + nfp*16)*64 + ck + bKo));
                ldsm4(&bh[4*nfp], BH + bo);
                ldsm4(&bl[4*nfp], BL + bo);
            }
            #pragma unroll
            for (int mf=0; mf<MF; mf++){
                uint32_t ao = swz((uint32_t)((aRowB + mf*16)*64 + ck + aKo));
                uint32_t ah[4];
                ldsm4(ah, AH + ao);
                if (F16A){
                    #pragma unroll
                    for (int nf=0; nf<NF; nf++) mma_f16(acc[mf][nf], ah, &bh[2*nf]);
                    #pragma unroll
                    for (int nf=0; nf<NF; nf++) mma_f16(acc[mf][nf], ah, &bl[2*nf]);
                } else {
                    uint32_t al[4];
                    ldsm4(al, AL + ao);
                    #pragma unroll
                    for (int nf=0; nf<NF; nf++) mma_bf16(acc[mf][nf], ah, &bh[2*nf]);
                    #pragma unroll
                    for (int nf=0; nf<NF; nf++) mma_bf16(acc[mf][nf], ah, &bl[2*nf]);
                    #pragma unroll
                    for (int nf=0; nf<NF; nf++) mma_bf16(acc[mf][nf], al, &bh[2*nf]);
                }
            }
        }
    }

    // ---- epilogue ----
    const ll cbase = zl*zC1 + zh*zC2
                   + ((ll)blockIdx.y*128 + wm*WTM)*ldc + n0 + wn*32;
    #pragma unroll
    for (int mf=0; mf<MF; mf++){
        int r0 = mf*16 + grp;
        #pragma unroll
        for (int nf=0; nf<NF; nf++){
            int c = nf*8 + tig*2;
            #pragma unroll
            for (int half_=0; half_<2; half_++){
                ll off = cbase + (ll)(r0 + half_*8)*ldc + c;
                float v0 = acc[mf][nf][2*half_+0]*alpha;
                float v1 = acc[mf][nf][2*half_+1]*alpha;
                if (SPLIT_OUT){
                    bf16 h0,l0,h1,l1;
                    split2(v0,h0,l0); split2(v1,h1,l1);
                    bf162 hp; hp.x=h0; hp.y=h1;
                    bf162 lp; lp.x=l0; lp.y=l1;
                    *(bf162*)(Ch + off) = hp;
                    *(bf162*)(Cl + off) = lp;
                } else {
                    float2 o; o.x=v0; o.y=v1;
                    *(float2*)(Cf + off) = o;
                }
            }
        }
    }
}

// ---------------- causal softmax -> single fp16 probs ----------------
__global__ void softmax_kernel(){
    const int s = blockIdx.x;
    const ll z = blockIdx.y;
    const float* row = g_scores + (z*S_LEN + (ll)s)*S_LEN;
    half* pr = g_pr + (z*S_LEN + (ll)s)*S_LEN;
    const int n = s + 1;
    const int nend = ((s>>7)+1)<<7;
    const int tid = threadIdx.x;

    float e[16];
    float mx = -1e30f;
    #pragma unroll
    for (int i=0;i<16;i++){
        int t = tid + i*128;
        e[i] = (t < n) ? row[t] : -1e30f;
        mx = fmaxf(mx, e[i]);
    }
    mx = warpMax(mx);
    __shared__ float redm[4], reds[4];
    if ((tid&31)==0) redm[tid>>5] = mx;
    __syncthreads();
    mx = fmaxf(fmaxf(redm[0],redm[1]), fmaxf(redm[2],redm[3]));

    float sum = 0.f;
    #pragma unroll
    for (int i=0;i<16;i++){
        int t = tid + i*128;
        float v = (t < n) ? exp2f(e[i] - mx) : 0.f;
        e[i] = v;
        sum += v;
    }
    sum = warpSum(sum);
    if ((tid&31)==0) reds[tid>>5] = sum;
    __syncthreads();
    sum = reds[0]+reds[1]+reds[2]+reds[3];
    const float inv = 1.0f / sum;

    #pragma unroll
    for (int i=0;i<16;i++){
        int t = tid + i*128;
        if (t < nend) pr[t] = __float2half_rn(e[i]*inv);
    }
}

// ---------------- host side ----------------
static void launch_g(int BN, bool split, bool f16a,
    const bf16* Ah, const bf16* Al, const bf16* Bh, const bf16* Bl,
    float* Cf, bf16* Ch, bf16* Cl,
    int M, int N, int K, int lda, int ldb, int ldc,
    int Z, int zdiv,
    ll zA1, ll zA2, ll zB1, ll zB2, ll zC1, ll zC2,
    float alpha, bool causal, bool klimit)
{
    dim3 grid(N/BN, M/128, Z);
    int c = causal?1:0, kl = klimit?1:0;
    if (f16a){ // BN=128, split-out, fp16-A two-pass, 4 stages
        size_t sm = (size_t)4 * (128*64 + 2*128*64);
        cudaFuncSetAttribute(mma_gemm<128,true,true>, cudaFuncAttributeMaxDynamicSharedMemorySize, (int)sm);
        mma_gemm<128,true,true><<<grid,256,sm>>>(Ah,Al,Bh,Bl,Cf,Ch,Cl,K,lda,ldb,ldc,zdiv,zA1,zA2,zB1,zB2,zC1,zC2,alpha,c,kl);
        return;
    }
    size_t sm = (size_t)3 * (2*128*64 + 2*(size_t)BN*64);
    if (BN == 128){
        if (split){
            cudaFuncSetAttribute(mma_gemm<128,true,false>, cudaFuncAttributeMaxDynamicSharedMemorySize, (int)sm);
            mma_gemm<128,true,false><<<grid,256,sm>>>(Ah,Al,Bh,Bl,Cf,Ch,Cl,K,lda,ldb,ldc,zdiv,zA1,zA2,zB1,zB2,zC1,zC2,alpha,c,kl);
        } else {
            cudaFuncSetAttribute(mma_gemm<128,false,false>, cudaFuncAttributeMaxDynamicSharedMemorySize, (int)sm);
            mma_gemm<128,false,false><<<grid,256,sm>>>(Ah,Al,Bh,Bl,Cf,Ch,Cl,K,lda,ldb,ldc,zdiv,zA1,zA2,zB1,zB2,zC1,zC2,alpha,c,kl);
        }
    } else {
        cudaFuncSetAttribute(mma_gemm<64,true,false>, cudaFuncAttributeMaxDynamicSharedMemorySize, (int)sm);
        mma_gemm<64,true,false><<<grid,256,sm>>>(Ah,Al,Bh,Bl,Cf,Ch,Cl,K,lda,ldb,ldc,zdiv,zA1,zA2,zB1,zB2,zC1,zC2,alpha,c,kl);
    }
}

#define SYM(p, s) cudaGetSymbolAddress((void**)&p, s)

extern "C" void kernel_launch(void* const* d_in, const int* in_sizes, int n_in,
                              void* d_out, int out_size)
{
    (void)in_sizes; (void)n_in; (void)out_size;
    const float* x      = (const float*)d_in[0];
    const float* angles = (const float*)d_in[1];
    const float* wq     = (const float*)d_in[2];
    const float* wkv_a  = (const float*)d_in[3];
    const float* wkv_b  = (const float*)d_in[4];
    const float* wo     = (const float*)d_in[5];
    const float* kvw    = (const float*)d_in[6];
    float* out = (float*)d_out;

    bf16 *xsh,*xsl,*wqh,*wql,*wah,*wal,*wbh,*wbl,*wbTh,*wbTl,*woh,*wol;
    bf16 *qsh,*qsl,*keh,*kel,*qeh,*qel,*olh,*oll,*osh,*osl,*kvh,*kvl;
    half *keTh,*keTl,*pr;
    float *sc;
    SYM(xsh,g_xs_h); SYM(xsl,g_xs_l); SYM(wqh,g_wqs_h); SYM(wql,g_wqs_l);
    SYM(wah,g_was_h); SYM(wal,g_was_l); SYM(wbh,g_wbs_h); SYM(wbl,g_wbs_l);
    SYM(wbTh,g_wbT_h); SYM(wbTl,g_wbT_l); SYM(woh,g_wos_h); SYM(wol,g_wos_l);
    SYM(qsh,g_qs_h); SYM(qsl,g_qs_l); SYM(kvh,g_kvs_h); SYM(kvl,g_kvs_l);
    SYM(keh,g_ke_h); SYM(kel,g_ke_l); SYM(keTh,g_keT_h); SYM(keTl,g_keT_l);
    SYM(qeh,g_qe_h); SYM(qel,g_qe_l); SYM(pr,g_pr);
    SYM(olh,g_ol_h); SYM(oll,g_ol_l); SYM(osh,g_os_h); SYM(osl,g_os_l);
    SYM(sc,g_scores);

    const double msc = 0.1*log(40.0) + 1.0;
    const float softmax_scale = (float)(pow((double)QD, -0.5)*msc*msc);
    const float score_alpha = (float)((double)softmax_scale * LOG2E);

    // 0) split inputs into bf16 hi/lo planes
    {
        int n;
        n = NTOK*DIM/4;            split_arr<<<(n+255)/256,256>>>((const float4*)x, xsh, xsl, n);
        n = QOUT*DIM/4;            split_arr<<<(n+255)/256,256>>>((const float4*)wq, wqh, wql, n);
        n = KVOUT*DIM/4;           split_arr<<<(n+255)/256,256>>>((const float4*)wkv_a, wah, wal, n);
        zero_tail_was<<<((KVPAD-KVOUT)*DIM+255)/256,256>>>();
        n = NH*(NOPE+VDIM)*KVR/4;  split_arr<<<(n+255)/256,256>>>((const float4*)wkv_b, wbh, wbl, n);
        n = DIM*NH*VDIM/4;         split_arr<<<(n+255)/256,256>>>((const float4*)wo, woh, wol, n);
        n = NH*KVR*NOPE;           splitT_wkvb<<<(n+255)/256,256>>>(wkv_b);
    }
    rope_prep_kernel<<<(S_LEN*RHALF+127)/128, 128>>>(angles);

    // 1) q = x @ wq^T
    launch_g(128,true,false, xsh,xsl, wqh,wql, 0, qsh,qsl,
             NTOK, QOUT, DIM, DIM, DIM, QOUT, 1,1, 0,0,0,0,0,0, 1.f,false,false);

    // 2) kv = x @ wkv_a^T  (single launch, N padded to 640)
    launch_g(128,true,false, xsh,xsl, wah,wal, 0, kvh,kvl,
             NTOK, KVPAD, DIM, DIM, DIM, KVPAD, 1,1, 0,0,0,0,0,0, 1.f,false,false);

    // 3) keff planes, then coalesced fp16 keT transpose
    prep_keff_kernel<<<NTOK, 128>>>(kvw);
    transpose_keT<<<dim3(S_LEN/32, DEFF/32, BATCH), dim3(32,8)>>>();

    // 4) rope(q_pe) -> qeff[...,512:576]
    prep_qpe_kernel<<<NTOK, 512>>>();

    // 5) qeff[...,0:512] = q_nope @ wkv_bT  (per (b,h), K=128)
    launch_g(128,true,false, qsh,qsl, wbTh,wbTl, 0, qeh,qel,
             S_LEN, KVR, NOPE, QOUT, NOPE, DEFF, BATCH*NH, NH,
             (ll)QD, (ll)S_LEN*QOUT, (ll)KVR*NOPE, 0,
             (ll)S_LEN*DEFF, (ll)NH*S_LEN*DEFF, 1.f,false,false);

    // 6) scores = scale*log2e * qeff @ keff^T  (causal block-skip)
    launch_g(128,false,false, qeh,qel, keh,kel, sc, 0,0,
             S_LEN, S_LEN, DEFF, DEFF, DEFF, S_LEN, BATCH*NH, NH,
             (ll)S_LEN*DEFF, (ll)NH*S_LEN*DEFF, 0, (ll)S_LEN*DEFF,
             (ll)S_LEN*S_LEN, (ll)NH*S_LEN*S_LEN, score_alpha, true, false);

    // 7) softmax -> fp16 probs
    softmax_kernel<<<dim3(S_LEN, BATCH*NH), 128>>>();

    // 8) olat = probs(fp16) @ keT(fp16 hi/lo)^T, 2 passes, K causally capped
    launch_g(128,true,true, (const bf16*)pr, 0, (const bf16*)keTh, (const bf16*)keTl, 0, olh,oll,
             S_LEN, KVR, S_LEN, S_LEN, S_LEN, KVR, BATCH*NH, NH,
             (ll)S_LEN*S_LEN, (ll)NH*S_LEN*S_LEN, 0, (ll)DEFF*S_LEN,
             (ll)S_LEN*KVR, (ll)NH*S_LEN*KVR, 1.f, false, true);

    // 9) o[:, h*128:(h+1)*128] = olat_h @ wkv_b_v^T  (per (b,h), K=512)
    launch_g(128,true,false, olh,oll, wbh+(size_t)NOPE*KVR, wbl+(size_t)NOPE*KVR, 0, osh,osl,
             S_LEN, VDIM, KVR, KVR, KVR, NH*VDIM, BATCH*NH, NH,
             (ll)S_LEN*KVR, (ll)NH*S_LEN*KVR, (ll)(NOPE+VDIM)*KVR, 0,
             (ll)VDIM, (ll)S_LEN*NH*VDIM, 1.f, false, false);

    // 10) out = o @ wo^T  (fp32 output)
    launch_g(128,false,false, osh,osl, woh,wol, out, 0,0,
             NTOK, DIM, NH*VDIM, NH*VDIM, NH*VDIM, DIM, 1,1,
             0,0,0,0,0,0, 1.f,false,false);
}

// round 9
// speedup vs baseline: 1.3197x; 1.0736x over previous
#include <cuda_runtime.h>
#include <cuda_bf16.h>
#include <cuda_fp16.h>
#include <math.h>
#include <stdint.h>

// ---------------- problem constants ----------------
#define S_LEN 2048
#define BATCH 2
#define NTOK  (S_LEN*BATCH)     // 4096
#define NH    16
#define DIM   2048
#define NOPE  128
#define ROPE  64
#define RHALF 32
#define VDIM  128
#define KVR   512
#define QD    (NOPE+ROPE)       // 192
#define QOUT  (NH*QD)           // 3072
#define KVOUT (KVR+ROPE)        // 576
#define KVPAD 640               // kv-proj N padded to 5*128
#define DEFF  576
#define LOG2E 1.4426950408889634

typedef long long ll;
typedef __nv_bfloat16 bf16;
typedef __nv_bfloat162 bf162;

// ---------------- scratch ----------------
__device__ __align__(16) bf16 g_xs_h [(size_t)NTOK*DIM],    g_xs_l [(size_t)NTOK*DIM];
__device__ __align__(16) bf16 g_wqs_h[(size_t)QOUT*DIM],    g_wqs_l[(size_t)QOUT*DIM];
__device__ __align__(16) bf16 g_was_h[(size_t)KVPAD*DIM],   g_was_l[(size_t)KVPAD*DIM];
__device__ __align__(16) half g_wbf_h[(size_t)NH*(NOPE+VDIM)*KVR], g_wbf_l[(size_t)NH*(NOPE+VDIM)*KVR];
__device__ __align__(16) bf16 g_wbT_h[(size_t)NH*KVR*NOPE], g_wbT_l[(size_t)NH*KVR*NOPE];
__device__ __align__(16) half g_wof_h[(size_t)DIM*NH*VDIM], g_wof_l[(size_t)DIM*NH*VDIM];
__device__ __align__(16) bf16 g_qs_h [(size_t)NTOK*QOUT],   g_qs_l [(size_t)NTOK*QOUT];
__device__ __align__(16) bf16 g_kvs_h[(size_t)NTOK*KVPAD],  g_kvs_l[(size_t)NTOK*KVPAD];
__device__ __align__(16) bf16 g_ke_h [(size_t)NTOK*DEFF],   g_ke_l [(size_t)NTOK*DEFF];
__device__ __align__(16) half g_keT_h[(size_t)BATCH*DEFF*S_LEN], g_keT_l[(size_t)BATCH*DEFF*S_LEN];
__device__ __align__(16) bf16 g_qe_h [(size_t)BATCH*NH*S_LEN*DEFF], g_qe_l [(size_t)BATCH*NH*S_LEN*DEFF];
__device__ float g_scores[(size_t)BATCH*NH*S_LEN*S_LEN];
__device__ __align__(16) half g_pr   [(size_t)BATCH*NH*S_LEN*S_LEN];
__device__ __align__(16) half g_ol   [(size_t)BATCH*NH*S_LEN*KVR];
__device__ __align__(16) half g_os   [(size_t)NTOK*NH*VDIM];
__device__ float g_cos[S_LEN*RHALF];
__device__ float g_sin[S_LEN*RHALF];

// ---------------- helpers ----------------
__device__ __forceinline__ float warpMax(float v){
    #pragma unroll
    for (int o=16;o;o>>=1) v = fmaxf(v, __shfl_xor_sync(0xffffffffu, v, o));
    return v;
}
__device__ __forceinline__ float warpSum(float v){
    #pragma unroll
    for (int o=16;o;o>>=1) v += __shfl_xor_sync(0xffffffffu, v, o);
    return v;
}
__device__ __forceinline__ uint32_t smem_u32(const void* p){
    uint32_t a;
    asm("{ .reg .u64 t; cvta.to.shared.u64 t, %1; cvt.u32.u64 %0, t; }" : "=r"(a) : "l"(p));
    return a;
}
__device__ __forceinline__ void split2(float f, bf16& h, bf16& l){
    h = __float2bfloat16_rn(f);
    l = __float2bfloat16_rn(f - __bfloat162float(h));
}
__device__ __forceinline__ void split2h(float f, half& h, half& l){
    h = __float2half_rn(f);
    l = __float2half_rn(f - __half2float(h));
}
__device__ __forceinline__ float rejoin(bf16 h, bf16 l){
    return __bfloat162float(h) + __bfloat162float(l);
}
__device__ __forceinline__ void mma_bf16(float* d, const uint32_t* a, const uint32_t* b){
    asm volatile(
        "mma.sync.aligned.m16n8k16.row.col.f32.bf16.bf16.f32 "
        "{%0,%1,%2,%3}, {%4,%5,%6,%7}, {%8,%9}, {%0,%1,%2,%3};"
        : "+f"(d[0]), "+f"(d[1]), "+f"(d[2]), "+f"(d[3])
        : "r"(a[0]), "r"(a[1]), "r"(a[2]), "r"(a[3]), "r"(b[0]), "r"(b[1]));
}
__device__ __forceinline__ void mma_f16(float* d, const uint32_t* a, const uint32_t* b){
    asm volatile(
        "mma.sync.aligned.m16n8k16.row.col.f32.f16.f16.f32 "
        "{%0,%1,%2,%3}, {%4,%5,%6,%7}, {%8,%9}, {%0,%1,%2,%3};"
        : "+f"(d[0]), "+f"(d[1]), "+f"(d[2]), "+f"(d[3])
        : "r"(a[0]), "r"(a[1]), "r"(a[2]), "r"(a[3]), "r"(b[0]), "r"(b[1]));
}
__device__ __forceinline__ void ldsm4(uint32_t* r, uint32_t a){
    asm volatile("ldmatrix.sync.aligned.m8n8.x4.shared.b16 {%0,%1,%2,%3}, [%4];"
        : "=r"(r[0]), "=r"(r[1]), "=r"(r[2]), "=r"(r[3]) : "r"(a));
}
__device__ __forceinline__ void cp16(uint32_t dst, const void* src){
    asm volatile("cp.async.cg.shared.global [%0], [%1], 16;\n" :: "r"(dst), "l"(src) : "memory");
}
__device__ __forceinline__ void cp_commit(){ asm volatile("cp.async.commit_group;\n" ::: "memory"); }
template<int N>
__device__ __forceinline__ void cp_wait(){ asm volatile("cp.async.wait_group %0;\n" :: "n"(N) : "memory"); }

__device__ __forceinline__ uint32_t swz(uint32_t o){ return o ^ ((o>>3)&0x30u); }

// ---------------- split kernels ----------------
__global__ void split_arr(const float4* __restrict__ src, bf16* __restrict__ h, bf16* __restrict__ l, int n4){
    int i = blockIdx.x*blockDim.x + threadIdx.x;
    if (i >= n4) return;
    float4 v = src[i];
    bf16 h0,l0,h1,l1,h2,l2,h3,l3;
    split2(v.x,h0,l0); split2(v.y,h1,l1); split2(v.z,h2,l2); split2(v.w,h3,l3);
    bf162* hp = (bf162*)(h + 4*(size_t)i);
    bf162* lp = (bf162*)(l + 4*(size_t)i);
    bf162 a; a.x=h0; a.y=h1; hp[0]=a;
    bf162 b; b.x=h2; b.y=h3; hp[1]=b;
    bf162 c; c.x=l0; c.y=l1; lp[0]=c;
    bf162 d; d.x=l2; d.y=l3; lp[1]=d;
}
__global__ void split_arr_f16(const float4* __restrict__ src, half* __restrict__ h, half* __restrict__ l, int n4){
    int i = blockIdx.x*blockDim.x + threadIdx.x;
    if (i >= n4) return;
    float4 v = src[i];
    half h0,l0,h1,l1,h2,l2,h3,l3;
    split2h(v.x,h0,l0); split2h(v.y,h1,l1); split2h(v.z,h2,l2); split2h(v.w,h3,l3);
    __half2* hp = (__half2*)(h + 4*(size_t)i);
    __half2* lp = (__half2*)(l + 4*(size_t)i);
    __half2 a; a.x=h0; a.y=h1; hp[0]=a;
    __half2 b; b.x=h2; b.y=h3; hp[1]=b;
    __half2 c; c.x=l0; c.y=l1; lp[0]=c;
    __half2 d; d.x=l2; d.y=l3; lp[1]=d;
}
__global__ void zero_tail_was(){
    int i = blockIdx.x*blockDim.x + threadIdx.x;
    if (i < (KVPAD-KVOUT)*DIM){
        bf16 z = __float2bfloat16_rn(0.f);
        g_was_h[(size_t)KVOUT*DIM + i] = z;
        g_was_l[(size_t)KVOUT*DIM + i] = z;
    }
}
__global__ void splitT_wkvb(const float* __restrict__ wb){
    int i = blockIdx.x*blockDim.x + threadIdx.x;
    if (i >= NH*KVR*NOPE) return;
    int d = i % NOPE, c = (i/NOPE) % KVR, h = i/(NOPE*KVR);
    float v = wb[((size_t)h*(NOPE+VDIM) + d)*KVR + c];
    split2(v, g_wbT_h[i], g_wbT_l[i]);
}

// ---------------- prep kernels ----------------
__global__ void rope_prep_kernel(const float* __restrict__ ang){
    int i = blockIdx.x*blockDim.x + threadIdx.x;
    if (i < S_LEN*RHALF){
        float a = ang[i];
        g_cos[i] = cosf(a);
        g_sin[i] = sinf(a);
    }
}

__global__ void prep_keff_kernel(const float* __restrict__ kvw){
    int t = blockIdx.x;
    int s = t % S_LEN;
    int tid = threadIdx.x;
    float v[4];
    #pragma unroll
    for (int j=0;j<4;j++){
        size_t idx = (size_t)t*KVPAD + 4*tid + j;
        v[j] = rejoin(g_kvs_h[idx], g_kvs_l[idx]);
    }
    float ss = v[0]*v[0]+v[1]*v[1]+v[2]*v[2]+v[3]*v[3];
    ss = warpSum(ss);
    __shared__ float red[4];
    if ((tid&31)==0) red[tid>>5] = ss;
    __syncthreads();
    float tot = red[0]+red[1]+red[2]+red[3];
    float r = rsqrtf(tot*(1.0f/KVR) + 1e-6f);
    #pragma unroll
    for (int j=0;j<4;j++){
        int c = 4*tid + j;
        float o = v[j]*r*kvw[c];
        bf16 h,l; split2(o,h,l);
        size_t di = (size_t)t*DEFF + c;
        g_ke_h[di]=h; g_ke_l[di]=l;
    }
    if (tid < RHALF){
        size_t pi = (size_t)t*KVPAD + KVR + 2*tid;
        float xr = rejoin(g_kvs_h[pi],   g_kvs_l[pi]);
        float xi = rejoin(g_kvs_h[pi+1], g_kvs_l[pi+1]);
        float c  = g_cos[s*RHALF+tid], sn = g_sin[s*RHALF+tid];
        float yr = xr*c - xi*sn, yi = xr*sn + xi*c;
        bf16 hr,lr,hi2,li; split2(yr,hr,lr); split2(yi,hi2,li);
        size_t di = (size_t)t*DEFF + KVR + 2*tid;
        g_ke_h[di]=hr; g_ke_l[di]=lr; g_ke_h[di+1]=hi2; g_ke_l[di+1]=li;
    }
}

// coalesced tiled transpose: ke (bf16 planes) -> keT (fp16 hi/lo, [b][DEFF][S])
__global__ void transpose_keT(){
    __shared__ half th[32][33], tl[32][33];
    int b = blockIdx.z;
    int c0 = blockIdx.y*32, s0 = blockIdx.x*32;
    int tx = threadIdx.x, ty = threadIdx.y;   // 32 x 8
    #pragma unroll
    for (int i=0;i<32;i+=8){
        size_t idx = (size_t)(b*S_LEN + s0 + ty + i)*DEFF + c0 + tx;
        float f = rejoin(g_ke_h[idx], g_ke_l[idx]);
        half h, l; split2h(f, h, l);
        th[ty+i][tx] = h; tl[ty+i][tx] = l;
    }
    __syncthreads();
    #pragma unroll
    for (int i=0;i<32;i+=8){
        size_t o = ((size_t)b*DEFF + c0 + ty + i)*S_LEN + s0 + tx;
        g_keT_h[o] = th[tx][ty+i];
        g_keT_l[o] = tl[tx][ty+i];
    }
}

// one block per token, 512 threads = 16 heads x 32 rope pairs
__global__ void prep_qpe_kernel(){
    int t = blockIdx.x;
    int b = t / S_LEN, s = t % S_LEN;
    int h = threadIdx.x >> 5, i = threadIdx.x & 31;
    size_t si = (size_t)t*QOUT + h*QD + NOPE + 2*i;
    float xr = rejoin(g_qs_h[si],   g_qs_l[si]);
    float xi = rejoin(g_qs_h[si+1], g_qs_l[si+1]);
    float c  = g_cos[s*RHALF+i], sn = g_sin[s*RHALF+i];
    float yr = xr*c - xi*sn, yi = xr*sn + xi*c;
    size_t di = ((size_t)(b*NH+h)*S_LEN + s)*DEFF + KVR + 2*i;
    bf16 hh,ll_; split2(yr,hh,ll_); g_qe_h[di]=hh;   g_qe_l[di]=ll_;
    split2(yi,hh,ll_);              g_qe_h[di+1]=hh; g_qe_l[di+1]=ll_;
}

// ---------------- split GEMM with ldmatrix ----------------
// F16A=false: bf16x3 (A/B hi+lo planes, 3 passes, 3 stages).
// F16A=true : A = single fp16 plane, B = fp16 hi/lo planes, 2 passes, 4 stages.
// OUT: 0 = fp32, 1 = bf16 hi/lo planes, 2 = single fp16 plane.
template<int BN_T, int OUT, bool F16A>
__global__ __launch_bounds__(256,2) void mma_gemm(
    const bf16* __restrict__ Ah, const bf16* __restrict__ Al,
    const bf16* __restrict__ Bh, const bf16* __restrict__ Bl,
    float* __restrict__ Cf, bf16* __restrict__ Ch, bf16* __restrict__ Cl,
    int K, int lda, int ldb, int ldc, int zdiv,
    ll zA1, ll zA2, ll zB1, ll zB2, ll zC1, ll zC2,
    float alpha, int causal, int klimit)
{
    if (causal && blockIdx.x > blockIdx.y) return;
    constexpr int NST = F16A ? 4 : 3;
    constexpr int WN  = BN_T/32;
    constexpr int WM  = 8/WN;
    constexpr int WTM = 128/WM;
    constexpr int MF  = WTM/16;
    constexpr int NF  = 4;
    constexpr int SA  = 128*64;
    constexpr int SB  = BN_T*64;
    constexpr int STG = F16A ? (SA + 2*SB) : (2*SA + 2*SB);

    extern __shared__ char smc[];
    const uint32_t sbase = smem_u32(smc);

    const int tid = threadIdx.x, lane = tid & 31, wid = tid >> 5;
    const int wm = wid / WN, wn = wid % WN;
    const int grp = lane >> 2, tig = lane & 3;
    const int lrow = lane & 7, sub = lane >> 3;
    const int zl = blockIdx.z % zdiv, zh = blockIdx.z / zdiv;
    const ll n0 = (ll)blockIdx.x * BN_T;

    const int aRowB = wm*WTM + ((sub&1)<<3) + lrow;
    const int aKo   = (sub>>1)<<4;
    const int bRowB = wn*32 + ((sub>>1)<<3) + lrow;
    const int bKo   = (sub&1)<<4;

    const ll aoff = zl*zA1 + zh*zA2 + (ll)blockIdx.y*128*lda;
    const bf16* Ahb = Ah + aoff;
    const bf16* Alb = Al + aoff;
    const ll boff = zl*zB1 + zh*zB2 + n0*ldb;
    const bf16* Bhb = Bh + boff;
    const bf16* Blb = Bl + boff;

    int kEnd = K;
    if (klimit){ int kl = ((int)blockIdx.y + 1)*128; if (kl < kEnd) kEnd = kl; }
    const int nk = kEnd >> 5;

    float acc[MF][NF][4];
    #pragma unroll
    for (int i=0;i<MF;i++)
        #pragma unroll
        for (int j=0;j<NF;j++)
            #pragma unroll
            for (int c=0;c<4;c++) acc[i][j][c] = 0.f;

    const int row = tid >> 2, g = tid & 3;

    auto LOAD = [&](int kb){
        const int s = kb % NST;
        const uint32_t ub = sbase + (uint32_t)(s*STG);
        const ll koff = ((ll)kb << 5) + g*8;
        #pragma unroll
        for (int i=0;i<2;i++){
            int r = row + i*64;
            uint32_t o = swz((uint32_t)(r*64 + g*16));
            cp16(ub + o, Ahb + (ll)r*lda + koff);
            if (!F16A) cp16(ub + SA + o, Alb + (ll)r*lda + koff);
        }
        const uint32_t bb = ub + (F16A ? SA : 2*SA);
        #pragma unroll
        for (int i=0;i<BN_T/64;i++){
            int r = row + i*64;
            uint32_t o = swz((uint32_t)(r*64 + g*16));
            cp16(bb + o,      Bhb + (ll)r*ldb + koff);
            cp16(bb + SB + o, Blb + (ll)r*ldb + koff);
        }
        cp_commit();
    };

    #pragma unroll
    for (int kb=0; kb<NST-1; kb++) if (kb < nk) LOAD(kb);

    for (int k=0; k<nk; k++){
        cp_wait<NST-2>();
        __syncthreads();
        if (k + NST - 1 < nk) LOAD(k + NST - 1);
        else cp_commit();

        const int s = k % NST;
        const uint32_t AH = sbase + (uint32_t)(s*STG);
        const uint32_t BH = AH + (F16A ? SA : 2*SA);
        const uint32_t AL = AH + SA;
        const uint32_t BL = BH + SB;

        #pragma unroll
        for (int kk=0; kk<2; kk++){
            const int ck = kk*32;
            uint32_t bh[2*NF], bl[2*NF];
            #pragma unroll
            for (int nfp=0; nfp<NF/2; nfp++){
                uint32_t bo = swz((uint32_t)((bRowB + nfp*16)*64 + ck + bKo));
                ldsm4(&bh[4*nfp], BH + bo);
                ldsm4(&bl[4*nfp], BL + bo);
            }
            #pragma unroll
            for (int mf=0; mf<MF; mf++){
                uint32_t ao = swz((uint32_t)((aRowB + mf*16)*64 + ck + aKo));
                uint32_t ah[4];
                ldsm4(ah, AH + ao);
                if (F16A){
                    #pragma unroll
                    for (int nf=0; nf<NF; nf++) mma_f16(acc[mf][nf], ah, &bh[2*nf]);
                    #pragma unroll
                    for (int nf=0; nf<NF; nf++) mma_f16(acc[mf][nf], ah, &bl[2*nf]);
                } else {
                    uint32_t al[4];
                    ldsm4(al, AL + ao);
                    #pragma unroll
                    for (int nf=0; nf<NF; nf++) mma_bf16(acc[mf][nf], ah, &bh[2*nf]);
                    #pragma unroll
                    for (int nf=0; nf<NF; nf++) mma_bf16(acc[mf][nf], ah, &bl[2*nf]);
                    #pragma unroll
                    for (int nf=0; nf<NF; nf++) mma_bf16(acc[mf][nf], al, &bh[2*nf]);
                }
            }
        }
    }

    // ---- epilogue ----
    const ll cbase = zl*zC1 + zh*zC2
                   + ((ll)blockIdx.y*128 + wm*WTM)*ldc + n0 + wn*32;
    #pragma unroll
    for (int mf=0; mf<MF; mf++){
        int r0 = mf*16 + grp;
        #pragma unroll
        for (int nf=0; nf<NF; nf++){
            int c = nf*8 + tig*2;
            #pragma unroll
            for (int half_=0; half_<2; half_++){
                ll off = cbase + (ll)(r0 + half_*8)*ldc + c;
                float v0 = acc[mf][nf][2*half_+0]*alpha;
                float v1 = acc[mf][nf][2*half_+1]*alpha;
                if (OUT == 1){
                    bf16 h0,l0,h1,l1;
                    split2(v0,h0,l0); split2(v1,h1,l1);
                    bf162 hp; hp.x=h0; hp.y=h1;
                    bf162 lp; lp.x=l0; lp.y=l1;
                    *(bf162*)(Ch + off) = hp;
                    *(bf162*)(Cl + off) = lp;
                } else if (OUT == 2){
                    __half2 hp;
                    hp.x = __float2half_rn(v0);
                    hp.y = __float2half_rn(v1);
                    *(__half2*)((half*)Ch + off) = hp;
                } else {
                    float2 o; o.x=v0; o.y=v1;
                    *(float2*)(Cf + off) = o;
                }
            }
        }
    }
}

// ---------------- causal softmax -> single fp16 probs ----------------
__global__ void softmax_kernel(){
    const int s = blockIdx.x;
    const ll z = blockIdx.y;
    const float* row = g_scores + (z*S_LEN + (ll)s)*S_LEN;
    half* pr = g_pr + (z*S_LEN + (ll)s)*S_LEN;
    const int n = s + 1;
    const int nend = ((s>>7)+1)<<7;
    const int tid = threadIdx.x;

    float e[16];
    float mx = -1e30f;
    #pragma unroll
    for (int i=0;i<16;i++){
        int t = tid + i*128;
        e[i] = (t < n) ? row[t] : -1e30f;
        mx = fmaxf(mx, e[i]);
    }
    mx = warpMax(mx);
    __shared__ float redm[4], reds[4];
    if ((tid&31)==0) redm[tid>>5] = mx;
    __syncthreads();
    mx = fmaxf(fmaxf(redm[0],redm[1]), fmaxf(redm[2],redm[3]));

    float sum = 0.f;
    #pragma unroll
    for (int i=0;i<16;i++){
        int t = tid + i*128;
        float v = (t < n) ? exp2f(e[i] - mx) : 0.f;
        e[i] = v;
        sum += v;
    }
    sum = warpSum(sum);
    if ((tid&31)==0) reds[tid>>5] = sum;
    __syncthreads();
    sum = reds[0]+reds[1]+reds[2]+reds[3];
    const float inv = 1.0f / sum;

    #pragma unroll
    for (int i=0;i<16;i++){
        int t = tid + i*128;
        if (t < nend) pr[t] = __float2half_rn(e[i]*inv);
    }
}

// ---------------- host side ----------------
// omode: 0 fp32, 1 bf16 hi/lo, 2 fp16 single
static void launch_g(int omode, bool f16a,
    const bf16* Ah, const bf16* Al, const bf16* Bh, const bf16* Bl,
    float* Cf, bf16* Ch, bf16* Cl,
    int M, int N, int K, int lda, int ldb, int ldc,
    int Z, int zdiv,
    ll zA1, ll zA2, ll zB1, ll zB2, ll zC1, ll zC2,
    float alpha, bool causal, bool klimit)
{
    dim3 grid(N/128, M/128, Z);
    int c = causal?1:0, kl = klimit?1:0;
    if (f16a){
        size_t sm = (size_t)4 * (128*64 + 2*128*64);
        if (omode == 2){
            cudaFuncSetAttribute(mma_gemm<128,2,true>, cudaFuncAttributeMaxDynamicSharedMemorySize, (int)sm);
            mma_gemm<128,2,true><<<grid,256,sm>>>(Ah,Al,Bh,Bl,Cf,Ch,Cl,K,lda,ldb,ldc,zdiv,zA1,zA2,zB1,zB2,zC1,zC2,alpha,c,kl);
        } else {
            cudaFuncSetAttribute(mma_gemm<128,0,true>, cudaFuncAttributeMaxDynamicSharedMemorySize, (int)sm);
            mma_gemm<128,0,true><<<grid,256,sm>>>(Ah,Al,Bh,Bl,Cf,Ch,Cl,K,lda,ldb,ldc,zdiv,zA1,zA2,zB1,zB2,zC1,zC2,alpha,c,kl);
        }
        return;
    }
    size_t sm = (size_t)3 * (2*128*64 + 2*128*64);
    if (omode == 1){
        cudaFuncSetAttribute(mma_gemm<128,1,false>, cudaFuncAttributeMaxDynamicSharedMemorySize, (int)sm);
        mma_gemm<128,1,false><<<grid,256,sm>>>(Ah,Al,Bh,Bl,Cf,Ch,Cl,K,lda,ldb,ldc,zdiv,zA1,zA2,zB1,zB2,zC1,zC2,alpha,c,kl);
    } else {
        cudaFuncSetAttribute(mma_gemm<128,0,false>, cudaFuncAttributeMaxDynamicSharedMemorySize, (int)sm);
        mma_gemm<128,0,false><<<grid,256,sm>>>(Ah,Al,Bh,Bl,Cf,Ch,Cl,K,lda,ldb,ldc,zdiv,zA1,zA2,zB1,zB2,zC1,zC2,alpha,c,kl);
    }
}

#define SYM(p, s) cudaGetSymbolAddress((void**)&p, s)

extern "C" void kernel_launch(void* const* d_in, const int* in_sizes, int n_in,
                              void* d_out, int out_size)
{
    (void)in_sizes; (void)n_in; (void)out_size;
    const float* x      = (const float*)d_in[0];
    const float* angles = (const float*)d_in[1];
    const float* wq     = (const float*)d_in[2];
    const float* wkv_a  = (const float*)d_in[3];
    const float* wkv_b  = (const float*)d_in[4];
    const float* wo     = (const float*)d_in[5];
    const float* kvw    = (const float*)d_in[6];
    float* out = (float*)d_out;

    bf16 *xsh,*xsl,*wqh,*wql,*wah,*wal,*wbTh,*wbTl;
    bf16 *qsh,*qsl,*keh,*kel,*qeh,*qel,*kvh,*kvl;
    half *wbfh,*wbfl,*wofh,*wofl,*keTh,*keTl,*pr,*ol,*os;
    float *sc;
    SYM(xsh,g_xs_h); SYM(xsl,g_xs_l); SYM(wqh,g_wqs_h); SYM(wql,g_wqs_l);
    SYM(wah,g_was_h); SYM(wal,g_was_l); SYM(wbfh,g_wbf_h); SYM(wbfl,g_wbf_l);
    SYM(wbTh,g_wbT_h); SYM(wbTl,g_wbT_l); SYM(wofh,g_wof_h); SYM(wofl,g_wof_l);
    SYM(qsh,g_qs_h); SYM(qsl,g_qs_l); SYM(kvh,g_kvs_h); SYM(kvl,g_kvs_l);
    SYM(keh,g_ke_h); SYM(kel,g_ke_l); SYM(keTh,g_keT_h); SYM(keTl,g_keT_l);
    SYM(qeh,g_qe_h); SYM(qel,g_qe_l); SYM(pr,g_pr);
    SYM(ol,g_ol); SYM(os,g_os);
    SYM(sc,g_scores);

    const double msc = 0.1*log(40.0) + 1.0;
    const float softmax_scale = (float)(pow((double)QD, -0.5)*msc*msc);
    const float score_alpha = (float)((double)softmax_scale * LOG2E);

    // 0) splits
    {
        int n;
        n = NTOK*DIM/4;            split_arr<<<(n+255)/256,256>>>((const float4*)x, xsh, xsl, n);
        n = QOUT*DIM/4;            split_arr<<<(n+255)/256,256>>>((const float4*)wq, wqh, wql, n);
        n = KVOUT*DIM/4;           split_arr<<<(n+255)/256,256>>>((const float4*)wkv_a, wah, wal, n);
        zero_tail_was<<<((KVPAD-KVOUT)*DIM+255)/256,256>>>();
        n = NH*(NOPE+VDIM)*KVR/4;  split_arr_f16<<<(n+255)/256,256>>>((const float4*)wkv_b, wbfh, wbfl, n);
        n = DIM*NH*VDIM/4;         split_arr_f16<<<(n+255)/256,256>>>((const float4*)wo, wofh, wofl, n);
        n = NH*KVR*NOPE;           splitT_wkvb<<<(n+255)/256,256>>>(wkv_b);
    }
    rope_prep_kernel<<<(S_LEN*RHALF+127)/128, 128>>>(angles);

    // 1) q = x @ wq^T (bf16x3)
    launch_g(1,false, xsh,xsl, wqh,wql, 0, qsh,qsl,
             NTOK, QOUT, DIM, DIM, DIM, QOUT, 1,1, 0,0,0,0,0,0, 1.f,false,false);

    // 2) kv = x @ wkv_a^T (bf16x3, N padded to 640)
    launch_g(1,false, xsh,xsl, wah,wal, 0, kvh,kvl,
             NTOK, KVPAD, DIM, DIM, DIM, KVPAD, 1,1, 0,0,0,0,0,0, 1.f,false,false);

    // 3) keff planes + fp16 keT transpose
    prep_keff_kernel<<<NTOK, 128>>>(kvw);
    transpose_keT<<<dim3(S_LEN/32, DEFF/32, BATCH), dim3(32,8)>>>();

    // 4) rope(q_pe)
    prep_qpe_kernel<<<NTOK, 512>>>();

    // 5) qeff[...,0:512] = q_nope @ wkv_bT (bf16x3, per (b,h), K=128)
    launch_g(1,false, qsh,qsl, wbTh,wbTl, 0, qeh,qel,
             S_LEN, KVR, NOPE, QOUT, NOPE, DEFF, BATCH*NH, NH,
             (ll)QD, (ll)S_LEN*QOUT, (ll)KVR*NOPE, 0,
             (ll)S_LEN*DEFF, (ll)NH*S_LEN*DEFF, 1.f,false,false);

    // 6) scores (bf16x3, causal block-skip)
    launch_g(0,false, qeh,qel, keh,kel, sc, 0,0,
             S_LEN, S_LEN, DEFF, DEFF, DEFF, S_LEN, BATCH*NH, NH,
             (ll)S_LEN*DEFF, (ll)NH*S_LEN*DEFF, 0, (ll)S_LEN*DEFF,
             (ll)S_LEN*S_LEN, (ll)NH*S_LEN*S_LEN, score_alpha, true, false);

    // 7) softmax -> fp16 probs
    softmax_kernel<<<dim3(S_LEN, BATCH*NH), 128>>>();

    // 8) olat = probs(fp16) @ keT(fp16 hi/lo)^T -> single fp16 olat, K capped
    launch_g(2,true, (const bf16*)pr, 0, (const bf16*)keTh, (const bf16*)keTl, 0, (bf16*)ol, 0,
             S_LEN, KVR, S_LEN, S_LEN, S_LEN, KVR, BATCH*NH, NH,
             (ll)S_LEN*S_LEN, (ll)NH*S_LEN*S_LEN, 0, (ll)DEFF*S_LEN,
             (ll)S_LEN*KVR, (ll)NH*S_LEN*KVR, 1.f, false, true);

    // 9) o = olat(fp16) @ wkv_b_v(fp16 hi/lo)^T -> single fp16 o (per (b,h), K=512)
    launch_g(2,true, (const bf16*)ol, 0, (const bf16*)(wbfh+(size_t)NOPE*KVR), (const bf16*)(wbfl+(size_t)NOPE*KVR), 0, (bf16*)os, 0,
             S_LEN, VDIM, KVR, KVR, KVR, NH*VDIM, BATCH*NH, NH,
             (ll)S_LEN*KVR, (ll)NH*S_LEN*KVR, (ll)(NOPE+VDIM)*KVR, 0,
             (ll)VDIM, (ll)S_LEN*NH*VDIM, 1.f, false, false);

    // 10) out = o(fp16) @ wo(fp16 hi/lo)^T -> fp32
    launch_g(0,true, (const bf16*)os, 0, (const bf16*)wofh, (const bf16*)wofl, out, 0,0,
             NTOK, DIM, NH*VDIM, NH*VDIM, NH*VDIM, DIM, 1,1,
             0,0,0,0,0,0, 1.f,false,false);
}

// round 10
// speedup vs baseline: 1.4857x; 1.1258x over previous
#include <cuda_runtime.h>
#include <cuda_bf16.h>
#include <cuda_fp16.h>
#include <math.h>
#include <stdint.h>

// ---------------- problem constants ----------------
#define S_LEN 2048
#define BATCH 2
#define NTOK  (S_LEN*BATCH)     // 4096
#define NH    16
#define DIM   2048
#define NOPE  128
#define ROPE  64
#define RHALF 32
#define VDIM  128
#define KVR   512
#define QD    (NOPE+ROPE)       // 192
#define QOUT  (NH*QD)           // 3072
#define KVOUT (KVR+ROPE)        // 576
#define KVPAD 640               // kv-proj N padded to 5*128
#define DEFF  576
#define LOG2E 1.4426950408889634

typedef long long ll;
typedef __nv_bfloat16 bf16;
typedef __nv_bfloat162 bf162;

// ---------------- scratch ----------------
__device__ __align__(16) bf16 g_xs_h [(size_t)NTOK*DIM],    g_xs_l [(size_t)NTOK*DIM];
__device__ __align__(16) bf16 g_wqs_h[(size_t)QOUT*DIM],    g_wqs_l[(size_t)QOUT*DIM];
__device__ __align__(16) bf16 g_was_h[(size_t)KVPAD*DIM],   g_was_l[(size_t)KVPAD*DIM];
__device__ __align__(16) half g_wbf_h[(size_t)NH*(NOPE+VDIM)*KVR], g_wbf_l[(size_t)NH*(NOPE+VDIM)*KVR];
__device__ __align__(16) bf16 g_wbT_h[(size_t)NH*KVR*NOPE], g_wbT_l[(size_t)NH*KVR*NOPE];
__device__ __align__(16) half g_wof_h[(size_t)DIM*NH*VDIM], g_wof_l[(size_t)DIM*NH*VDIM];
__device__ __align__(16) bf16 g_qs_h [(size_t)NTOK*QOUT],   g_qs_l [(size_t)NTOK*QOUT];
__device__ __align__(16) bf16 g_kvs_h[(size_t)NTOK*KVPAD],  g_kvs_l[(size_t)NTOK*KVPAD];
__device__ __align__(16) half g_ke_h [(size_t)NTOK*DEFF],   g_ke_l [(size_t)NTOK*DEFF];
__device__ __align__(16) half g_keT_h[(size_t)BATCH*DEFF*S_LEN], g_keT_l[(size_t)BATCH*DEFF*S_LEN];
__device__ __align__(16) half g_qe  [(size_t)BATCH*NH*S_LEN*DEFF];
__device__ float g_scores[(size_t)BATCH*NH*S_LEN*S_LEN];
__device__ __align__(16) half g_pr   [(size_t)BATCH*NH*S_LEN*S_LEN];
__device__ __align__(16) half g_ol   [(size_t)BATCH*NH*S_LEN*KVR];
__device__ __align__(16) half g_os   [(size_t)NTOK*NH*VDIM];
__device__ float g_cos[S_LEN*RHALF];
__device__ float g_sin[S_LEN*RHALF];

// ---------------- helpers ----------------
__device__ __forceinline__ float warpMax(float v){
    #pragma unroll
    for (int o=16;o;o>>=1) v = fmaxf(v, __shfl_xor_sync(0xffffffffu, v, o));
    return v;
}
__device__ __forceinline__ float warpSum(float v){
    #pragma unroll
    for (int o=16;o;o>>=1) v += __shfl_xor_sync(0xffffffffu, v, o);
    return v;
}
__device__ __forceinline__ uint32_t smem_u32(const void* p){
    uint32_t a;
    asm("{ .reg .u64 t; cvta.to.shared.u64 t, %1; cvt.u32.u64 %0, t; }" : "=r"(a) : "l"(p));
    return a;
}
__device__ __forceinline__ void split2(float f, bf16& h, bf16& l){
    h = __float2bfloat16_rn(f);
    l = __float2bfloat16_rn(f - __bfloat162float(h));
}
__device__ __forceinline__ void split2h(float f, half& h, half& l){
    h = __float2half_rn(f);
    l = __float2half_rn(f - __half2float(h));
}
__device__ __forceinline__ float rejoin(bf16 h, bf16 l){
    return __bfloat162float(h) + __bfloat162float(l);
}
__device__ __forceinline__ float rejoinh(half h, half l){
    return __half2float(h) + __half2float(l);
}
__device__ __forceinline__ void mma_bf16(float* d, const uint32_t* a, const uint32_t* b){
    asm volatile(
        "mma.sync.aligned.m16n8k16.row.col.f32.bf16.bf16.f32 "
        "{%0,%1,%2,%3}, {%4,%5,%6,%7}, {%8,%9}, {%0,%1,%2,%3};"
        : "+f"(d[0]), "+f"(d[1]), "+f"(d[2]), "+f"(d[3])
        : "r"(a[0]), "r"(a[1]), "r"(a[2]), "r"(a[3]), "r"(b[0]), "r"(b[1]));
}
__device__ __forceinline__ void mma_f16(float* d, const uint32_t* a, const uint32_t* b){
    asm volatile(
        "mma.sync.aligned.m16n8k16.row.col.f32.f16.f16.f32 "
        "{%0,%1,%2,%3}, {%4,%5,%6,%7}, {%8,%9}, {%0,%1,%2,%3};"
        : "+f"(d[0]), "+f"(d[1]), "+f"(d[2]), "+f"(d[3])
        : "r"(a[0]), "r"(a[1]), "r"(a[2]), "r"(a[3]), "r"(b[0]), "r"(b[1]));
}
__device__ __forceinline__ void ldsm4(uint32_t* r, uint32_t a){
    asm volatile("ldmatrix.sync.aligned.m8n8.x4.shared.b16 {%0,%1,%2,%3}, [%4];"
        : "=r"(r[0]), "=r"(r[1]), "=r"(r[2]), "=r"(r[3]) : "r"(a));
}
__device__ __forceinline__ void cp16(uint32_t dst, const void* src){
    asm volatile("cp.async.cg.shared.global [%0], [%1], 16;\n" :: "r"(dst), "l"(src) : "memory");
}
__device__ __forceinline__ void cp_commit(){ asm volatile("cp.async.commit_group;\n" ::: "memory"); }
template<int N>
__device__ __forceinline__ void cp_wait(){ asm volatile("cp.async.wait_group %0;\n" :: "n"(N) : "memory"); }

__device__ __forceinline__ uint32_t swz(uint32_t o){ return o ^ ((o>>3)&0x30u); }

// ---------------- split kernels ----------------
__global__ void split_arr(const float4* __restrict__ src, bf16* __restrict__ h, bf16* __restrict__ l, int n4){
    int i = blockIdx.x*blockDim.x + threadIdx.x;
    if (i >= n4) return;
    float4 v = src[i];
    bf16 h0,l0,h1,l1,h2,l2,h3,l3;
    split2(v.x,h0,l0); split2(v.y,h1,l1); split2(v.z,h2,l2); split2(v.w,h3,l3);
    bf162* hp = (bf162*)(h + 4*(size_t)i);
    bf162* lp = (bf162*)(l + 4*(size_t)i);
    bf162 a; a.x=h0; a.y=h1; hp[0]=a;
    bf162 b; b.x=h2; b.y=h3; hp[1]=b;
    bf162 c; c.x=l0; c.y=l1; lp[0]=c;
    bf162 d; d.x=l2; d.y=l3; lp[1]=d;
}
__global__ void split_arr_f16(const float4* __restrict__ src, half* __restrict__ h, half* __restrict__ l, int n4){
    int i = blockIdx.x*blockDim.x + threadIdx.x;
    if (i >= n4) return;
    float4 v = src[i];
    half h0,l0,h1,l1,h2,l2,h3,l3;
    split2h(v.x,h0,l0); split2h(v.y,h1,l1); split2h(v.z,h2,l2); split2h(v.w,h3,l3);
    __half2* hp = (__half2*)(h + 4*(size_t)i);
    __half2* lp = (__half2*)(l + 4*(size_t)i);
    __half2 a; a.x=h0; a.y=h1; hp[0]=a;
    __half2 b; b.x=h2; b.y=h3; hp[1]=b;
    __half2 c; c.x=l0; c.y=l1; lp[0]=c;
    __half2 d; d.x=l2; d.y=l3; lp[1]=d;
}
__global__ void zero_tail_was(){
    int i = blockIdx.x*blockDim.x + threadIdx.x;
    if (i < (KVPAD-KVOUT)*DIM){
        bf16 z = __float2bfloat16_rn(0.f);
        g_was_h[(size_t)KVOUT*DIM + i] = z;
        g_was_l[(size_t)KVOUT*DIM + i] = z;
    }
}
__global__ void splitT_wkvb(const float* __restrict__ wb){
    int i = blockIdx.x*blockDim.x + threadIdx.x;
    if (i >= NH*KVR*NOPE) return;
    int d = i % NOPE, c = (i/NOPE) % KVR, h = i/(NOPE*KVR);
    float v = wb[((size_t)h*(NOPE+VDIM) + d)*KVR + c];
    split2(v, g_wbT_h[i], g_wbT_l[i]);
}

// ---------------- prep kernels ----------------
__global__ void rope_prep_kernel(const float* __restrict__ ang){
    int i = blockIdx.x*blockDim.x + threadIdx.x;
    if (i < S_LEN*RHALF){
        float a = ang[i];
        g_cos[i] = cosf(a);
        g_sin[i] = sinf(a);
    }
}

__global__ void prep_keff_kernel(const float* __restrict__ kvw){
    int t = blockIdx.x;
    int s = t % S_LEN;
    int tid = threadIdx.x;
    float v[4];
    #pragma unroll
    for (int j=0;j<4;j++){
        size_t idx = (size_t)t*KVPAD + 4*tid + j;
        v[j] = rejoin(g_kvs_h[idx], g_kvs_l[idx]);
    }
    float ss = v[0]*v[0]+v[1]*v[1]+v[2]*v[2]+v[3]*v[3];
    ss = warpSum(ss);
    __shared__ float red[4];
    if ((tid&31)==0) red[tid>>5] = ss;
    __syncthreads();
    float tot = red[0]+red[1]+red[2]+red[3];
    float r = rsqrtf(tot*(1.0f/KVR) + 1e-6f);
    #pragma unroll
    for (int j=0;j<4;j++){
        int c = 4*tid + j;
        float o = v[j]*r*kvw[c];
        half h,l; split2h(o,h,l);
        size_t di = (size_t)t*DEFF + c;
        g_ke_h[di]=h; g_ke_l[di]=l;
    }
    if (tid < RHALF){
        size_t pi = (size_t)t*KVPAD + KVR + 2*tid;
        float xr = rejoin(g_kvs_h[pi],   g_kvs_l[pi]);
        float xi = rejoin(g_kvs_h[pi+1], g_kvs_l[pi+1]);
        float c  = g_cos[s*RHALF+tid], sn = g_sin[s*RHALF+tid];
        float yr = xr*c - xi*sn, yi = xr*sn + xi*c;
        half hr,lr,hi2,li; split2h(yr,hr,lr); split2h(yi,hi2,li);
        size_t di = (size_t)t*DEFF + KVR + 2*tid;
        g_ke_h[di]=hr; g_ke_l[di]=lr; g_ke_h[di+1]=hi2; g_ke_l[di+1]=li;
    }
}

// coalesced tiled transpose: ke (fp16 planes) -> keT (fp16 hi/lo, [b][DEFF][S])
__global__ void transpose_keT(){
    __shared__ half th[32][33], tl[32][33];
    int b = blockIdx.z;
    int c0 = blockIdx.y*32, s0 = blockIdx.x*32;
    int tx = threadIdx.x, ty = threadIdx.y;   // 32 x 8
    #pragma unroll
    for (int i=0;i<32;i+=8){
        size_t idx = (size_t)(b*S_LEN + s0 + ty + i)*DEFF + c0 + tx;
        th[ty+i][tx] = g_ke_h[idx];
        tl[ty+i][tx] = g_ke_l[idx];
    }
    __syncthreads();
    #pragma unroll
    for (int i=0;i<32;i+=8){
        size_t o = ((size_t)b*DEFF + c0 + ty + i)*S_LEN + s0 + tx;
        g_keT_h[o] = th[tx][ty+i];
        g_keT_l[o] = tl[tx][ty+i];
    }
}

// one block per token, 512 threads = 16 heads x 32 rope pairs
__global__ void prep_qpe_kernel(){
    int t = blockIdx.x;
    int b = t / S_LEN, s = t % S_LEN;
    int h = threadIdx.x >> 5, i = threadIdx.x & 31;
    size_t si = (size_t)t*QOUT + h*QD + NOPE + 2*i;
    float xr = rejoin(g_qs_h[si],   g_qs_l[si]);
    float xi = rejoin(g_qs_h[si+1], g_qs_l[si+1]);
    float c  = g_cos[s*RHALF+i], sn = g_sin[s*RHALF+i];
    float yr = xr*c - xi*sn, yi = xr*sn + xi*c;
    size_t di = ((size_t)(b*NH+h)*S_LEN + s)*DEFF + KVR + 2*i;
    g_qe[di]   = __float2half_rn(yr);
    g_qe[di+1] = __float2half_rn(yi);
}

// ---------------- split GEMM with ldmatrix ----------------
// F16A=false: bf16x3 (A/B hi+lo planes, 3 passes, 3 stages).
// F16A=true : A = single fp16 plane, B = fp16 hi/lo planes, 2 passes, 4 stages.
// OUT: 0 = fp32, 1 = bf16 hi/lo planes, 2 = single fp16 plane.
template<int BN_T, int OUT, bool F16A>
__global__ __launch_bounds__(256,2) void mma_gemm(
    const bf16* __restrict__ Ah, const bf16* __restrict__ Al,
    const bf16* __restrict__ Bh, const bf16* __restrict__ Bl,
    float* __restrict__ Cf, bf16* __restrict__ Ch, bf16* __restrict__ Cl,
    int K, int lda, int ldb, int ldc, int zdiv,
    ll zA1, ll zA2, ll zB1, ll zB2, ll zC1, ll zC2,
    float alpha, int causal, int klimit)
{
    if (causal && blockIdx.x > blockIdx.y) return;
    constexpr int NST = F16A ? 4 : 3;
    constexpr int WN  = BN_T/32;
    constexpr int WM  = 8/WN;
    constexpr int WTM = 128/WM;
    constexpr int MF  = WTM/16;
    constexpr int NF  = 4;
    constexpr int SA  = 128*64;
    constexpr int SB  = BN_T*64;
    constexpr int STG = F16A ? (SA + 2*SB) : (2*SA + 2*SB);

    extern __shared__ char smc[];
    const uint32_t sbase = smem_u32(smc);

    const int tid = threadIdx.x, lane = tid & 31, wid = tid >> 5;
    const int wm = wid / WN, wn = wid % WN;
    const int grp = lane >> 2, tig = lane & 3;
    const int lrow = lane & 7, sub = lane >> 3;
    const int zl = blockIdx.z % zdiv, zh = blockIdx.z / zdiv;
    const ll n0 = (ll)blockIdx.x * BN_T;

    const int aRowB = wm*WTM + ((sub&1)<<3) + lrow;
    const int aKo   = (sub>>1)<<4;
    const int bRowB = wn*32 + ((sub>>1)<<3) + lrow;
    const int bKo   = (sub&1)<<4;

    const ll aoff = zl*zA1 + zh*zA2 + (ll)blockIdx.y*128*lda;
    const bf16* Ahb = Ah + aoff;
    const bf16* Alb = Al + aoff;
    const ll boff = zl*zB1 + zh*zB2 + n0*ldb;
    const bf16* Bhb = Bh + boff;
    const bf16* Blb = Bl + boff;

    int kEnd = K;
    if (klimit){ int kl = ((int)blockIdx.y + 1)*128; if (kl < kEnd) kEnd = kl; }
    const int nk = kEnd >> 5;

    float acc[MF][NF][4];
    #pragma unroll
    for (int i=0;i<MF;i++)
        #pragma unroll
        for (int j=0;j<NF;j++)
            #pragma unroll
            for (int c=0;c<4;c++) acc[i][j][c] = 0.f;

    const int row = tid >> 2, g = tid & 3;

    auto LOAD = [&](int kb){
        const int s = kb % NST;
        const uint32_t ub = sbase + (uint32_t)(s*STG);
        const ll koff = ((ll)kb << 5) + g*8;
        #pragma unroll
        for (int i=0;i<2;i++){
            int r = row + i*64;
            uint32_t o = swz((uint32_t)(r*64 + g*16));
            cp16(ub + o, Ahb + (ll)r*lda + koff);
            if (!F16A) cp16(ub + SA + o, Alb + (ll)r*lda + koff);
        }
        const uint32_t bb = ub + (F16A ? SA : 2*SA);
        #pragma unroll
        for (int i=0;i<BN_T/64;i++){
            int r = row + i*64;
            uint32_t o = swz((uint32_t)(r*64 + g*16));
            cp16(bb + o,      Bhb + (ll)r*ldb + koff);
            cp16(bb + SB + o, Blb + (ll)r*ldb + koff);
        }
        cp_commit();
    };

    #pragma unroll
    for (int kb=0; kb<NST-1; kb++) if (kb < nk) LOAD(kb);

    for (int k=0; k<nk; k++){
        cp_wait<NST-2>();
        __syncthreads();
        if (k + NST - 1 < nk) LOAD(k + NST - 1);
        else cp_commit();

        const int s = k % NST;
        const uint32_t AH = sbase + (uint32_t)(s*STG);
        const uint32_t BH = AH + (F16A ? SA : 2*SA);
        const uint32_t AL = AH + SA;
        const uint32_t BL = BH + SB;

        #pragma unroll
        for (int kk=0; kk<2; kk++){
            const int ck = kk*32;
            uint32_t bh[2*NF], bl[2*NF];
            #pragma unroll
            for (int nfp=0; nfp<NF/2; nfp++){
                uint32_t bo = swz((uint32_t)((bRowB + nfp*16)*64 + ck + bKo));
                ldsm4(&bh[4*nfp], BH + bo);
                ldsm4(&bl[4*nfp], BL + bo);
            }
            #pragma unroll
            for (int mf=0; mf<MF; mf++){
                uint32_t ao = swz((uint32_t)((aRowB + mf*16)*64 + ck + aKo));
                uint32_t ah[4];
                ldsm4(ah, AH + ao);
                if (F16A){
                    #pragma unroll
                    for (int nf=0; nf<NF; nf++) mma_f16(acc[mf][nf], ah, &bh[2*nf]);
                    #pragma unroll
                    for (int nf=0; nf<NF; nf++) mma_f16(acc[mf][nf], ah, &bl[2*nf]);
                } else {
                    uint32_t al[4];
                    ldsm4(al, AL + ao);
                    #pragma unroll
                    for (int nf=0; nf<NF; nf++) mma_bf16(acc[mf][nf], ah, &bh[2*nf]);
                    #pragma unroll
                    for (int nf=0; nf<NF; nf++) mma_bf16(acc[mf][nf], ah, &bl[2*nf]);
                    #pragma unroll
                    for (int nf=0; nf<NF; nf++) mma_bf16(acc[mf][nf], al, &bh[2*nf]);
                }
            }
        }
    }

    // ---- epilogue ----
    const ll cbase = zl*zC1 + zh*zC2
                   + ((ll)blockIdx.y*128 + wm*WTM)*ldc + n0 + wn*32;
    #pragma unroll
    for (int mf=0; mf<MF; mf++){
        int r0 = mf*16 + grp;
        #pragma unroll
        for (int nf=0; nf<NF; nf++){
            int c = nf*8 + tig*2;
            #pragma unroll
            for (int half_=0; half_<2; half_++){
                ll off = cbase + (ll)(r0 + half_*8)*ldc + c;
                float v0 = acc[mf][nf][2*half_+0]*alpha;
                float v1 = acc[mf][nf][2*half_+1]*alpha;
                if (OUT == 1){
                    bf16 h0,l0,h1,l1;
                    split2(v0,h0,l0); split2(v1,h1,l1);
                    bf162 hp; hp.x=h0; hp.y=h1;
                    bf162 lp; lp.x=l0; lp.y=l1;
                    *(bf162*)(Ch + off) = hp;
                    *(bf162*)(Cl + off) = lp;
                } else if (OUT == 2){
                    __half2 hp;
                    hp.x = __float2half_rn(v0);
                    hp.y = __float2half_rn(v1);
                    *(__half2*)((half*)Ch + off) = hp;
                } else {
                    float2 o; o.x=v0; o.y=v1;
                    *(float2*)(Cf + off) = o;
                }
            }
        }
    }
}

// ---------------- causal softmax -> single fp16 probs ----------------
__global__ void softmax_kernel(){
    const int s = blockIdx.x;
    const ll z = blockIdx.y;
    const float* row = g_scores + (z*S_LEN + (ll)s)*S_LEN;
    half* pr = g_pr + (z*S_LEN + (ll)s)*S_LEN;
    const int n = s + 1;
    const int nend = ((s>>7)+1)<<7;
    const int tid = threadIdx.x;

    float e[16];
    float mx = -1e30f;
    #pragma unroll
    for (int i=0;i<16;i++){
        int t = tid + i*128;
        e[i] = (t < n) ? row[t] : -1e30f;
        mx = fmaxf(mx, e[i]);
    }
    mx = warpMax(mx);
    __shared__ float redm[4], reds[4];
    if ((tid&31)==0) redm[tid>>5] = mx;
    __syncthreads();
    mx = fmaxf(fmaxf(redm[0],redm[1]), fmaxf(redm[2],redm[3]));

    float sum = 0.f;
    #pragma unroll
    for (int i=0;i<16;i++){
        int t = tid + i*128;
        float v = (t < n) ? exp2f(e[i] - mx) : 0.f;
        e[i] = v;
        sum += v;
    }
    sum = warpSum(sum);
    if ((tid&31)==0) reds[tid>>5] = sum;
    __syncthreads();
    sum = reds[0]+reds[1]+reds[2]+reds[3];
    const float inv = 1.0f / sum;

    #pragma unroll
    for (int i=0;i<16;i++){
        int t = tid + i*128;
        if (t < nend) pr[t] = __float2half_rn(e[i]*inv);
    }
}

// ---------------- host side ----------------
// omode: 0 fp32, 1 bf16 hi/lo, 2 fp16 single
static void launch_g(int omode, bool f16a,
    const bf16* Ah, const bf16* Al, const bf16* Bh, const bf16* Bl,
    float* Cf, bf16* Ch, bf16* Cl,
    int M, int N, int K, int lda, int ldb, int ldc,
    int Z, int zdiv,
    ll zA1, ll zA2, ll zB1, ll zB2, ll zC1, ll zC2,
    float alpha, bool causal, bool klimit)
{
    dim3 grid(N/128, M/128, Z);
    int c = causal?1:0, kl = klimit?1:0;
    if (f16a){
        size_t sm = (size_t)4 * (128*64 + 2*128*64);
        if (omode == 2){
            cudaFuncSetAttribute(mma_gemm<128,2,true>, cudaFuncAttributeMaxDynamicSharedMemorySize, (int)sm);
            mma_gemm<128,2,true><<<grid,256,sm>>>(Ah,Al,Bh,Bl,Cf,Ch,Cl,K,lda,ldb,ldc,zdiv,zA1,zA2,zB1,zB2,zC1,zC2,alpha,c,kl);
        } else {
            cudaFuncSetAttribute(mma_gemm<128,0,true>, cudaFuncAttributeMaxDynamicSharedMemorySize, (int)sm);
            mma_gemm<128,0,true><<<grid,256,sm>>>(Ah,Al,Bh,Bl,Cf,Ch,Cl,K,lda,ldb,ldc,zdiv,zA1,zA2,zB1,zB2,zC1,zC2,alpha,c,kl);
        }
        return;
    }
    size_t sm = (size_t)3 * (2*128*64 + 2*128*64);
    if (omode == 1){
        cudaFuncSetAttribute(mma_gemm<128,1,false>, cudaFuncAttributeMaxDynamicSharedMemorySize, (int)sm);
        mma_gemm<128,1,false><<<grid,256,sm>>>(Ah,Al,Bh,Bl,Cf,Ch,Cl,K,lda,ldb,ldc,zdiv,zA1,zA2,zB1,zB2,zC1,zC2,alpha,c,kl);
    } else if (omode == 2){
        cudaFuncSetAttribute(mma_gemm<128,2,false>, cudaFuncAttributeMaxDynamicSharedMemorySize, (int)sm);
        mma_gemm<128,2,false><<<grid,256,sm>>>(Ah,Al,Bh,Bl,Cf,Ch,Cl,K,lda,ldb,ldc,zdiv,zA1,zA2,zB1,zB2,zC1,zC2,alpha,c,kl);
    } else {
        cudaFuncSetAttribute(mma_gemm<128,0,false>, cudaFuncAttributeMaxDynamicSharedMemorySize, (int)sm);
        mma_gemm<128,0,false><<<grid,256,sm>>>(Ah,Al,Bh,Bl,Cf,Ch,Cl,K,lda,ldb,ldc,zdiv,zA1,zA2,zB1,zB2,zC1,zC2,alpha,c,kl);
    }
}

#define SYM(p, s) cudaGetSymbolAddress((void**)&p, s)

extern "C" void kernel_launch(void* const* d_in, const int* in_sizes, int n_in,
                              void* d_out, int out_size)
{
    (void)in_sizes; (void)n_in; (void)out_size;
    const float* x      = (const float*)d_in[0];
    const float* angles = (const float*)d_in[1];
    const float* wq     = (const float*)d_in[2];
    const float* wkv_a  = (const float*)d_in[3];
    const float* wkv_b  = (const float*)d_in[4];
    const float* wo     = (const float*)d_in[5];
    const float* kvw    = (const float*)d_in[6];
    float* out = (float*)d_out;

    bf16 *xsh,*xsl,*wqh,*wql,*wah,*wal,*wbTh,*wbTl;
    bf16 *qsh,*qsl,*kvh,*kvl;
    half *wbfh,*wbfl,*wofh,*wofl,*keh,*kel,*keTh,*keTl,*qe,*pr,*ol,*os;
    float *sc;
    SYM(xsh,g_xs_h); SYM(xsl,g_xs_l); SYM(wqh,g_wqs_h); SYM(wql,g_wqs_l);
    SYM(wah,g_was_h); SYM(wal,g_was_l); SYM(wbfh,g_wbf_h); SYM(wbfl,g_wbf_l);
    SYM(wbTh,g_wbT_h); SYM(wbTl,g_wbT_l); SYM(wofh,g_wof_h); SYM(wofl,g_wof_l);
    SYM(qsh,g_qs_h); SYM(qsl,g_qs_l); SYM(kvh,g_kvs_h); SYM(kvl,g_kvs_l);
    SYM(keh,g_ke_h); SYM(kel,g_ke_l); SYM(keTh,g_keT_h); SYM(keTl,g_keT_l);
    SYM(qe,g_qe); SYM(pr,g_pr);
    SYM(ol,g_ol); SYM(os,g_os);
    SYM(sc,g_scores);

    const double msc = 0.1*log(40.0) + 1.0;
    const float softmax_scale = (float)(pow((double)QD, -0.5)*msc*msc);
    const float score_alpha = (float)((double)softmax_scale * LOG2E);

    // 0) splits
    {
        int n;
        n = NTOK*DIM/4;            split_arr<<<(n+255)/256,256>>>((const float4*)x, xsh, xsl, n);
        n = QOUT*DIM/4;            split_arr<<<(n+255)/256,256>>>((const float4*)wq, wqh, wql, n);
        n = KVOUT*DIM/4;           split_arr<<<(n+255)/256,256>>>((const float4*)wkv_a, wah, wal, n);
        zero_tail_was<<<((KVPAD-KVOUT)*DIM+255)/256,256>>>();
        n = NH*(NOPE+VDIM)*KVR/4;  split_arr_f16<<<(n+255)/256,256>>>((const float4*)wkv_b, wbfh, wbfl, n);
        n = DIM*NH*VDIM/4;         split_arr_f16<<<(n+255)/256,256>>>((const float4*)wo, wofh, wofl, n);
        n = NH*KVR*NOPE;           splitT_wkvb<<<(n+255)/256,256>>>(wkv_b);
    }
    rope_prep_kernel<<<(S_LEN*RHALF+127)/128, 128>>>(angles);

    // 1) q = x @ wq^T (bf16x3)
    launch_g(1,false, xsh,xsl, wqh,wql, 0, qsh,qsl,
             NTOK, QOUT, DIM, DIM, DIM, QOUT, 1,1, 0,0,0,0,0,0, 1.f,false,false);

    // 2) kv = x @ wkv_a^T (bf16x3, N padded to 640)
    launch_g(1,false, xsh,xsl, wah,wal, 0, kvh,kvl,
             NTOK, KVPAD, DIM, DIM, DIM, KVPAD, 1,1, 0,0,0,0,0,0, 1.f,false,false);

    // 3) keff fp16 hi/lo planes + keT transpose
    prep_keff_kernel<<<NTOK, 128>>>(kvw);
    transpose_keT<<<dim3(S_LEN/32, DEFF/32, BATCH), dim3(32,8)>>>();

    // 4) rope(q_pe) -> qe fp16
    prep_qpe_kernel<<<NTOK, 512>>>();

    // 5) qe[...,0:512] = q_nope @ wkv_bT (bf16x3 internal, fp16-single output)
    launch_g(2,false, qsh,qsl, wbTh,wbTl, 0, (bf16*)qe, 0,
             S_LEN, KVR, NOPE, QOUT, NOPE, DEFF, BATCH*NH, NH,
             (ll)QD, (ll)S_LEN*QOUT, (ll)KVR*NOPE, 0,
             (ll)S_LEN*DEFF, (ll)NH*S_LEN*DEFF, 1.f,false,false);

    // 6) scores = scale * qe(fp16) @ ke(fp16 hi/lo)^T  (2-pass, causal block-skip)
    launch_g(0,true, (const bf16*)qe, 0, (const bf16*)keh, (const bf16*)kel, sc, 0,0,
             S_LEN, S_LEN, DEFF, DEFF, DEFF, S_LEN, BATCH*NH, NH,
             (ll)S_LEN*DEFF, (ll)NH*S_LEN*DEFF, 0, (ll)S_LEN*DEFF,
             (ll)S_LEN*S_LEN, (ll)NH*S_LEN*S_LEN, score_alpha, true, false);

    // 7) softmax -> fp16 probs
    softmax_kernel<<<dim3(S_LEN, BATCH*NH), 128>>>();

    // 8) olat = probs(fp16) @ keT(fp16 hi/lo)^T -> fp16, K capped
    launch_g(2,true, (const bf16*)pr, 0, (const bf16*)keTh, (const bf16*)keTl, 0, (bf16*)ol, 0,
             S_LEN, KVR, S_LEN, S_LEN, S_LEN, KVR, BATCH*NH, NH,
             (ll)S_LEN*S_LEN, (ll)NH*S_LEN*S_LEN, 0, (ll)DEFF*S_LEN,
             (ll)S_LEN*KVR, (ll)NH*S_LEN*KVR, 1.f, false, true);

    // 9) o = olat(fp16) @ wkv_b_v(fp16 hi/lo)^T -> fp16 (per (b,h), K=512)
    launch_g(2,true, (const bf16*)ol, 0, (const bf16*)(wbfh+(size_t)NOPE*KVR), (const bf16*)(wbfl+(size_t)NOPE*KVR), 0, (bf16*)os, 0,
             S_LEN, VDIM, KVR, KVR, KVR, NH*VDIM, BATCH*NH, NH,
             (ll)S_LEN*KVR, (ll)NH*S_LEN*KVR, (ll)(NOPE+VDIM)*KVR, 0,
             (ll)VDIM, (ll)S_LEN*NH*VDIM, 1.f, false, false);

    // 10) out = o(fp16) @ wo(fp16 hi/lo)^T -> fp32
    launch_g(0,true, (const bf16*)os, 0, (const bf16*)wofh, (const bf16*)wofl, out, 0,0,
             NTOK, DIM, NH*VDIM, NH*VDIM, NH*VDIM, DIM, 1,1,
             0,0,0,0,0,0, 1.f,false,false);
}

// round 11
// speedup vs baseline: 1.8972x; 1.2770x over previous
#include <cuda_runtime.h>
#include <cuda_bf16.h>
#include <cuda_fp16.h>
#include <math.h>
#include <stdint.h>

// ---------------- problem constants ----------------
#define S_LEN 2048
#define BATCH 2
#define NTOK  (S_LEN*BATCH)     // 4096
#define NH    16
#define DIM   2048
#define NOPE  128
#define ROPE  64
#define RHALF 32
#define VDIM  128
#define KVR   512
#define QD    (NOPE+ROPE)       // 192
#define QOUT  (NH*QD)           // 3072
#define KVOUT (KVR+ROPE)        // 576
#define KVPAD 640               // kv-proj N padded to 5*128
#define DEFF  576
#define LOG2E 1.4426950408889634

typedef long long ll;
typedef __nv_bfloat16 bf16;
typedef __nv_bfloat162 bf162;

// ---------------- scratch ----------------
__device__ __align__(16) bf16 g_xs_h [(size_t)NTOK*DIM],    g_xs_l [(size_t)NTOK*DIM];
__device__ __align__(16) bf16 g_wqs_h[(size_t)QOUT*DIM],    g_wqs_l[(size_t)QOUT*DIM];
__device__ __align__(16) bf16 g_was_h[(size_t)KVPAD*DIM],   g_was_l[(size_t)KVPAD*DIM];
__device__ __align__(16) half g_wbf_h[(size_t)NH*(NOPE+VDIM)*KVR], g_wbf_l[(size_t)NH*(NOPE+VDIM)*KVR];
__device__ __align__(16) bf16 g_wbT_h[(size_t)NH*KVR*NOPE], g_wbT_l[(size_t)NH*KVR*NOPE];
__device__ __align__(16) half g_wof_h[(size_t)DIM*NH*VDIM], g_wof_l[(size_t)DIM*NH*VDIM];
__device__ __align__(16) bf16 g_qs_h [(size_t)NTOK*QOUT],   g_qs_l [(size_t)NTOK*QOUT];
__device__ __align__(16) bf16 g_kvs_h[(size_t)NTOK*KVPAD],  g_kvs_l[(size_t)NTOK*KVPAD];
__device__ __align__(16) half g_ke  [(size_t)NTOK*DEFF];
__device__ __align__(16) half g_keT [(size_t)BATCH*DEFF*S_LEN];
__device__ __align__(16) half g_qe  [(size_t)BATCH*NH*S_LEN*DEFF];
__device__ float g_scores[(size_t)BATCH*NH*S_LEN*S_LEN];
__device__ __align__(16) half g_pr   [(size_t)BATCH*NH*S_LEN*S_LEN];
__device__ __align__(16) half g_ol   [(size_t)BATCH*NH*S_LEN*KVR];
__device__ __align__(16) half g_os   [(size_t)NTOK*NH*VDIM];
__device__ float g_cos[S_LEN*RHALF];
__device__ float g_sin[S_LEN*RHALF];

// ---------------- helpers ----------------
__device__ __forceinline__ float warpMax(float v){
    #pragma unroll
    for (int o=16;o;o>>=1) v = fmaxf(v, __shfl_xor_sync(0xffffffffu, v, o));
    return v;
}
__device__ __forceinline__ float warpSum(float v){
    #pragma unroll
    for (int o=16;o;o>>=1) v += __shfl_xor_sync(0xffffffffu, v, o);
    return v;
}
__device__ __forceinline__ uint32_t smem_u32(const void* p){
    uint32_t a;
    asm("{ .reg .u64 t; cvta.to.shared.u64 t, %1; cvt.u32.u64 %0, t; }" : "=r"(a) : "l"(p));
    return a;
}
__device__ __forceinline__ void split2(float f, bf16& h, bf16& l){
    h = __float2bfloat16_rn(f);
    l = __float2bfloat16_rn(f - __bfloat162float(h));
}
__device__ __forceinline__ void split2h(float f, half& h, half& l){
    h = __float2half_rn(f);
    l = __float2half_rn(f - __half2float(h));
}
__device__ __forceinline__ float rejoin(bf16 h, bf16 l){
    return __bfloat162float(h) + __bfloat162float(l);
}
__device__ __forceinline__ void mma_bf16(float* d, const uint32_t* a, const uint32_t* b){
    asm volatile(
        "mma.sync.aligned.m16n8k16.row.col.f32.bf16.bf16.f32 "
        "{%0,%1,%2,%3}, {%4,%5,%6,%7}, {%8,%9}, {%0,%1,%2,%3};"
        : "+f"(d[0]), "+f"(d[1]), "+f"(d[2]), "+f"(d[3])
        : "r"(a[0]), "r"(a[1]), "r"(a[2]), "r"(a[3]), "r"(b[0]), "r"(b[1]));
}
__device__ __forceinline__ void mma_f16(float* d, const uint32_t* a, const uint32_t* b){
    asm volatile(
        "mma.sync.aligned.m16n8k16.row.col.f32.f16.f16.f32 "
        "{%0,%1,%2,%3}, {%4,%5,%6,%7}, {%8,%9}, {%0,%1,%2,%3};"
        : "+f"(d[0]), "+f"(d[1]), "+f"(d[2]), "+f"(d[3])
        : "r"(a[0]), "r"(a[1]), "r"(a[2]), "r"(a[3]), "r"(b[0]), "r"(b[1]));
}
__device__ __forceinline__ void ldsm4(uint32_t* r, uint32_t a){
    asm volatile("ldmatrix.sync.aligned.m8n8.x4.shared.b16 {%0,%1,%2,%3}, [%4];"
        : "=r"(r[0]), "=r"(r[1]), "=r"(r[2]), "=r"(r[3]) : "r"(a));
}
__device__ __forceinline__ void cp16(uint32_t dst, const void* src){
    asm volatile("cp.async.cg.shared.global [%0], [%1], 16;\n" :: "r"(dst), "l"(src) : "memory");
}
__device__ __forceinline__ void cp_commit(){ asm volatile("cp.async.commit_group;\n" ::: "memory"); }
template<int N>
__device__ __forceinline__ void cp_wait(){ asm volatile("cp.async.wait_group %0;\n" :: "n"(N) : "memory"); }

__device__ __forceinline__ uint32_t swz(uint32_t o){ return o ^ ((o>>3)&0x30u); }

// ---------------- split kernels ----------------
__global__ void split_arr(const float4* __restrict__ src, bf16* __restrict__ h, bf16* __restrict__ l, int n4){
    int i = blockIdx.x*blockDim.x + threadIdx.x;
    if (i >= n4) return;
    float4 v = src[i];
    bf16 h0,l0,h1,l1,h2,l2,h3,l3;
    split2(v.x,h0,l0); split2(v.y,h1,l1); split2(v.z,h2,l2); split2(v.w,h3,l3);
    bf162* hp = (bf162*)(h + 4*(size_t)i);
    bf162* lp = (bf162*)(l + 4*(size_t)i);
    bf162 a; a.x=h0; a.y=h1; hp[0]=a;
    bf162 b; b.x=h2; b.y=h3; hp[1]=b;
    bf162 c; c.x=l0; c.y=l1; lp[0]=c;
    bf162 d; d.x=l2; d.y=l3; lp[1]=d;
}
__global__ void split_arr_f16(const float4* __restrict__ src, half* __restrict__ h, half* __restrict__ l, int n4){
    int i = blockIdx.x*blockDim.x + threadIdx.x;
    if (i >= n4) return;
    float4 v = src[i];
    half h0,l0,h1,l1,h2,l2,h3,l3;
    split2h(v.x,h0,l0); split2h(v.y,h1,l1); split2h(v.z,h2,l2); split2h(v.w,h3,l3);
    __half2* hp = (__half2*)(h + 4*(size_t)i);
    __half2* lp = (__half2*)(l + 4*(size_t)i);
    __half2 a; a.x=h0; a.y=h1; hp[0]=a;
    __half2 b; b.x=h2; b.y=h3; hp[1]=b;
    __half2 c; c.x=l0; c.y=l1; lp[0]=c;
    __half2 d; d.x=l2; d.y=l3; lp[1]=d;
}
__global__ void zero_tail_was(){
    int i = blockIdx.x*blockDim.x + threadIdx.x;
    if (i < (KVPAD-KVOUT)*DIM){
        bf16 z = __float2bfloat16_rn(0.f);
        g_was_h[(size_t)KVOUT*DIM + i] = z;
        g_was_l[(size_t)KVOUT*DIM + i] = z;
    }
}
__global__ void splitT_wkvb(const float* __restrict__ wb){
    int i = blockIdx.x*blockDim.x + threadIdx.x;
    if (i >= NH*KVR*NOPE) return;
    int d = i % NOPE, c = (i/NOPE) % KVR, h = i/(NOPE*KVR);
    float v = wb[((size_t)h*(NOPE+VDIM) + d)*KVR + c];
    split2(v, g_wbT_h[i], g_wbT_l[i]);
}

// ---------------- prep kernels ----------------
__global__ void rope_prep_kernel(const float* __restrict__ ang){
    int i = blockIdx.x*blockDim.x + threadIdx.x;
    if (i < S_LEN*RHALF){
        float a = ang[i];
        g_cos[i] = cosf(a);
        g_sin[i] = sinf(a);
    }
}

__global__ void prep_keff_kernel(const float* __restrict__ kvw){
    int t = blockIdx.x;
    int s = t % S_LEN;
    int tid = threadIdx.x;
    float v[4];
    #pragma unroll
    for (int j=0;j<4;j++){
        size_t idx = (size_t)t*KVPAD + 4*tid + j;
        v[j] = rejoin(g_kvs_h[idx], g_kvs_l[idx]);
    }
    float ss = v[0]*v[0]+v[1]*v[1]+v[2]*v[2]+v[3]*v[3];
    ss = warpSum(ss);
    __shared__ float red[4];
    if ((tid&31)==0) red[tid>>5] = ss;
    __syncthreads();
    float tot = red[0]+red[1]+red[2]+red[3];
    float r = rsqrtf(tot*(1.0f/KVR) + 1e-6f);
    #pragma unroll
    for (int j=0;j<4;j++){
        int c = 4*tid + j;
        g_ke[(size_t)t*DEFF + c] = __float2half_rn(v[j]*r*kvw[c]);
    }
    if (tid < RHALF){
        size_t pi = (size_t)t*KVPAD + KVR + 2*tid;
        float xr = rejoin(g_kvs_h[pi],   g_kvs_l[pi]);
        float xi = rejoin(g_kvs_h[pi+1], g_kvs_l[pi+1]);
        float c  = g_cos[s*RHALF+tid], sn = g_sin[s*RHALF+tid];
        size_t di = (size_t)t*DEFF + KVR + 2*tid;
        g_ke[di]   = __float2half_rn(xr*c - xi*sn);
        g_ke[di+1] = __float2half_rn(xr*sn + xi*c);
    }
}

// coalesced tiled transpose: ke (fp16, [tok][DEFF]) -> keT (fp16, [b][DEFF][S])
__global__ void transpose_keT(){
    __shared__ half th[32][33];
    int b = blockIdx.z;
    int c0 = blockIdx.y*32, s0 = blockIdx.x*32;
    int tx = threadIdx.x, ty = threadIdx.y;   // 32 x 8
    #pragma unroll
    for (int i=0;i<32;i+=8){
        th[ty+i][tx] = g_ke[(size_t)(b*S_LEN + s0 + ty + i)*DEFF + c0 + tx];
    }
    __syncthreads();
    #pragma unroll
    for (int i=0;i<32;i+=8){
        g_keT[((size_t)b*DEFF + c0 + ty + i)*S_LEN + s0 + tx] = th[tx][ty+i];
    }
}

// one block per token, 512 threads = 16 heads x 32 rope pairs
__global__ void prep_qpe_kernel(){
    int t = blockIdx.x;
    int b = t / S_LEN, s = t % S_LEN;
    int h = threadIdx.x >> 5, i = threadIdx.x & 31;
    size_t si = (size_t)t*QOUT + h*QD + NOPE + 2*i;
    float xr = rejoin(g_qs_h[si],   g_qs_l[si]);
    float xi = rejoin(g_qs_h[si+1], g_qs_l[si+1]);
    float c  = g_cos[s*RHALF+i], sn = g_sin[s*RHALF+i];
    size_t di = ((size_t)(b*NH+h)*S_LEN + s)*DEFF + KVR + 2*i;
    g_qe[di]   = __float2half_rn(xr*c - xi*sn);
    g_qe[di+1] = __float2half_rn(xr*sn + xi*c);
}

// ---------------- split GEMM with ldmatrix ----------------
// MODE 0: bf16x3  (A hi/lo bf16, B hi/lo bf16, 3 passes, 3 stages)
// MODE 1: fp16 2p (A single fp16, B hi/lo fp16, 2 passes, 4 stages)
// MODE 2: fp16 1p (A single fp16, B single fp16, 1 pass, 4 stages)
// OUT: 0 = fp32, 1 = bf16 hi/lo planes, 2 = single fp16 plane.
template<int BN_T, int OUT, int MODE>
__global__ __launch_bounds__(256,2) void mma_gemm(
    const bf16* __restrict__ Ah, const bf16* __restrict__ Al,
    const bf16* __restrict__ Bh, const bf16* __restrict__ Bl,
    float* __restrict__ Cf, bf16* __restrict__ Ch, bf16* __restrict__ Cl,
    int K, int lda, int ldb, int ldc, int zdiv,
    ll zA1, ll zA2, ll zB1, ll zB2, ll zC1, ll zC2,
    float alpha, int causal, int klimit)
{
    if (causal && blockIdx.x > blockIdx.y) return;
    constexpr int NST = (MODE==0) ? 3 : 4;
    constexpr int NPA = (MODE==0) ? 2 : 1;
    constexpr int NPB = (MODE==2) ? 1 : 2;
    constexpr int WN  = BN_T/32;
    constexpr int WM  = 8/WN;
    constexpr int WTM = 128/WM;
    constexpr int MF  = WTM/16;
    constexpr int NF  = 4;
    constexpr int SA  = 128*64;
    constexpr int SB  = BN_T*64;
    constexpr int STG = NPA*SA + NPB*SB;

    extern __shared__ char smc[];
    const uint32_t sbase = smem_u32(smc);

    const int tid = threadIdx.x, lane = tid & 31, wid = tid >> 5;
    const int wm = wid / WN, wn = wid % WN;
    const int grp = lane >> 2, tig = lane & 3;
    const int lrow = lane & 7, sub = lane >> 3;
    const int zl = blockIdx.z % zdiv, zh = blockIdx.z / zdiv;
    const ll n0 = (ll)blockIdx.x * BN_T;

    const int aRowB = wm*WTM + ((sub&1)<<3) + lrow;
    const int aKo   = (sub>>1)<<4;
    const int bRowB = wn*32 + ((sub>>1)<<3) + lrow;
    const int bKo   = (sub&1)<<4;

    const ll aoff = zl*zA1 + zh*zA2 + (ll)blockIdx.y*128*lda;
    const bf16* Ahb = Ah + aoff;
    const bf16* Alb = Al + aoff;
    const ll boff = zl*zB1 + zh*zB2 + n0*ldb;
    const bf16* Bhb = Bh + boff;
    const bf16* Blb = Bl + boff;

    int kEnd = K;
    if (klimit){ int kl = ((int)blockIdx.y + 1)*128; if (kl < kEnd) kEnd = kl; }
    const int nk = kEnd >> 5;

    float acc[MF][NF][4];
    #pragma unroll
    for (int i=0;i<MF;i++)
        #pragma unroll
        for (int j=0;j<NF;j++)
            #pragma unroll
            for (int c=0;c<4;c++) acc[i][j][c] = 0.f;

    const int row = tid >> 2, g = tid & 3;

    auto LOAD = [&](int kb){
        const int s = kb % NST;
        const uint32_t ub = sbase + (uint32_t)(s*STG);
        const ll koff = ((ll)kb << 5) + g*8;
        #pragma unroll
        for (int i=0;i<2;i++){
            int r = row + i*64;
            uint32_t o = swz((uint32_t)(r*64 + g*16));
            cp16(ub + o, Ahb + (ll)r*lda + koff);
            if (MODE==0) cp16(ub + SA + o, Alb + (ll)r*lda + koff);
        }
        const uint32_t bb = ub + NPA*SA;
        #pragma unroll
        for (int i=0;i<BN_T/64;i++){
            int r = row + i*64;
            uint32_t o = swz((uint32_t)(r*64 + g*16));
            cp16(bb + o, Bhb + (ll)r*ldb + koff);
            if (MODE!=2) cp16(bb + SB + o, Blb + (ll)r*ldb + koff);
        }
        cp_commit();
    };

    #pragma unroll
    for (int kb=0; kb<NST-1; kb++) if (kb < nk) LOAD(kb);

    for (int k=0; k<nk; k++){
        cp_wait<NST-2>();
        __syncthreads();
        if (k + NST - 1 < nk) LOAD(k + NST - 1);
        else cp_commit();

        const int s = k % NST;
        const uint32_t AH = sbase + (uint32_t)(s*STG);
        const uint32_t AL = AH + SA;
        const uint32_t BH = AH + NPA*SA;
        const uint32_t BL = BH + SB;

        #pragma unroll
        for (int kk=0; kk<2; kk++){
            const int ck = kk*32;
            uint32_t bh[2*NF], bl[2*NF];
            #pragma unroll
            for (int nfp=0; nfp<NF/2; nfp++){
                uint32_t bo = swz((uint32_t)((bRowB + nfp*16)*64 + ck + bKo));
                ldsm4(&bh[4*nfp], BH + bo);
                if (MODE!=2) ldsm4(&bl[4*nfp], BL + bo);
            }
            #pragma unroll
            for (int mf=0; mf<MF; mf++){
                uint32_t ao = swz((uint32_t)((aRowB + mf*16)*64 + ck + aKo));
                uint32_t ah[4];
                ldsm4(ah, AH + ao);
                if (MODE==2){
                    #pragma unroll
                    for (int nf=0; nf<NF; nf++) mma_f16(acc[mf][nf], ah, &bh[2*nf]);
                } else if (MODE==1){
                    #pragma unroll
                    for (int nf=0; nf<NF; nf++) mma_f16(acc[mf][nf], ah, &bh[2*nf]);
                    #pragma unroll
                    for (int nf=0; nf<NF; nf++) mma_f16(acc[mf][nf], ah, &bl[2*nf]);
                } else {
                    uint32_t al[4];
                    ldsm4(al, AL + ao);
                    #pragma unroll
                    for (int nf=0; nf<NF; nf++) mma_bf16(acc[mf][nf], ah, &bh[2*nf]);
                    #pragma unroll
                    for (int nf=0; nf<NF; nf++) mma_bf16(acc[mf][nf], ah, &bl[2*nf]);
                    #pragma unroll
                    for (int nf=0; nf<NF; nf++) mma_bf16(acc[mf][nf], al, &bh[2*nf]);
                }
            }
        }
    }

    // ---- epilogue ----
    const ll cbase = zl*zC1 + zh*zC2
                   + ((ll)blockIdx.y*128 + wm*WTM)*ldc + n0 + wn*32;
    #pragma unroll
    for (int mf=0; mf<MF; mf++){
        int r0 = mf*16 + grp;
        #pragma unroll
        for (int nf=0; nf<NF; nf++){
            int c = nf*8 + tig*2;
            #pragma unroll
            for (int half_=0; half_<2; half_++){
                ll off = cbase + (ll)(r0 + half_*8)*ldc + c;
                float v0 = acc[mf][nf][2*half_+0]*alpha;
                float v1 = acc[mf][nf][2*half_+1]*alpha;
                if (OUT == 1){
                    bf16 h0,l0,h1,l1;
                    split2(v0,h0,l0); split2(v1,h1,l1);
                    bf162 hp; hp.x=h0; hp.y=h1;
                    bf162 lp; lp.x=l0; lp.y=l1;
                    *(bf162*)(Ch + off) = hp;
                    *(bf162*)(Cl + off) = lp;
                } else if (OUT == 2){
                    __half2 hp;
                    hp.x = __float2half_rn(v0);
                    hp.y = __float2half_rn(v1);
                    *(__half2*)((half*)Ch + off) = hp;
                } else {
                    float2 o; o.x=v0; o.y=v1;
                    *(float2*)(Cf + off) = o;
                }
            }
        }
    }
}

// ---------------- causal softmax -> single fp16 probs ----------------
__global__ void softmax_kernel(){
    const int s = blockIdx.x;
    const ll z = blockIdx.y;
    const float* row = g_scores + (z*S_LEN + (ll)s)*S_LEN;
    half* pr = g_pr + (z*S_LEN + (ll)s)*S_LEN;
    const int n = s + 1;
    const int nend = ((s>>7)+1)<<7;
    const int tid = threadIdx.x;

    float e[16];
    float mx = -1e30f;
    #pragma unroll
    for (int i=0;i<16;i++){
        int t = tid + i*128;
        e[i] = (t < n) ? row[t] : -1e30f;
        mx = fmaxf(mx, e[i]);
    }
    mx = warpMax(mx);
    __shared__ float redm[4], reds[4];
    if ((tid&31)==0) redm[tid>>5] = mx;
    __syncthreads();
    mx = fmaxf(fmaxf(redm[0],redm[1]), fmaxf(redm[2],redm[3]));

    float sum = 0.f;
    #pragma unroll
    for (int i=0;i<16;i++){
        int t = tid + i*128;
        float v = (t < n) ? exp2f(e[i] - mx) : 0.f;
        e[i] = v;
        sum += v;
    }
    sum = warpSum(sum);
    if ((tid&31)==0) reds[tid>>5] = sum;
    __syncthreads();
    sum = reds[0]+reds[1]+reds[2]+reds[3];
    const float inv = 1.0f / sum;

    #pragma unroll
    for (int i=0;i<16;i++){
        int t = tid + i*128;
        if (t < nend) pr[t] = __float2half_rn(e[i]*inv);
    }
}

// ---------------- host side ----------------
// omode: 0 fp32, 1 bf16 hi/lo, 2 fp16 single ; mode: 0 bf16x3, 1 fp16-2p, 2 fp16-1p
static void launch_g(int omode, int mode,
    const bf16* Ah, const bf16* Al, const bf16* Bh, const bf16* Bl,
    float* Cf, bf16* Ch, bf16* Cl,
    int M, int N, int K, int lda, int ldb, int ldc,
    int Z, int zdiv,
    ll zA1, ll zA2, ll zB1, ll zB2, ll zC1, ll zC2,
    float alpha, bool causal, bool klimit)
{
    dim3 grid(N/128, M/128, Z);
    int c = causal?1:0, kl = klimit?1:0;
    #define GO(O,M_) { \
        size_t sm = (size_t)((M_==0)?3:4) * ((((M_==0)?2:1) + ((M_==2)?1:2))*128*64); \
        cudaFuncSetAttribute(mma_gemm<128,O,M_>, cudaFuncAttributeMaxDynamicSharedMemorySize, (int)sm); \
        mma_gemm<128,O,M_><<<grid,256,sm>>>(Ah,Al,Bh,Bl,Cf,Ch,Cl,K,lda,ldb,ldc,zdiv,zA1,zA2,zB1,zB2,zC1,zC2,alpha,c,kl); \
        return; }
    if (mode==0 && omode==1) GO(1,0);
    if (mode==0 && omode==2) GO(2,0);
    if (mode==1 && omode==2) GO(2,1);
    if (mode==2 && omode==0) GO(0,2);
    if (mode==2 && omode==2) GO(2,2);
    #undef GO
}

#define SYM(p, s) cudaGetSymbolAddress((void**)&p, s)

extern "C" void kernel_launch(void* const* d_in, const int* in_sizes, int n_in,
                              void* d_out, int out_size)
{
    (void)in_sizes; (void)n_in; (void)out_size;
    const float* x      = (const float*)d_in[0];
    const float* angles = (const float*)d_in[1];
    const float* wq     = (const float*)d_in[2];
    const float* wkv_a  = (const float*)d_in[3];
    const float* wkv_b  = (const float*)d_in[4];
    const float* wo     = (const float*)d_in[5];
    const float* kvw    = (const float*)d_in[6];
    float* out = (float*)d_out;

    bf16 *xsh,*xsl,*wqh,*wql,*wah,*wal,*wbTh,*wbTl;
    bf16 *qsh,*qsl,*kvh,*kvl;
    half *wbfh,*wbfl,*wofh,*wofl,*ke,*keT,*qe,*pr,*ol,*os;
    float *sc;
    SYM(xsh,g_xs_h); SYM(xsl,g_xs_l); SYM(wqh,g_wqs_h); SYM(wql,g_wqs_l);
    SYM(wah,g_was_h); SYM(wal,g_was_l); SYM(wbfh,g_wbf_h); SYM(wbfl,g_wbf_l);
    SYM(wbTh,g_wbT_h); SYM(wbTl,g_wbT_l); SYM(wofh,g_wof_h); SYM(wofl,g_wof_l);
    SYM(qsh,g_qs_h); SYM(qsl,g_qs_l); SYM(kvh,g_kvs_h); SYM(kvl,g_kvs_l);
    SYM(ke,g_ke); SYM(keT,g_keT);
    SYM(qe,g_qe); SYM(pr,g_pr);
    SYM(ol,g_ol); SYM(os,g_os);
    SYM(sc,g_scores);

    const double msc = 0.1*log(40.0) + 1.0;
    const float softmax_scale = (float)(pow((double)QD, -0.5)*msc*msc);
    const float score_alpha = (float)((double)softmax_scale * LOG2E);

    // 0) splits
    {
        int n;
        n = NTOK*DIM/4;            split_arr<<<(n+255)/256,256>>>((const float4*)x, xsh, xsl, n);
        n = QOUT*DIM/4;            split_arr<<<(n+255)/256,256>>>((const float4*)wq, wqh, wql, n);
        n = KVOUT*DIM/4;           split_arr<<<(n+255)/256,256>>>((const float4*)wkv_a, wah, wal, n);
        zero_tail_was<<<((KVPAD-KVOUT)*DIM+255)/256,256>>>();
        n = NH*(NOPE+VDIM)*KVR/4;  split_arr_f16<<<(n+255)/256,256>>>((const float4*)wkv_b, wbfh, wbfl, n);
        n = DIM*NH*VDIM/4;         split_arr_f16<<<(n+255)/256,256>>>((const float4*)wo, wofh, wofl, n);
        n = NH*KVR*NOPE;           splitT_wkvb<<<(n+255)/256,256>>>(wkv_b);
    }
    rope_prep_kernel<<<(S_LEN*RHALF+127)/128, 128>>>(angles);

    // 1) q = x @ wq^T (bf16x3 -> bf16 hi/lo)
    launch_g(1,0, xsh,xsl, wqh,wql, 0, qsh,qsl,
             NTOK, QOUT, DIM, DIM, DIM, QOUT, 1,1, 0,0,0,0,0,0, 1.f,false,false);

    // 2) kv = x @ wkv_a^T (bf16x3, N padded to 640)
    launch_g(1,0, xsh,xsl, wah,wal, 0, kvh,kvl,
             NTOK, KVPAD, DIM, DIM, DIM, KVPAD, 1,1, 0,0,0,0,0,0, 1.f,false,false);

    // 3) keff (single fp16) + keT transpose
    prep_keff_kernel<<<NTOK, 128>>>(kvw);
    transpose_keT<<<dim3(S_LEN/32, DEFF/32, BATCH), dim3(32,8)>>>();

    // 4) rope(q_pe) -> qe fp16
    prep_qpe_kernel<<<NTOK, 512>>>();

    // 5) qe[...,0:512] = q_nope @ wkv_bT (bf16x3 -> fp16 single)
    launch_g(2,0, qsh,qsl, wbTh,wbTl, 0, (bf16*)qe, 0,
             S_LEN, KVR, NOPE, QOUT, NOPE, DEFF, BATCH*NH, NH,
             (ll)QD, (ll)S_LEN*QOUT, (ll)KVR*NOPE, 0,
             (ll)S_LEN*DEFF, (ll)NH*S_LEN*DEFF, 1.f,false,false);

    // 6) scores = scale * qe(fp16) @ ke(fp16)^T  (1-pass, causal block-skip)
    launch_g(0,2, (const bf16*)qe, 0, (const bf16*)ke, 0, sc, 0,0,
             S_LEN, S_LEN, DEFF, DEFF, DEFF, S_LEN, BATCH*NH, NH,
             (ll)S_LEN*DEFF, (ll)NH*S_LEN*DEFF, 0, (ll)S_LEN*DEFF,
             (ll)S_LEN*S_LEN, (ll)NH*S_LEN*S_LEN, score_alpha, true, false);

    // 7) softmax -> fp16 probs
    softmax_kernel<<<dim3(S_LEN, BATCH*NH), 128>>>();

    // 8) olat = probs(fp16) @ keT(fp16)^T -> fp16, 1-pass, K capped
    launch_g(2,2, (const bf16*)pr, 0, (const bf16*)keT, 0, 0, (bf16*)ol, 0,
             S_LEN, KVR, S_LEN, S_LEN, S_LEN, KVR, BATCH*NH, NH,
             (ll)S_LEN*S_LEN, (ll)NH*S_LEN*S_LEN, 0, (ll)DEFF*S_LEN,
             (ll)S_LEN*KVR, (ll)NH*S_LEN*KVR, 1.f, false, true);

    // 9) o = olat(fp16) @ wkv_b_v(fp16 hi/lo)^T -> fp16 (2-pass, per (b,h), K=512)
    launch_g(2,1, (const bf16*)ol, 0, (const bf16*)(wbfh+(size_t)NOPE*KVR), (const bf16*)(wbfl+(size_t)NOPE*KVR), 0, (bf16*)os, 0,
             S_LEN, VDIM, KVR, KVR, KVR, NH*VDIM, BATCH*NH, NH,
             (ll)S_LEN*KVR, (ll)NH*S_LEN*KVR, (ll)(NOPE+VDIM)*KVR, 0,
             (ll)VDIM, (ll)S_LEN*NH*VDIM, 1.f, false, false);

    // 10) out = o(fp16) @ wo(fp16)^T -> fp32, 1-pass
    launch_g(0,2, (const bf16*)os, 0, (const bf16*)wofh, 0, out, 0,0,
             NTOK, DIM, NH*VDIM, NH*VDIM, NH*VDIM, DIM, 1,1,
             0,0,0,0,0,0, 1.f,false,false);
}

// round 12
// speedup vs baseline: 2.1458x; 1.1311x over previous
#include <cuda_runtime.h>
#include <cuda_bf16.h>
#include <cuda_fp16.h>
#include <math.h>
#include <stdint.h>

// ---------------- problem constants ----------------
#define S_LEN 2048
#define BATCH 2
#define NTOK  (S_LEN*BATCH)     // 4096
#define NH    16
#define DIM   2048
#define NOPE  128
#define ROPE  64
#define RHALF 32
#define VDIM  128
#define KVR   512
#define QD    (NOPE+ROPE)       // 192
#define QOUT  (NH*QD)           // 3072
#define KVOUT (KVR+ROPE)        // 576
#define KVPAD 640               // kv-proj N padded to 5*128
#define DEFF  576
#define LOG2E 1.4426950408889634

typedef long long ll;
typedef __nv_bfloat16 bf16;
typedef __nv_bfloat162 bf162;

// ---------------- scratch ----------------
__device__ __align__(16) bf16 g_xs_h [(size_t)NTOK*DIM],    g_xs_l [(size_t)NTOK*DIM];
__device__ __align__(16) half g_xs_f [(size_t)NTOK*DIM];
__device__ __align__(16) half g_wqf_h[(size_t)QOUT*DIM],    g_wqf_l[(size_t)QOUT*DIM];
__device__ __align__(16) bf16 g_was_h[(size_t)KVPAD*DIM],   g_was_l[(size_t)KVPAD*DIM];
__device__ __align__(16) half g_wbv  [(size_t)NH*VDIM*KVR];
__device__ __align__(16) bf16 g_wbT_h[(size_t)NH*KVR*NOPE], g_wbT_l[(size_t)NH*KVR*NOPE];
__device__ __align__(16) half g_wof  [(size_t)DIM*NH*VDIM];
__device__ __align__(16) bf16 g_qs_h [(size_t)NTOK*QOUT],   g_qs_l [(size_t)NTOK*QOUT];
__device__ __align__(16) bf16 g_kvs_h[(size_t)NTOK*KVPAD],  g_kvs_l[(size_t)NTOK*KVPAD];
__device__ __align__(16) half g_ke  [(size_t)NTOK*DEFF];
__device__ __align__(16) half g_keT [(size_t)BATCH*DEFF*S_LEN];
__device__ __align__(16) half g_qe  [(size_t)BATCH*NH*S_LEN*DEFF];
__device__ float g_scores[(size_t)BATCH*NH*S_LEN*S_LEN];
__device__ __align__(16) half g_pr   [(size_t)BATCH*NH*S_LEN*S_LEN];
__device__ __align__(16) half g_ol   [(size_t)BATCH*NH*S_LEN*KVR];
__device__ __align__(16) half g_os   [(size_t)NTOK*NH*VDIM];
__device__ float g_cos[S_LEN*RHALF];
__device__ float g_sin[S_LEN*RHALF];

// ---------------- helpers ----------------
__device__ __forceinline__ float warpMax(float v){
    #pragma unroll
    for (int o=16;o;o>>=1) v = fmaxf(v, __shfl_xor_sync(0xffffffffu, v, o));
    return v;
}
__device__ __forceinline__ float warpSum(float v){
    #pragma unroll
    for (int o=16;o;o>>=1) v += __shfl_xor_sync(0xffffffffu, v, o);
    return v;
}
__device__ __forceinline__ uint32_t smem_u32(const void* p){
    uint32_t a;
    asm("{ .reg .u64 t; cvta.to.shared.u64 t, %1; cvt.u32.u64 %0, t; }" : "=r"(a) : "l"(p));
    return a;
}
__device__ __forceinline__ void split2(float f, bf16& h, bf16& l){
    h = __float2bfloat16_rn(f);
    l = __float2bfloat16_rn(f - __bfloat162float(h));
}
__device__ __forceinline__ void split2h(float f, half& h, half& l){
    h = __float2half_rn(f);
    l = __float2half_rn(f - __half2float(h));
}
__device__ __forceinline__ float rejoin(bf16 h, bf16 l){
    return __bfloat162float(h) + __bfloat162float(l);
}
__device__ __forceinline__ void mma_bf16(float* d, const uint32_t* a, const uint32_t* b){
    asm volatile(
        "mma.sync.aligned.m16n8k16.row.col.f32.bf16.bf16.f32 "
        "{%0,%1,%2,%3}, {%4,%5,%6,%7}, {%8,%9}, {%0,%1,%2,%3};"
        : "+f"(d[0]), "+f"(d[1]), "+f"(d[2]), "+f"(d[3])
        : "r"(a[0]), "r"(a[1]), "r"(a[2]), "r"(a[3]), "r"(b[0]), "r"(b[1]));
}
__device__ __forceinline__ void mma_f16(float* d, const uint32_t* a, const uint32_t* b){
    asm volatile(
        "mma.sync.aligned.m16n8k16.row.col.f32.f16.f16.f32 "
        "{%0,%1,%2,%3}, {%4,%5,%6,%7}, {%8,%9}, {%0,%1,%2,%3};"
        : "+f"(d[0]), "+f"(d[1]), "+f"(d[2]), "+f"(d[3])
        : "r"(a[0]), "r"(a[1]), "r"(a[2]), "r"(a[3]), "r"(b[0]), "r"(b[1]));
}
__device__ __forceinline__ void ldsm4(uint32_t* r, uint32_t a){
    asm volatile("ldmatrix.sync.aligned.m8n8.x4.shared.b16 {%0,%1,%2,%3}, [%4];"
        : "=r"(r[0]), "=r"(r[1]), "=r"(r[2]), "=r"(r[3]) : "r"(a));
}
__device__ __forceinline__ void cp16(uint32_t dst, const void* src){
    asm volatile("cp.async.cg.shared.global [%0], [%1], 16;\n" :: "r"(dst), "l"(src) : "memory");
}
__device__ __forceinline__ void cp_commit(){ asm volatile("cp.async.commit_group;\n" ::: "memory"); }
template<int N>
__device__ __forceinline__ void cp_wait(){ asm volatile("cp.async.wait_group %0;\n" :: "n"(N) : "memory"); }

__device__ __forceinline__ uint32_t swz(uint32_t o){ return o ^ ((o>>3)&0x30u); }

// ---------------- split / convert kernels ----------------
__global__ void split_arr(const float4* __restrict__ src, bf16* __restrict__ h, bf16* __restrict__ l, int n4){
    int i = blockIdx.x*blockDim.x + threadIdx.x;
    if (i >= n4) return;
    float4 v = src[i];
    bf16 h0,l0,h1,l1,h2,l2,h3,l3;
    split2(v.x,h0,l0); split2(v.y,h1,l1); split2(v.z,h2,l2); split2(v.w,h3,l3);
    bf162* hp = (bf162*)(h + 4*(size_t)i);
    bf162* lp = (bf162*)(l + 4*(size_t)i);
    bf162 a; a.x=h0; a.y=h1; hp[0]=a;
    bf162 b; b.x=h2; b.y=h3; hp[1]=b;
    bf162 c; c.x=l0; c.y=l1; lp[0]=c;
    bf162 d; d.x=l2; d.y=l3; lp[1]=d;
}
__global__ void split_arr_f16(const float4* __restrict__ src, half* __restrict__ h, half* __restrict__ l, int n4){
    int i = blockIdx.x*blockDim.x + threadIdx.x;
    if (i >= n4) return;
    float4 v = src[i];
    half h0,l0,h1,l1,h2,l2,h3,l3;
    split2h(v.x,h0,l0); split2h(v.y,h1,l1); split2h(v.z,h2,l2); split2h(v.w,h3,l3);
    __half2* hp = (__half2*)(h + 4*(size_t)i);
    __half2* lp = (__half2*)(l + 4*(size_t)i);
    __half2 a; a.x=h0; a.y=h1; hp[0]=a;
    __half2 b; b.x=h2; b.y=h3; hp[1]=b;
    __half2 c; c.x=l0; c.y=l1; lp[0]=c;
    __half2 d; d.x=l2; d.y=l3; lp[1]=d;
}
__global__ void cvt_f16(const float4* __restrict__ src, half* __restrict__ dst, int n4){
    int i = blockIdx.x*blockDim.x + threadIdx.x;
    if (i >= n4) return;
    float4 v = src[i];
    __half2* dp = (__half2*)(dst + 4*(size_t)i);
    __half2 a; a.x=__float2half_rn(v.x); a.y=__float2half_rn(v.y); dp[0]=a;
    __half2 b; b.x=__float2half_rn(v.z); b.y=__float2half_rn(v.w); dp[1]=b;
}
// wbv[h][v][c] = fp16(wkv_b[h*256 + 128 + v][c])
__global__ void cvtV_f16(const float* __restrict__ wb){
    int i = blockIdx.x*blockDim.x + threadIdx.x;
    if (i >= NH*VDIM*KVR) return;
    int c = i % KVR, v = (i/KVR) % VDIM, h = i/(KVR*VDIM);
    g_wbv[i] = __float2half_rn(wb[((size_t)h*(NOPE+VDIM) + NOPE + v)*KVR + c]);
}
__global__ void zero_tail_was(){
    int i = blockIdx.x*blockDim.x + threadIdx.x;
    if (i < (KVPAD-KVOUT)*DIM){
        bf16 z = __float2bfloat16_rn(0.f);
        g_was_h[(size_t)KVOUT*DIM + i] = z;
        g_was_l[(size_t)KVOUT*DIM + i] = z;
    }
}
__global__ void splitT_wkvb(const float* __restrict__ wb){
    int i = blockIdx.x*blockDim.x + threadIdx.x;
    if (i >= NH*KVR*NOPE) return;
    int d = i % NOPE, c = (i/NOPE) % KVR, h = i/(NOPE*KVR);
    float v = wb[((size_t)h*(NOPE+VDIM) + d)*KVR + c];
    split2(v, g_wbT_h[i], g_wbT_l[i]);
}

// ---------------- prep kernels ----------------
__global__ void rope_prep_kernel(const float* __restrict__ ang){
    int i = blockIdx.x*blockDim.x + threadIdx.x;
    if (i < S_LEN*RHALF){
        float a = ang[i];
        g_cos[i] = cosf(a);
        g_sin[i] = sinf(a);
    }
}

__global__ void prep_keff_kernel(const float* __restrict__ kvw){
    int t = blockIdx.x;
    int s = t % S_LEN;
    int tid = threadIdx.x;
    float v[4];
    #pragma unroll
    for (int j=0;j<4;j++){
        size_t idx = (size_t)t*KVPAD + 4*tid + j;
        v[j] = rejoin(g_kvs_h[idx], g_kvs_l[idx]);
    }
    float ss = v[0]*v[0]+v[1]*v[1]+v[2]*v[2]+v[3]*v[3];
    ss = warpSum(ss);
    __shared__ float red[4];
    if ((tid&31)==0) red[tid>>5] = ss;
    __syncthreads();
    float tot = red[0]+red[1]+red[2]+red[3];
    float r = rsqrtf(tot*(1.0f/KVR) + 1e-6f);
    #pragma unroll
    for (int j=0;j<4;j++){
        int c = 4*tid + j;
        g_ke[(size_t)t*DEFF + c] = __float2half_rn(v[j]*r*kvw[c]);
    }
    if (tid < RHALF){
        size_t pi = (size_t)t*KVPAD + KVR + 2*tid;
        float xr = rejoin(g_kvs_h[pi],   g_kvs_l[pi]);
        float xi = rejoin(g_kvs_h[pi+1], g_kvs_l[pi+1]);
        float c  = g_cos[s*RHALF+tid], sn = g_sin[s*RHALF+tid];
        size_t di = (size_t)t*DEFF + KVR + 2*tid;
        g_ke[di]   = __float2half_rn(xr*c - xi*sn);
        g_ke[di+1] = __float2half_rn(xr*sn + xi*c);
    }
}

// coalesced tiled transpose: ke (fp16, [tok][DEFF]) -> keT (fp16, [b][DEFF][S])
__global__ void transpose_keT(){
    __shared__ half th[32][33];
    int b = blockIdx.z;
    int c0 = blockIdx.y*32, s0 = blockIdx.x*32;
    int tx = threadIdx.x, ty = threadIdx.y;   // 32 x 8
    #pragma unroll
    for (int i=0;i<32;i+=8){
        th[ty+i][tx] = g_ke[(size_t)(b*S_LEN + s0 + ty + i)*DEFF + c0 + tx];
    }
    __syncthreads();
    #pragma unroll
    for (int i=0;i<32;i+=8){
        g_keT[((size_t)b*DEFF + c0 + ty + i)*S_LEN + s0 + tx] = th[tx][ty+i];
    }
}

// one block per token, 512 threads = 16 heads x 32 rope pairs
__global__ void prep_qpe_kernel(){
    int t = blockIdx.x;
    int b = t / S_LEN, s = t % S_LEN;
    int h = threadIdx.x >> 5, i = threadIdx.x & 31;
    size_t si = (size_t)t*QOUT + h*QD + NOPE + 2*i;
    float xr = rejoin(g_qs_h[si],   g_qs_l[si]);
    float xi = rejoin(g_qs_h[si+1], g_qs_l[si+1]);
    float c  = g_cos[s*RHALF+i], sn = g_sin[s*RHALF+i];
    size_t di = ((size_t)(b*NH+h)*S_LEN + s)*DEFF + KVR + 2*i;
    g_qe[di]   = __float2half_rn(xr*c - xi*sn);
    g_qe[di+1] = __float2half_rn(xr*sn + xi*c);
}

// ---------------- split GEMM with ldmatrix ----------------
// MODE 0: bf16x3  (A hi/lo bf16, B hi/lo bf16, 3 passes, 3 stages)
// MODE 1: fp16 2p (A single fp16, B hi/lo fp16, 2 passes, 4 stages)
// MODE 2: fp16 1p (A single fp16, B single fp16, 1 pass, 4 stages)
// OUT: 0 = fp32, 1 = bf16 hi/lo planes, 2 = single fp16 plane.
template<int BN_T, int OUT, int MODE>
__global__ __launch_bounds__(256,2) void mma_gemm(
    const bf16* __restrict__ Ah, const bf16* __restrict__ Al,
    const bf16* __restrict__ Bh, const bf16* __restrict__ Bl,
    float* __restrict__ Cf, bf16* __restrict__ Ch, bf16* __restrict__ Cl,
    int K, int lda, int ldb, int ldc, int zdiv,
    ll zA1, ll zA2, ll zB1, ll zB2, ll zC1, ll zC2,
    float alpha, int causal, int klimit)
{
    if (causal && blockIdx.x > blockIdx.y) return;
    constexpr int NST = (MODE==0) ? 3 : 4;
    constexpr int NPA = (MODE==0) ? 2 : 1;
    constexpr int NPB = (MODE==2) ? 1 : 2;
    constexpr int WN  = BN_T/32;
    constexpr int WM  = 8/WN;
    constexpr int WTM = 128/WM;
    constexpr int MF  = WTM/16;
    constexpr int NF  = 4;
    constexpr int SA  = 128*64;
    constexpr int SB  = BN_T*64;
    constexpr int STG = NPA*SA + NPB*SB;

    extern __shared__ char smc[];
    const uint32_t sbase = smem_u32(smc);

    const int tid = threadIdx.x, lane = tid & 31, wid = tid >> 5;
    const int wm = wid / WN, wn = wid % WN;
    const int grp = lane >> 2, tig = lane & 3;
    const int lrow = lane & 7, sub = lane >> 3;
    const int zl = blockIdx.z % zdiv, zh = blockIdx.z / zdiv;
    const ll n0 = (ll)blockIdx.x * BN_T;

    const int aRowB = wm*WTM + ((sub&1)<<3) + lrow;
    const int aKo   = (sub>>1)<<4;
    const int bRowB = wn*32 + ((sub>>1)<<3) + lrow;
    const int bKo   = (sub&1)<<4;

    const ll aoff = zl*zA1 + zh*zA2 + (ll)blockIdx.y*128*lda;
    const bf16* Ahb = Ah + aoff;
    const bf16* Alb = Al + aoff;
    const ll boff = zl*zB1 + zh*zB2 + n0*ldb;
    const bf16* Bhb = Bh + boff;
    const bf16* Blb = Bl + boff;

    int kEnd = K;
    if (klimit){ int kl = ((int)blockIdx.y + 1)*128; if (kl < kEnd) kEnd = kl; }
    const int nk = kEnd >> 5;

    float acc[MF][NF][4];
    #pragma unroll
    for (int i=0;i<MF;i++)
        #pragma unroll
        for (int j=0;j<NF;j++)
            #pragma unroll
            for (int c=0;c<4;c++) acc[i][j][c] = 0.f;

    const int row = tid >> 2, g = tid & 3;

    auto LOAD = [&](int kb){
        const int s = kb % NST;
        const uint32_t ub = sbase + (uint32_t)(s*STG);
        const ll koff = ((ll)kb << 5) + g*8;
        #pragma unroll
        for (int i=0;i<2;i++){
            int r = row + i*64;
            uint32_t o = swz((uint32_t)(r*64 + g*16));
            cp16(ub + o, Ahb + (ll)r*lda + koff);
            if (MODE==0) cp16(ub + SA + o, Alb + (ll)r*lda + koff);
        }
        const uint32_t bb = ub + NPA*SA;
        #pragma unroll
        for (int i=0;i<BN_T/64;i++){
            int r = row + i*64;
            uint32_t o = swz((uint32_t)(r*64 + g*16));
            cp16(bb + o, Bhb + (ll)r*ldb + koff);
            if (MODE!=2) cp16(bb + SB + o, Blb + (ll)r*ldb + koff);
        }
        cp_commit();
    };

    #pragma unroll
    for (int kb=0; kb<NST-1; kb++) if (kb < nk) LOAD(kb);

    for (int k=0; k<nk; k++){
        cp_wait<NST-2>();
        __syncthreads();
        if (k + NST - 1 < nk) LOAD(k + NST - 1);
        else cp_commit();

        const int s = k % NST;
        const uint32_t AH = sbase + (uint32_t)(s*STG);
        const uint32_t AL = AH + SA;
        const uint32_t BH = AH + NPA*SA;
        const uint32_t BL = BH + SB;

        #pragma unroll
        for (int kk=0; kk<2; kk++){
            const int ck = kk*32;
            uint32_t bh[2*NF], bl[2*NF];
            #pragma unroll
            for (int nfp=0; nfp<NF/2; nfp++){
                uint32_t bo = swz((uint32_t)((bRowB + nfp*16)*64 + ck + bKo));
                ldsm4(&bh[4*nfp], BH + bo);
                if (MODE!=2) ldsm4(&bl[4*nfp], BL + bo);
            }
            #pragma unroll
            for (int mf=0; mf<MF; mf++){
                uint32_t ao = swz((uint32_t)((aRowB + mf*16)*64 + ck + aKo));
                uint32_t ah[4];
                ldsm4(ah, AH + ao);
                if (MODE==2){
                    #pragma unroll
                    for (int nf=0; nf<NF; nf++) mma_f16(acc[mf][nf], ah, &bh[2*nf]);
                } else if (MODE==1){
                    #pragma unroll
                    for (int nf=0; nf<NF; nf++) mma_f16(acc[mf][nf], ah, &bh[2*nf]);
                    #pragma unroll
                    for (int nf=0; nf<NF; nf++) mma_f16(acc[mf][nf], ah, &bl[2*nf]);
                } else {
                    uint32_t al[4];
                    ldsm4(al, AL + ao);
                    #pragma unroll
                    for (int nf=0; nf<NF; nf++) mma_bf16(acc[mf][nf], ah, &bh[2*nf]);
                    #pragma unroll
                    for (int nf=0; nf<NF; nf++) mma_bf16(acc[mf][nf], ah, &bl[2*nf]);
                    #pragma unroll
                    for (int nf=0; nf<NF; nf++) mma_bf16(acc[mf][nf], al, &bh[2*nf]);
                }
            }
        }
    }

    // ---- epilogue ----
    const ll cbase = zl*zC1 + zh*zC2
                   + ((ll)blockIdx.y*128 + wm*WTM)*ldc + n0 + wn*32;
    #pragma unroll
    for (int mf=0; mf<MF; mf++){
        int r0 = mf*16 + grp;
        #pragma unroll
        for (int nf=0; nf<NF; nf++){
            int c = nf*8 + tig*2;
            #pragma unroll
            for (int half_=0; half_<2; half_++){
                ll off = cbase + (ll)(r0 + half_*8)*ldc + c;
                float v0 = acc[mf][nf][2*half_+0]*alpha;
                float v1 = acc[mf][nf][2*half_+1]*alpha;
                if (OUT == 1){
                    bf16 h0,l0,h1,l1;
                    split2(v0,h0,l0); split2(v1,h1,l1);
                    bf162 hp; hp.x=h0; hp.y=h1;
                    bf162 lp; lp.x=l0; lp.y=l1;
                    *(bf162*)(Ch + off) = hp;
                    *(bf162*)(Cl + off) = lp;
                } else if (OUT == 2){
                    __half2 hp;
                    hp.x = __float2half_rn(v0);
                    hp.y = __float2half_rn(v1);
                    *(__half2*)((half*)Ch + off) = hp;
                } else {
                    float2 o; o.x=v0; o.y=v1;
                    *(float2*)(Cf + off) = o;
                }
            }
        }
    }
}

// ---------------- causal softmax -> single fp16 probs ----------------
__global__ void softmax_kernel(){
    const int s = blockIdx.x;
    const ll z = blockIdx.y;
    const float* row = g_scores + (z*S_LEN + (ll)s)*S_LEN;
    half* pr = g_pr + (z*S_LEN + (ll)s)*S_LEN;
    const int n = s + 1;
    const int nend = ((s>>7)+1)<<7;
    const int tid = threadIdx.x;

    float e[16];
    float mx = -1e30f;
    #pragma unroll
    for (int i=0;i<16;i++){
        int t = tid + i*128;
        e[i] = (t < n) ? row[t] : -1e30f;
        mx = fmaxf(mx, e[i]);
    }
    mx = warpMax(mx);
    __shared__ float redm[4], reds[4];
    if ((tid&31)==0) redm[tid>>5] = mx;
    __syncthreads();
    mx = fmaxf(fmaxf(redm[0],redm[1]), fmaxf(redm[2],redm[3]));

    float sum = 0.f;
    #pragma unroll
    for (int i=0;i<16;i++){
        int t = tid + i*128;
        float v = (t < n) ? exp2f(e[i] - mx) : 0.f;
        e[i] = v;
        sum += v;
    }
    sum = warpSum(sum);
    if ((tid&31)==0) reds[tid>>5] = sum;
    __syncthreads();
    sum = reds[0]+reds[1]+reds[2]+reds[3];
    const float inv = 1.0f / sum;

    #pragma unroll
    for (int i=0;i<16;i++){
        int t = tid + i*128;
        if (t < nend) pr[t] = __float2half_rn(e[i]*inv);
    }
}

// ---------------- host side ----------------
// omode: 0 fp32, 1 bf16 hi/lo, 2 fp16 single ; mode: 0 bf16x3, 1 fp16-2p, 2 fp16-1p
static void launch_g(int omode, int mode,
    const bf16* Ah, const bf16* Al, const bf16* Bh, const bf16* Bl,
    float* Cf, bf16* Ch, bf16* Cl,
    int M, int N, int K, int lda, int ldb, int ldc,
    int Z, int zdiv,
    ll zA1, ll zA2, ll zB1, ll zB2, ll zC1, ll zC2,
    float alpha, bool causal, bool klimit)
{
    dim3 grid(N/128, M/128, Z);
    int c = causal?1:0, kl = klimit?1:0;
    #define GO(O,M_) { \
        size_t sm = (size_t)((M_==0)?3:4) * ((((M_==0)?2:1) + ((M_==2)?1:2))*128*64); \
        cudaFuncSetAttribute(mma_gemm<128,O,M_>, cudaFuncAttributeMaxDynamicSharedMemorySize, (int)sm); \
        mma_gemm<128,O,M_><<<grid,256,sm>>>(Ah,Al,Bh,Bl,Cf,Ch,Cl,K,lda,ldb,ldc,zdiv,zA1,zA2,zB1,zB2,zC1,zC2,alpha,c,kl); \
        return; }
    if (mode==0 && omode==1) GO(1,0);
    if (mode==0 && omode==2) GO(2,0);
    if (mode==1 && omode==1) GO(1,1);
    if (mode==1 && omode==2) GO(2,1);
    if (mode==2 && omode==0) GO(0,2);
    if (mode==2 && omode==2) GO(2,2);
    #undef GO
}

#define SYM(p, s) cudaGetSymbolAddress((void**)&p, s)

extern "C" void kernel_launch(void* const* d_in, const int* in_sizes, int n_in,
                              void* d_out, int out_size)
{
    (void)in_sizes; (void)n_in; (void)out_size;
    const float* x      = (const float*)d_in[0];
    const float* angles = (const float*)d_in[1];
    const float* wq     = (const float*)d_in[2];
    const float* wkv_a  = (const float*)d_in[3];
    const float* wkv_b  = (const float*)d_in[4];
    const float* wo     = (const float*)d_in[5];
    const float* kvw    = (const float*)d_in[6];
    float* out = (float*)d_out;

    bf16 *xsh,*xsl,*wah,*wal,*wbTh,*wbTl;
    bf16 *qsh,*qsl,*kvh,*kvl;
    half *xsf,*wqfh,*wqfl,*wbv,*wof,*ke,*keT,*qe,*pr,*ol,*os;
    float *sc;
    SYM(xsh,g_xs_h); SYM(xsl,g_xs_l); SYM(xsf,g_xs_f);
    SYM(wqfh,g_wqf_h); SYM(wqfl,g_wqf_l);
    SYM(wah,g_was_h); SYM(wal,g_was_l); SYM(wbv,g_wbv);
    SYM(wbTh,g_wbT_h); SYM(wbTl,g_wbT_l); SYM(wof,g_wof);
    SYM(qsh,g_qs_h); SYM(qsl,g_qs_l); SYM(kvh,g_kvs_h); SYM(kvl,g_kvs_l);
    SYM(ke,g_ke); SYM(keT,g_keT);
    SYM(qe,g_qe); SYM(pr,g_pr);
    SYM(ol,g_ol); SYM(os,g_os);
    SYM(sc,g_scores);

    const double msc = 0.1*log(40.0) + 1.0;
    const float softmax_scale = (float)(pow((double)QD, -0.5)*msc*msc);
    const float score_alpha = (float)((double)softmax_scale * LOG2E);

    // 0) splits / converts
    {
        int n;
        n = NTOK*DIM/4;            split_arr<<<(n+255)/256,256>>>((const float4*)x, xsh, xsl, n);
        n = NTOK*DIM/4;            cvt_f16<<<(n+255)/256,256>>>((const float4*)x, xsf, n);
        n = QOUT*DIM/4;            split_arr_f16<<<(n+255)/256,256>>>((const float4*)wq, wqfh, wqfl, n);
        n = KVOUT*DIM/4;           split_arr<<<(n+255)/256,256>>>((const float4*)wkv_a, wah, wal, n);
        zero_tail_was<<<((KVPAD-KVOUT)*DIM+255)/256,256>>>();
        n = NH*VDIM*KVR;           cvtV_f16<<<(n+255)/256,256>>>(wkv_b);
        n = DIM*NH*VDIM/4;         cvt_f16<<<(n+255)/256,256>>>((const float4*)wo, wof, n);
        n = NH*KVR*NOPE;           splitT_wkvb<<<(n+255)/256,256>>>(wkv_b);
    }
    rope_prep_kernel<<<(S_LEN*RHALF+127)/128, 128>>>(angles);

    // 1) q = x(fp16) @ wq(fp16 hi/lo)^T  (2-pass -> bf16 hi/lo)
    launch_g(1,1, (const bf16*)xsf, 0, (const bf16*)wqfh, (const bf16*)wqfl, 0, qsh,qsl,
             NTOK, QOUT, DIM, DIM, DIM, QOUT, 1,1, 0,0,0,0,0,0, 1.f,false,false);

    // 2) kv = x @ wkv_a^T (bf16x3, N padded to 640)
    launch_g(1,0, xsh,xsl, wah,wal, 0, kvh,kvl,
             NTOK, KVPAD, DIM, DIM, DIM, KVPAD, 1,1, 0,0,0,0,0,0, 1.f,false,false);

    // 3) keff (single fp16) + keT transpose
    prep_keff_kernel<<<NTOK, 128>>>(kvw);
    transpose_keT<<<dim3(S_LEN/32, DEFF/32, BATCH), dim3(32,8)>>>();

    // 4) rope(q_pe) -> qe fp16
    prep_qpe_kernel<<<NTOK, 512>>>();

    // 5) qe[...,0:512] = q_nope @ wkv_bT (bf16x3 -> fp16 single)
    launch_g(2,0, qsh,qsl, wbTh,wbTl, 0, (bf16*)qe, 0,
             S_LEN, KVR, NOPE, QOUT, NOPE, DEFF, BATCH*NH, NH,
             (ll)QD, (ll)S_LEN*QOUT, (ll)KVR*NOPE, 0,
             (ll)S_LEN*DEFF, (ll)NH*S_LEN*DEFF, 1.f,false,false);

    // 6) scores = scale * qe(fp16) @ ke(fp16)^T  (1-pass, causal block-skip)
    launch_g(0,2, (const bf16*)qe, 0, (const bf16*)ke, 0, sc, 0,0,
             S_LEN, S_LEN, DEFF, DEFF, DEFF, S_LEN, BATCH*NH, NH,
             (ll)S_LEN*DEFF, (ll)NH*S_LEN*DEFF, 0, (ll)S_LEN*DEFF,
             (ll)S_LEN*S_LEN, (ll)NH*S_LEN*S_LEN, score_alpha, true, false);

    // 7) softmax -> fp16 probs
    softmax_kernel<<<dim3(S_LEN, BATCH*NH), 128>>>();

    // 8) olat = probs(fp16) @ keT(fp16)^T -> fp16, 1-pass, K capped
    launch_g(2,2, (const bf16*)pr, 0, (const bf16*)keT, 0, 0, (bf16*)ol, 0,
             S_LEN, KVR, S_LEN, S_LEN, S_LEN, KVR, BATCH*NH, NH,
             (ll)S_LEN*S_LEN, (ll)NH*S_LEN*S_LEN, 0, (ll)DEFF*S_LEN,
             (ll)S_LEN*KVR, (ll)NH*S_LEN*KVR, 1.f, false, true);

    // 9) o = olat(fp16) @ wbv(fp16)^T -> fp16, 1-pass (per (b,h), K=512)
    launch_g(2,2, (const bf16*)ol, 0, (const bf16*)wbv, 0, 0, (bf16*)os, 0,
             S_LEN, VDIM, KVR, KVR, KVR, NH*VDIM, BATCH*NH, NH,
             (ll)S_LEN*KVR, (ll)NH*S_LEN*KVR, (ll)VDIM*KVR, 0,
             (ll)VDIM, (ll)S_LEN*NH*VDIM, 1.f, false, false);

    // 10) out = o(fp16) @ wo(fp16)^T -> fp32, 1-pass
    launch_g(0,2, (const bf16*)os, 0, (const bf16*)wof, 0, out, 0,0,
             NTOK, DIM, NH*VDIM, NH*VDIM, NH*VDIM, DIM, 1,1,
             0,0,0,0,0,0, 1.f,false,false);
}

// round 13
// speedup vs baseline: 2.3164x; 1.0795x over previous
#include <cuda_runtime.h>
#include <cuda_bf16.h>
#include <cuda_fp16.h>
#include <math.h>
#include <stdint.h>

// ---------------- problem constants ----------------
#define S_LEN 2048
#define BATCH 2
#define NTOK  (S_LEN*BATCH)     // 4096
#define NH    16
#define DIM   2048
#define NOPE  128
#define ROPE  64
#define RHALF 32
#define VDIM  128
#define KVR   512
#define QD    (NOPE+ROPE)       // 192
#define QOUT  (NH*QD)           // 3072
#define KVOUT (KVR+ROPE)        // 576
#define KVPAD 640               // kv-proj N padded to 5*128
#define DEFF  576
#define LOG2E 1.4426950408889634

typedef long long ll;
typedef __nv_bfloat16 bf16;
typedef __nv_bfloat162 bf162;

// ---------------- scratch ----------------
__device__ __align__(16) half g_xs_f [(size_t)NTOK*DIM];
__device__ __align__(16) half g_wqf_h[(size_t)QOUT*DIM],  g_wqf_l[(size_t)QOUT*DIM];
__device__ __align__(16) half g_waf_h[(size_t)KVPAD*DIM], g_waf_l[(size_t)KVPAD*DIM];
__device__ __align__(16) half g_wbv  [(size_t)NH*VDIM*KVR];
__device__ __align__(16) half g_wbTf_h[(size_t)NH*KVR*NOPE], g_wbTf_l[(size_t)NH*KVR*NOPE];
__device__ __align__(16) half g_wof  [(size_t)DIM*NH*VDIM];
__device__ __align__(16) half g_qs_f [(size_t)NTOK*QOUT];
__device__ __align__(16) bf16 g_kvs_h[(size_t)NTOK*KVPAD],  g_kvs_l[(size_t)NTOK*KVPAD];
__device__ __align__(16) half g_ke  [(size_t)NTOK*DEFF];
__device__ __align__(16) half g_keT [(size_t)BATCH*DEFF*S_LEN];
__device__ __align__(16) half g_qe  [(size_t)BATCH*NH*S_LEN*DEFF];
__device__ float g_scores[(size_t)BATCH*NH*S_LEN*S_LEN];
__device__ __align__(16) half g_pr   [(size_t)BATCH*NH*S_LEN*S_LEN];
__device__ __align__(16) half g_ol   [(size_t)BATCH*NH*S_LEN*KVR];
__device__ __align__(16) half g_os   [(size_t)NTOK*NH*VDIM];
__device__ float g_cos[S_LEN*RHALF];
__device__ float g_sin[S_LEN*RHALF];

// ---------------- helpers ----------------
__device__ __forceinline__ float warpMax(float v){
    #pragma unroll
    for (int o=16;o;o>>=1) v = fmaxf(v, __shfl_xor_sync(0xffffffffu, v, o));
    return v;
}
__device__ __forceinline__ float warpSum(float v){
    #pragma unroll
    for (int o=16;o;o>>=1) v += __shfl_xor_sync(0xffffffffu, v, o);
    return v;
}
__device__ __forceinline__ uint32_t smem_u32(const void* p){
    uint32_t a;
    asm("{ .reg .u64 t; cvta.to.shared.u64 t, %1; cvt.u32.u64 %0, t; }" : "=r"(a) : "l"(p));
    return a;
}
__device__ __forceinline__ void split2(float f, bf16& h, bf16& l){
    h = __float2bfloat16_rn(f);
    l = __float2bfloat16_rn(f - __bfloat162float(h));
}
__device__ __forceinline__ void split2h(float f, half& h, half& l){
    h = __float2half_rn(f);
    l = __float2half_rn(f - __half2float(h));
}
__device__ __forceinline__ float rejoin(bf16 h, bf16 l){
    return __bfloat162float(h) + __bfloat162float(l);
}
__device__ __forceinline__ void mma_bf16(float* d, const uint32_t* a, const uint32_t* b){
    asm volatile(
        "mma.sync.aligned.m16n8k16.row.col.f32.bf16.bf16.f32 "
        "{%0,%1,%2,%3}, {%4,%5,%6,%7}, {%8,%9}, {%0,%1,%2,%3};"
        : "+f"(d[0]), "+f"(d[1]), "+f"(d[2]), "+f"(d[3])
        : "r"(a[0]), "r"(a[1]), "r"(a[2]), "r"(a[3]), "r"(b[0]), "r"(b[1]));
}
__device__ __forceinline__ void mma_f16(float* d, const uint32_t* a, const uint32_t* b){
    asm volatile(
        "mma.sync.aligned.m16n8k16.row.col.f32.f16.f16.f32 "
        "{%0,%1,%2,%3}, {%4,%5,%6,%7}, {%8,%9}, {%0,%1,%2,%3};"
        : "+f"(d[0]), "+f"(d[1]), "+f"(d[2]), "+f"(d[3])
        : "r"(a[0]), "r"(a[1]), "r"(a[2]), "r"(a[3]), "r"(b[0]), "r"(b[1]));
}
__device__ __forceinline__ void ldsm4(uint32_t* r, uint32_t a){
    asm volatile("ldmatrix.sync.aligned.m8n8.x4.shared.b16 {%0,%1,%2,%3}, [%4];"
        : "=r"(r[0]), "=r"(r[1]), "=r"(r[2]), "=r"(r[3]) : "r"(a));
}
__device__ __forceinline__ void cp16(uint32_t dst, const void* src){
    asm volatile("cp.async.cg.shared.global [%0], [%1], 16;\n" :: "r"(dst), "l"(src) : "memory");
}
__device__ __forceinline__ void cp_commit(){ asm volatile("cp.async.commit_group;\n" ::: "memory"); }
template<int N>
__device__ __forceinline__ void cp_wait(){ asm volatile("cp.async.wait_group %0;\n" :: "n"(N) : "memory"); }

__device__ __forceinline__ uint32_t swz(uint32_t o){ return o ^ ((o>>3)&0x30u); }

// ---------------- split / convert kernels ----------------
__global__ void split_arr_f16(const float4* __restrict__ src, half* __restrict__ h, half* __restrict__ l, int n4){
    int i = blockIdx.x*blockDim.x + threadIdx.x;
    if (i >= n4) return;
    float4 v = src[i];
    half h0,l0,h1,l1,h2,l2,h3,l3;
    split2h(v.x,h0,l0); split2h(v.y,h1,l1); split2h(v.z,h2,l2); split2h(v.w,h3,l3);
    __half2* hp = (__half2*)(h + 4*(size_t)i);
    __half2* lp = (__half2*)(l + 4*(size_t)i);
    __half2 a; a.x=h0; a.y=h1; hp[0]=a;
    __half2 b; b.x=h2; b.y=h3; hp[1]=b;
    __half2 c; c.x=l0; c.y=l1; lp[0]=c;
    __half2 d; d.x=l2; d.y=l3; lp[1]=d;
}
__global__ void cvt_f16(const float4* __restrict__ src, half* __restrict__ dst, int n4){
    int i = blockIdx.x*blockDim.x + threadIdx.x;
    if (i >= n4) return;
    float4 v = src[i];
    __half2* dp = (__half2*)(dst + 4*(size_t)i);
    __half2 a; a.x=__float2half_rn(v.x); a.y=__float2half_rn(v.y); dp[0]=a;
    __half2 b; b.x=__float2half_rn(v.z); b.y=__float2half_rn(v.w); dp[1]=b;
}
// wbv[h][v][c] = fp16(wkv_b[h*256 + 128 + v][c])
__global__ void cvtV_f16(const float* __restrict__ wb){
    int i = blockIdx.x*blockDim.x + threadIdx.x;
    if (i >= NH*VDIM*KVR) return;
    int c = i % KVR, v = (i/KVR) % VDIM, h = i/(KVR*VDIM);
    g_wbv[i] = __float2half_rn(wb[((size_t)h*(NOPE+VDIM) + NOPE + v)*KVR + c]);
}
__global__ void zero_tail_waf(){
    int i = blockIdx.x*blockDim.x + threadIdx.x;
    if (i < (KVPAD-KVOUT)*DIM){
        half z = __float2half_rn(0.f);
        g_waf_h[(size_t)KVOUT*DIM + i] = z;
        g_waf_l[(size_t)KVOUT*DIM + i] = z;
    }
}
__global__ void splitT_wkvb(const float* __restrict__ wb){
    int i = blockIdx.x*blockDim.x + threadIdx.x;
    if (i >= NH*KVR*NOPE) return;
    int d = i % NOPE, c = (i/NOPE) % KVR, h = i/(NOPE*KVR);
    float v = wb[((size_t)h*(NOPE+VDIM) + d)*KVR + c];
    split2h(v, g_wbTf_h[i], g_wbTf_l[i]);
}

// ---------------- prep kernels ----------------
__global__ void rope_prep_kernel(const float* __restrict__ ang){
    int i = blockIdx.x*blockDim.x + threadIdx.x;
    if (i < S_LEN*RHALF){
        float a = ang[i];
        g_cos[i] = cosf(a);
        g_sin[i] = sinf(a);
    }
}

__global__ void prep_keff_kernel(const float* __restrict__ kvw){
    int t = blockIdx.x;
    int s = t % S_LEN;
    int tid = threadIdx.x;
    float v[4];
    #pragma unroll
    for (int j=0;j<4;j++){
        size_t idx = (size_t)t*KVPAD + 4*tid + j;
        v[j] = rejoin(g_kvs_h[idx], g_kvs_l[idx]);
    }
    float ss = v[0]*v[0]+v[1]*v[1]+v[2]*v[2]+v[3]*v[3];
    ss = warpSum(ss);
    __shared__ float red[4];
    if ((tid&31)==0) red[tid>>5] = ss;
    __syncthreads();
    float tot = red[0]+red[1]+red[2]+red[3];
    float r = rsqrtf(tot*(1.0f/KVR) + 1e-6f);
    #pragma unroll
    for (int j=0;j<4;j++){
        int c = 4*tid + j;
        g_ke[(size_t)t*DEFF + c] = __float2half_rn(v[j]*r*kvw[c]);
    }
    if (tid < RHALF){
        size_t pi = (size_t)t*KVPAD + KVR + 2*tid;
        float xr = rejoin(g_kvs_h[pi],   g_kvs_l[pi]);
        float xi = rejoin(g_kvs_h[pi+1], g_kvs_l[pi+1]);
        float c  = g_cos[s*RHALF+tid], sn = g_sin[s*RHALF+tid];
        size_t di = (size_t)t*DEFF + KVR + 2*tid;
        g_ke[di]   = __float2half_rn(xr*c - xi*sn);
        g_ke[di+1] = __float2half_rn(xr*sn + xi*c);
    }
}

// coalesced tiled transpose: ke (fp16, [tok][DEFF]) -> keT (fp16, [b][DEFF][S])
__global__ void transpose_keT(){
    __shared__ half th[32][33];
    int b = blockIdx.z;
    int c0 = blockIdx.y*32, s0 = blockIdx.x*32;
    int tx = threadIdx.x, ty = threadIdx.y;   // 32 x 8
    #pragma unroll
    for (int i=0;i<32;i+=8){
        th[ty+i][tx] = g_ke[(size_t)(b*S_LEN + s0 + ty + i)*DEFF + c0 + tx];
    }
    __syncthreads();
    #pragma unroll
    for (int i=0;i<32;i+=8){
        g_keT[((size_t)b*DEFF + c0 + ty + i)*S_LEN + s0 + tx] = th[tx][ty+i];
    }
}

// one block per token, 512 threads = 16 heads x 32 rope pairs; q stored fp16
__global__ void prep_qpe_kernel(){
    int t = blockIdx.x;
    int b = t / S_LEN, s = t % S_LEN;
    int h = threadIdx.x >> 5, i = threadIdx.x & 31;
    size_t si = (size_t)t*QOUT + h*QD + NOPE + 2*i;
    float xr = __half2float(g_qs_f[si]);
    float xi = __half2float(g_qs_f[si+1]);
    float c  = g_cos[s*RHALF+i], sn = g_sin[s*RHALF+i];
    size_t di = ((size_t)(b*NH+h)*S_LEN + s)*DEFF + KVR + 2*i;
    g_qe[di]   = __float2half_rn(xr*c - xi*sn);
    g_qe[di+1] = __float2half_rn(xr*sn + xi*c);
}

// ---------------- split GEMM with ldmatrix ----------------
// MODE 0: bf16x3  (A hi/lo bf16, B hi/lo bf16, 3 passes, 3 stages)
// MODE 1: fp16 2p (A single fp16, B hi/lo fp16, 2 passes, 4 stages)
// MODE 2: fp16 1p (A single fp16, B single fp16, 1 pass, 4 stages)
// OUT: 0 = fp32, 1 = bf16 hi/lo planes, 2 = single fp16 plane.
template<int BN_T, int OUT, int MODE>
__global__ __launch_bounds__(256,2) void mma_gemm(
    const bf16* __restrict__ Ah, const bf16* __restrict__ Al,
    const bf16* __restrict__ Bh, const bf16* __restrict__ Bl,
    float* __restrict__ Cf, bf16* __restrict__ Ch, bf16* __restrict__ Cl,
    int K, int lda, int ldb, int ldc, int zdiv,
    ll zA1, ll zA2, ll zB1, ll zB2, ll zC1, ll zC2,
    float alpha, int causal, int klimit)
{
    if (causal && blockIdx.x > blockIdx.y) return;
    constexpr int NST = (MODE==0) ? 3 : 4;
    constexpr int NPA = (MODE==0) ? 2 : 1;
    constexpr int NPB = (MODE==2) ? 1 : 2;
    constexpr int WN  = BN_T/32;
    constexpr int WM  = 8/WN;
    constexpr int WTM = 128/WM;
    constexpr int MF  = WTM/16;
    constexpr int NF  = 4;
    constexpr int SA  = 128*64;
    constexpr int SB  = BN_T*64;
    constexpr int STG = NPA*SA + NPB*SB;

    extern __shared__ char smc[];
    const uint32_t sbase = smem_u32(smc);

    const int tid = threadIdx.x, lane = tid & 31, wid = tid >> 5;
    const int wm = wid / WN, wn = wid % WN;
    const int grp = lane >> 2, tig = lane & 3;
    const int lrow = lane & 7, sub = lane >> 3;
    const int zl = blockIdx.z % zdiv, zh = blockIdx.z / zdiv;
    const ll n0 = (ll)blockIdx.x * BN_T;

    const int aRowB = wm*WTM + ((sub&1)<<3) + lrow;
    const int aKo   = (sub>>1)<<4;
    const int bRowB = wn*32 + ((sub>>1)<<3) + lrow;
    const int bKo   = (sub&1)<<4;

    const ll aoff = zl*zA1 + zh*zA2 + (ll)blockIdx.y*128*lda;
    const bf16* Ahb = Ah + aoff;
    const bf16* Alb = Al + aoff;
    const ll boff = zl*zB1 + zh*zB2 + n0*ldb;
    const bf16* Bhb = Bh + boff;
    const bf16* Blb = Bl + boff;

    int kEnd = K;
    if (klimit){ int kl = ((int)blockIdx.y + 1)*128; if (kl < kEnd) kEnd = kl; }
    const int nk = kEnd >> 5;

    float acc[MF][NF][4];
    #pragma unroll
    for (int i=0;i<MF;i++)
        #pragma unroll
        for (int j=0;j<NF;j++)
            #pragma unroll
            for (int c=0;c<4;c++) acc[i][j][c] = 0.f;

    const int row = tid >> 2, g = tid & 3;

    auto LOAD = [&](int kb){
        const int s = kb % NST;
        const uint32_t ub = sbase + (uint32_t)(s*STG);
        const ll koff = ((ll)kb << 5) + g*8;
        #pragma unroll
        for (int i=0;i<2;i++){
            int r = row + i*64;
            uint32_t o = swz((uint32_t)(r*64 + g*16));
            cp16(ub + o, Ahb + (ll)r*lda + koff);
            if (MODE==0) cp16(ub + SA + o, Alb + (ll)r*lda + koff);
        }
        const uint32_t bb = ub + NPA*SA;
        #pragma unroll
        for (int i=0;i<BN_T/64;i++){
            int r = row + i*64;
            uint32_t o = swz((uint32_t)(r*64 + g*16));
            cp16(bb + o, Bhb + (ll)r*ldb + koff);
            if (MODE!=2) cp16(bb + SB + o, Blb + (ll)r*ldb + koff);
        }
        cp_commit();
    };

    #pragma unroll
    for (int kb=0; kb<NST-1; kb++) if (kb < nk) LOAD(kb);

    for (int k=0; k<nk; k++){
        cp_wait<NST-2>();
        __syncthreads();
        if (k + NST - 1 < nk) LOAD(k + NST - 1);
        else cp_commit();

        const int s = k % NST;
        const uint32_t AH = sbase + (uint32_t)(s*STG);
        const uint32_t AL = AH + SA;
        const uint32_t BH = AH + NPA*SA;
        const uint32_t BL = BH + SB;

        #pragma unroll
        for (int kk=0; kk<2; kk++){
            const int ck = kk*32;
            uint32_t bh[2*NF], bl[2*NF];
            #pragma unroll
            for (int nfp=0; nfp<NF/2; nfp++){
                uint32_t bo = swz((uint32_t)((bRowB + nfp*16)*64 + ck + bKo));
                ldsm4(&bh[4*nfp], BH + bo);
                if (MODE!=2) ldsm4(&bl[4*nfp], BL + bo);
            }
            #pragma unroll
            for (int mf=0; mf<MF; mf++){
                uint32_t ao = swz((uint32_t)((aRowB + mf*16)*64 + ck + aKo));
                uint32_t ah[4];
                ldsm4(ah, AH + ao);
                if (MODE==2){
                    #pragma unroll
                    for (int nf=0; nf<NF; nf++) mma_f16(acc[mf][nf], ah, &bh[2*nf]);
                } else if (MODE==1){
                    #pragma unroll
                    for (int nf=0; nf<NF; nf++) mma_f16(acc[mf][nf], ah, &bh[2*nf]);
                    #pragma unroll
                    for (int nf=0; nf<NF; nf++) mma_f16(acc[mf][nf], ah, &bl[2*nf]);
                } else {
                    uint32_t al[4];
                    ldsm4(al, AL + ao);
                    #pragma unroll
                    for (int nf=0; nf<NF; nf++) mma_bf16(acc[mf][nf], ah, &bh[2*nf]);
                    #pragma unroll
                    for (int nf=0; nf<NF; nf++) mma_bf16(acc[mf][nf], ah, &bl[2*nf]);
                    #pragma unroll
                    for (int nf=0; nf<NF; nf++) mma_bf16(acc[mf][nf], al, &bh[2*nf]);
                }
            }
        }
    }

    // ---- epilogue ----
    const ll cbase = zl*zC1 + zh*zC2
                   + ((ll)blockIdx.y*128 + wm*WTM)*ldc + n0 + wn*32;
    #pragma unroll
    for (int mf=0; mf<MF; mf++){
        int r0 = mf*16 + grp;
        #pragma unroll
        for (int nf=0; nf<NF; nf++){
            int c = nf*8 + tig*2;
            #pragma unroll
            for (int half_=0; half_<2; half_++){
                ll off = cbase + (ll)(r0 + half_*8)*ldc + c;
                float v0 = acc[mf][nf][2*half_+0]*alpha;
                float v1 = acc[mf][nf][2*half_+1]*alpha;
                if (OUT == 1){
                    bf16 h0,l0,h1,l1;
                    split2(v0,h0,l0); split2(v1,h1,l1);
                    bf162 hp; hp.x=h0; hp.y=h1;
                    bf162 lp; lp.x=l0; lp.y=l1;
                    *(bf162*)(Ch + off) = hp;
                    *(bf162*)(Cl + off) = lp;
                } else if (OUT == 2){
                    __half2 hp;
                    hp.x = __float2half_rn(v0);
                    hp.y = __float2half_rn(v1);
                    *(__half2*)((half*)Ch + off) = hp;
                } else {
                    float2 o; o.x=v0; o.y=v1;
                    *(float2*)(Cf + off) = o;
                }
            }
        }
    }
}

// ---------------- causal softmax -> single fp16 probs ----------------
__global__ void softmax_kernel(){
    const int s = blockIdx.x;
    const ll z = blockIdx.y;
    const float* row = g_scores + (z*S_LEN + (ll)s)*S_LEN;
    half* pr = g_pr + (z*S_LEN + (ll)s)*S_LEN;
    const int n = s + 1;
    const int nend = ((s>>7)+1)<<7;
    const int tid = threadIdx.x;

    float e[16];
    float mx = -1e30f;
    #pragma unroll
    for (int i=0;i<16;i++){
        int t = tid + i*128;
        e[i] = (t < n) ? row[t] : -1e30f;
        mx = fmaxf(mx, e[i]);
    }
    mx = warpMax(mx);
    __shared__ float redm[4], reds[4];
    if ((tid&31)==0) redm[tid>>5] = mx;
    __syncthreads();
    mx = fmaxf(fmaxf(redm[0],redm[1]), fmaxf(redm[2],redm[3]));

    float sum = 0.f;
    #pragma unroll
    for (int i=0;i<16;i++){
        int t = tid + i*128;
        float v = (t < n) ? exp2f(e[i] - mx) : 0.f;
        e[i] = v;
        sum += v;
    }
    sum = warpSum(sum);
    if ((tid&31)==0) reds[tid>>5] = sum;
    __syncthreads();
    sum = reds[0]+reds[1]+reds[2]+reds[3];
    const float inv = 1.0f / sum;

    #pragma unroll
    for (int i=0;i<16;i++){
        int t = tid + i*128;
        if (t < nend) pr[t] = __float2half_rn(e[i]*inv);
    }
}

// ---------------- host side ----------------
// omode: 0 fp32, 1 bf16 hi/lo, 2 fp16 single ; mode: 0 bf16x3, 1 fp16-2p, 2 fp16-1p
static void launch_g(int omode, int mode,
    const bf16* Ah, const bf16* Al, const bf16* Bh, const bf16* Bl,
    float* Cf, bf16* Ch, bf16* Cl,
    int M, int N, int K, int lda, int ldb, int ldc,
    int Z, int zdiv,
    ll zA1, ll zA2, ll zB1, ll zB2, ll zC1, ll zC2,
    float alpha, bool causal, bool klimit)
{
    dim3 grid(N/128, M/128, Z);
    int c = causal?1:0, kl = klimit?1:0;
    #define GO(O,M_) { \
        size_t sm = (size_t)((M_==0)?3:4) * ((((M_==0)?2:1) + ((M_==2)?1:2))*128*64); \
        cudaFuncSetAttribute(mma_gemm<128,O,M_>, cudaFuncAttributeMaxDynamicSharedMemorySize, (int)sm); \
        mma_gemm<128,O,M_><<<grid,256,sm>>>(Ah,Al,Bh,Bl,Cf,Ch,Cl,K,lda,ldb,ldc,zdiv,zA1,zA2,zB1,zB2,zC1,zC2,alpha,c,kl); \
        return; }
    if (mode==1 && omode==1) GO(1,1);
    if (mode==1 && omode==2) GO(2,1);
    if (mode==2 && omode==0) GO(0,2);
    if (mode==2 && omode==2) GO(2,2);
    #undef GO
}

#define SYM(p, s) cudaGetSymbolAddress((void**)&p, s)

extern "C" void kernel_launch(void* const* d_in, const int* in_sizes, int n_in,
                              void* d_out, int out_size)
{
    (void)in_sizes; (void)n_in; (void)out_size;
    const float* x      = (const float*)d_in[0];
    const float* angles = (const float*)d_in[1];
    const float* wq     = (const float*)d_in[2];
    const float* wkv_a  = (const float*)d_in[3];
    const float* wkv_b  = (const float*)d_in[4];
    const float* wo     = (const float*)d_in[5];
    const float* kvw    = (const float*)d_in[6];
    float* out = (float*)d_out;

    bf16 *kvh,*kvl;
    half *xsf,*wqfh,*wqfl,*wafh,*wafl,*wbv,*wbTfh,*wbTfl,*wof;
    half *qsf,*ke,*keT,*qe,*pr,*ol,*os;
    float *sc;
    SYM(xsf,g_xs_f);
    SYM(wqfh,g_wqf_h); SYM(wqfl,g_wqf_l);
    SYM(wafh,g_waf_h); SYM(wafl,g_waf_l); SYM(wbv,g_wbv);
    SYM(wbTfh,g_wbTf_h); SYM(wbTfl,g_wbTf_l); SYM(wof,g_wof);
    SYM(qsf,g_qs_f); SYM(kvh,g_kvs_h); SYM(kvl,g_kvs_l);
    SYM(ke,g_ke); SYM(keT,g_keT);
    SYM(qe,g_qe); SYM(pr,g_pr);
    SYM(ol,g_ol); SYM(os,g_os);
    SYM(sc,g_scores);

    const double msc = 0.1*log(40.0) + 1.0;
    const float softmax_scale = (float)(pow((double)QD, -0.5)*msc*msc);
    const float score_alpha = (float)((double)softmax_scale * LOG2E);

    // 0) converts / splits (all fp16-based now)
    {
        int n;
        n = NTOK*DIM/4;            cvt_f16<<<(n+255)/256,256>>>((const float4*)x, xsf, n);
        n = QOUT*DIM/4;            split_arr_f16<<<(n+255)/256,256>>>((const float4*)wq, wqfh, wqfl, n);
        n = KVOUT*DIM/4;           split_arr_f16<<<(n+255)/256,256>>>((const float4*)wkv_a, wafh, wafl, n);
        zero_tail_waf<<<((KVPAD-KVOUT)*DIM+255)/256,256>>>();
        n = NH*VDIM*KVR;           cvtV_f16<<<(n+255)/256,256>>>(wkv_b);
        n = DIM*NH*VDIM/4;         cvt_f16<<<(n+255)/256,256>>>((const float4*)wo, wof, n);
        n = NH*KVR*NOPE;           splitT_wkvb<<<(n+255)/256,256>>>(wkv_b);
    }
    rope_prep_kernel<<<(S_LEN*RHALF+127)/128, 128>>>(angles);

    // 1) q = x(fp16) @ wq(fp16 hi/lo)^T  (2-pass -> fp16 single)
    launch_g(2,1, (const bf16*)xsf, 0, (const bf16*)wqfh, (const bf16*)wqfl, 0, (bf16*)qsf, 0,
             NTOK, QOUT, DIM, DIM, DIM, QOUT, 1,1, 0,0,0,0,0,0, 1.f,false,false);

    // 2) kv = x(fp16) @ wkv_a(fp16 hi/lo)^T  (2-pass -> bf16 hi/lo, N padded to 640)
    launch_g(1,1, (const bf16*)xsf, 0, (const bf16*)wafh, (const bf16*)wafl, 0, kvh,kvl,
             NTOK, KVPAD, DIM, DIM, DIM, KVPAD, 1,1, 0,0,0,0,0,0, 1.f,false,false);

    // 3) keff (single fp16) + keT transpose
    prep_keff_kernel<<<NTOK, 128>>>(kvw);
    transpose_keT<<<dim3(S_LEN/32, DEFF/32, BATCH), dim3(32,8)>>>();

    // 4) rope(q_pe) -> qe fp16
    prep_qpe_kernel<<<NTOK, 512>>>();

    // 5) qe[...,0:512] = q_nope(fp16) @ wbT(fp16 hi/lo)  (2-pass -> fp16 single)
    launch_g(2,1, (const bf16*)qsf, 0, (const bf16*)wbTfh, (const bf16*)wbTfl, 0, (bf16*)qe, 0,
             S_LEN, KVR, NOPE, QOUT, NOPE, DEFF, BATCH*NH, NH,
             (ll)QD, (ll)S_LEN*QOUT, (ll)KVR*NOPE, 0,
             (ll)S_LEN*DEFF, (ll)NH*S_LEN*DEFF, 1.f,false,false);

    // 6) scores = scale * qe(fp16) @ ke(fp16)^T  (1-pass, causal block-skip)
    launch_g(0,2, (const bf16*)qe, 0, (const bf16*)ke, 0, sc, 0,0,
             S_LEN, S_LEN, DEFF, DEFF, DEFF, S_LEN, BATCH*NH, NH,
             (ll)S_LEN*DEFF, (ll)NH*S_LEN*DEFF, 0, (ll)S_LEN*DEFF,
             (ll)S_LEN*S_LEN, (ll)NH*S_LEN*S_LEN, score_alpha, true, false);

    // 7) softmax -> fp16 probs
    softmax_kernel<<<dim3(S_LEN, BATCH*NH), 128>>>();

    // 8) olat = probs(fp16) @ keT(fp16)^T -> fp16, 1-pass, K capped
    launch_g(2,2, (const bf16*)pr, 0, (const bf16*)keT, 0, 0, (bf16*)ol, 0,
             S_LEN, KVR, S_LEN, S_LEN, S_LEN, KVR, BATCH*NH, NH,
             (ll)S_LEN*S_LEN, (ll)NH*S_LEN*S_LEN, 0, (ll)DEFF*S_LEN,
             (ll)S_LEN*KVR, (ll)NH*S_LEN*KVR, 1.f, false, true);

    // 9) o = olat(fp16) @ wbv(fp16)^T -> fp16, 1-pass (per (b,h), K=512)
    launch_g(2,2, (const bf16*)ol, 0, (const bf16*)wbv, 0, 0, (bf16*)os, 0,
             S_LEN, VDIM, KVR, KVR, KVR, NH*VDIM, BATCH*NH, NH,
             (ll)S_LEN*KVR, (ll)NH*S_LEN*KVR, (ll)VDIM*KVR, 0,
             (ll)VDIM, (ll)S_LEN*NH*VDIM, 1.f, false, false);

    // 10) out = o(fp16) @ wo(fp16)^T -> fp32, 1-pass
    launch_g(0,2, (const bf16*)os, 0, (const bf16*)wof, 0, out, 0,0,
             NTOK, DIM, NH*VDIM, NH*VDIM, NH*VDIM, DIM, 1,1,
             0,0,0,0,0,0, 1.f,false,false);
}

// round 14
// speedup vs baseline: 2.5875x; 1.1170x over previous
#include <cuda_runtime.h>
#include <cuda_bf16.h>
#include <cuda_fp16.h>
#include <math.h>
#include <stdint.h>

// ---------------- problem constants ----------------
#define S_LEN 2048
#define BATCH 2
#define NTOK  (S_LEN*BATCH)     // 4096
#define NH    16
#define DIM   2048
#define NOPE  128
#define ROPE  64
#define RHALF 32
#define VDIM  128
#define KVR   512
#define QD    (NOPE+ROPE)       // 192
#define QOUT  (NH*QD)           // 3072
#define KVOUT (KVR+ROPE)        // 576
#define KVPAD 640               // kv-proj N padded to 5*128
#define DEFF  576
#define LOG2E 1.4426950408889634

typedef long long ll;
typedef __nv_bfloat16 bf16;
typedef __nv_bfloat162 bf162;

// ---------------- scratch ----------------
__device__ __align__(16) half g_xs_f [(size_t)NTOK*DIM];
__device__ __align__(16) half g_wqf  [(size_t)QOUT*DIM];
__device__ __align__(16) half g_waf_h[(size_t)KVPAD*DIM], g_waf_l[(size_t)KVPAD*DIM];
__device__ __align__(16) half g_wbv  [(size_t)NH*VDIM*KVR];
__device__ __align__(16) half g_wbTf_h[(size_t)NH*KVR*NOPE], g_wbTf_l[(size_t)NH*KVR*NOPE];
__device__ __align__(16) half g_wof  [(size_t)DIM*NH*VDIM];
__device__ __align__(16) half g_qs_f [(size_t)NTOK*QOUT];
__device__ __align__(16) bf16 g_kvs_h[(size_t)NTOK*KVPAD],  g_kvs_l[(size_t)NTOK*KVPAD];
__device__ __align__(16) half g_ke  [(size_t)NTOK*DEFF];
__device__ __align__(16) half g_keT [(size_t)BATCH*DEFF*S_LEN];
__device__ __align__(16) half g_qe  [(size_t)BATCH*NH*S_LEN*DEFF];
__device__ float g_scores[(size_t)BATCH*NH*S_LEN*S_LEN];
__device__ __align__(16) half g_pr   [(size_t)BATCH*NH*S_LEN*S_LEN];
__device__ __align__(16) half g_ol   [(size_t)BATCH*NH*S_LEN*KVR];
__device__ __align__(16) half g_os   [(size_t)NTOK*NH*VDIM];
__device__ float g_cos[S_LEN*RHALF];
__device__ float g_sin[S_LEN*RHALF];

// ---------------- helpers ----------------
__device__ __forceinline__ float warpMax(float v){
    #pragma unroll
    for (int o=16;o;o>>=1) v = fmaxf(v, __shfl_xor_sync(0xffffffffu, v, o));
    return v;
}
__device__ __forceinline__ float warpSum(float v){
    #pragma unroll
    for (int o=16;o;o>>=1) v += __shfl_xor_sync(0xffffffffu, v, o);
    return v;
}
__device__ __forceinline__ uint32_t smem_u32(const void* p){
    uint32_t a;
    asm("{ .reg .u64 t; cvta.to.shared.u64 t, %1; cvt.u32.u64 %0, t; }" : "=r"(a) : "l"(p));
    return a;
}
__device__ __forceinline__ void split2(float f, bf16& h, bf16& l){
    h = __float2bfloat16_rn(f);
    l = __float2bfloat16_rn(f - __bfloat162float(h));
}
__device__ __forceinline__ void split2h(float f, half& h, half& l){
    h = __float2half_rn(f);
    l = __float2half_rn(f - __half2float(h));
}
__device__ __forceinline__ float rejoin(bf16 h, bf16 l){
    return __bfloat162float(h) + __bfloat162float(l);
}
__device__ __forceinline__ void mma_bf16(float* d, const uint32_t* a, const uint32_t* b){
    asm volatile(
        "mma.sync.aligned.m16n8k16.row.col.f32.bf16.bf16.f32 "
        "{%0,%1,%2,%3}, {%4,%5,%6,%7}, {%8,%9}, {%0,%1,%2,%3};"
        : "+f"(d[0]), "+f"(d[1]), "+f"(d[2]), "+f"(d[3])
        : "r"(a[0]), "r"(a[1]), "r"(a[2]), "r"(a[3]), "r"(b[0]), "r"(b[1]));
}
__device__ __forceinline__ void mma_f16(float* d, const uint32_t* a, const uint32_t* b){
    asm volatile(
        "mma.sync.aligned.m16n8k16.row.col.f32.f16.f16.f32 "
        "{%0,%1,%2,%3}, {%4,%5,%6,%7}, {%8,%9}, {%0,%1,%2,%3};"
        : "+f"(d[0]), "+f"(d[1]), "+f"(d[2]), "+f"(d[3])
        : "r"(a[0]), "r"(a[1]), "r"(a[2]), "r"(a[3]), "r"(b[0]), "r"(b[1]));
}
__device__ __forceinline__ void ldsm4(uint32_t* r, uint32_t a){
    asm volatile("ldmatrix.sync.aligned.m8n8.x4.shared.b16 {%0,%1,%2,%3}, [%4];"
        : "=r"(r[0]), "=r"(r[1]), "=r"(r[2]), "=r"(r[3]) : "r"(a));
}
__device__ __forceinline__ void cp16(uint32_t dst, const void* src){
    asm volatile("cp.async.cg.shared.global [%0], [%1], 16;\n" :: "r"(dst), "l"(src) : "memory");
}
__device__ __forceinline__ void cp_commit(){ asm volatile("cp.async.commit_group;\n" ::: "memory"); }
template<int N>
__device__ __forceinline__ void cp_wait(){ asm volatile("cp.async.wait_group %0;\n" :: "n"(N) : "memory"); }

__device__ __forceinline__ uint32_t swz(uint32_t o){ return o ^ ((o>>3)&0x30u); }

// ---------------- split / convert kernels ----------------
__global__ void split_arr_f16(const float4* __restrict__ src, half* __restrict__ h, half* __restrict__ l, int n4){
    int i = blockIdx.x*blockDim.x + threadIdx.x;
    if (i >= n4) return;
    float4 v = src[i];
    half h0,l0,h1,l1,h2,l2,h3,l3;
    split2h(v.x,h0,l0); split2h(v.y,h1,l1); split2h(v.z,h2,l2); split2h(v.w,h3,l3);
    __half2* hp = (__half2*)(h + 4*(size_t)i);
    __half2* lp = (__half2*)(l + 4*(size_t)i);
    __half2 a; a.x=h0; a.y=h1; hp[0]=a;
    __half2 b; b.x=h2; b.y=h3; hp[1]=b;
    __half2 c; c.x=l0; c.y=l1; lp[0]=c;
    __half2 d; d.x=l2; d.y=l3; lp[1]=d;
}
// split wkv_a over KVPAD rows: rows >= KVOUT are zero-filled (no separate tail kernel)
__global__ void split_waf_pad(const float4* __restrict__ src){
    int i = blockIdx.x*blockDim.x + threadIdx.x;
    if (i >= KVPAD*DIM/4) return;
    __half2 a,b,c,d;
    if (i < KVOUT*DIM/4){
        float4 v = src[i];
        half h0,l0,h1,l1,h2,l2,h3,l3;
        split2h(v.x,h0,l0); split2h(v.y,h1,l1); split2h(v.z,h2,l2); split2h(v.w,h3,l3);
        a.x=h0; a.y=h1; b.x=h2; b.y=h3; c.x=l0; c.y=l1; d.x=l2; d.y=l3;
    } else {
        half z = __float2half_rn(0.f);
        a.x=z; a.y=z; b=a; c=a; d=a;
    }
    __half2* hp = (__half2*)(g_waf_h + 4*(size_t)i);
    __half2* lp = (__half2*)(g_waf_l + 4*(size_t)i);
    hp[0]=a; hp[1]=b; lp[0]=c; lp[1]=d;
}
__global__ void cvt_f16(const float4* __restrict__ src, half* __restrict__ dst, int n4){
    int i = blockIdx.x*blockDim.x + threadIdx.x;
    if (i >= n4) return;
    float4 v = src[i];
    __half2* dp = (__half2*)(dst + 4*(size_t)i);
    __half2 a; a.x=__float2half_rn(v.x); a.y=__float2half_rn(v.y); dp[0]=a;
    __half2 b; b.x=__float2half_rn(v.z); b.y=__float2half_rn(v.w); dp[1]=b;
}
// wbv[h][v][c] = fp16(wkv_b[h*256 + 128 + v][c])
__global__ void cvtV_f16(const float* __restrict__ wb){
    int i = blockIdx.x*blockDim.x + threadIdx.x;
    if (i >= NH*VDIM*KVR) return;
    int c = i % KVR, v = (i/KVR) % VDIM, h = i/(KVR*VDIM);
    g_wbv[i] = __float2half_rn(wb[((size_t)h*(NOPE+VDIM) + NOPE + v)*KVR + c]);
}
__global__ void splitT_wkvb(const float* __restrict__ wb){
    int i = blockIdx.x*blockDim.x + threadIdx.x;
    if (i >= NH*KVR*NOPE) return;
    int d = i % NOPE, c = (i/NOPE) % KVR, h = i/(NOPE*KVR);
    float v = wb[((size_t)h*(NOPE+VDIM) + d)*KVR + c];
    split2h(v, g_wbTf_h[i], g_wbTf_l[i]);
}

// ---------------- prep kernels ----------------
__global__ void rope_prep_kernel(const float* __restrict__ ang){
    int i = blockIdx.x*blockDim.x + threadIdx.x;
    if (i < S_LEN*RHALF){
        float a = ang[i];
        g_cos[i] = cosf(a);
        g_sin[i] = sinf(a);
    }
}

__global__ void prep_keff_kernel(const float* __restrict__ kvw){
    int t = blockIdx.x;
    int s = t % S_LEN;
    int tid = threadIdx.x;
    float v[4];
    #pragma unroll
    for (int j=0;j<4;j++){
        size_t idx = (size_t)t*KVPAD + 4*tid + j;
        v[j] = rejoin(g_kvs_h[idx], g_kvs_l[idx]);
    }
    float ss = v[0]*v[0]+v[1]*v[1]+v[2]*v[2]+v[3]*v[3];
    ss = warpSum(ss);
    __shared__ float red[4];
    if ((tid&31)==0) red[tid>>5] = ss;
    __syncthreads();
    float tot = red[0]+red[1]+red[2]+red[3];
    float r = rsqrtf(tot*(1.0f/KVR) + 1e-6f);
    #pragma unroll
    for (int j=0;j<4;j++){
        int c = 4*tid + j;
        g_ke[(size_t)t*DEFF + c] = __float2half_rn(v[j]*r*kvw[c]);
    }
    if (tid < RHALF){
        size_t pi = (size_t)t*KVPAD + KVR + 2*tid;
        float xr = rejoin(g_kvs_h[pi],   g_kvs_l[pi]);
        float xi = rejoin(g_kvs_h[pi+1], g_kvs_l[pi+1]);
        float c  = g_cos[s*RHALF+tid], sn = g_sin[s*RHALF+tid];
        size_t di = (size_t)t*DEFF + KVR + 2*tid;
        g_ke[di]   = __float2half_rn(xr*c - xi*sn);
        g_ke[di+1] = __float2half_rn(xr*sn + xi*c);
    }
}

// coalesced tiled transpose: ke (fp16, [tok][DEFF]) -> keT (fp16, [b][DEFF][S])
__global__ void transpose_keT(){
    __shared__ half th[32][33];
    int b = blockIdx.z;
    int c0 = blockIdx.y*32, s0 = blockIdx.x*32;
    int tx = threadIdx.x, ty = threadIdx.y;   // 32 x 8
    #pragma unroll
    for (int i=0;i<32;i+=8){
        th[ty+i][tx] = g_ke[(size_t)(b*S_LEN + s0 + ty + i)*DEFF + c0 + tx];
    }
    __syncthreads();
    #pragma unroll
    for (int i=0;i<32;i+=8){
        g_keT[((size_t)b*DEFF + c0 + ty + i)*S_LEN + s0 + tx] = th[tx][ty+i];
    }
}

// one block per token, 512 threads = 16 heads x 32 rope pairs; q stored fp16
__global__ void prep_qpe_kernel(){
    int t = blockIdx.x;
    int b = t / S_LEN, s = t % S_LEN;
    int h = threadIdx.x >> 5, i = threadIdx.x & 31;
    size_t si = (size_t)t*QOUT + h*QD + NOPE + 2*i;
    float xr = __half2float(g_qs_f[si]);
    float xi = __half2float(g_qs_f[si+1]);
    float c  = g_cos[s*RHALF+i], sn = g_sin[s*RHALF+i];
    size_t di = ((size_t)(b*NH+h)*S_LEN + s)*DEFF + KVR + 2*i;
    g_qe[di]   = __float2half_rn(xr*c - xi*sn);
    g_qe[di+1] = __float2half_rn(xr*sn + xi*c);
}

// ---------------- split GEMM with ldmatrix ----------------
// MODE 0: bf16x3  (A hi/lo bf16, B hi/lo bf16, 3 passes, 3 stages)
// MODE 1: fp16 2p (A single fp16, B hi/lo fp16, 2 passes, 4 stages)
// MODE 2: fp16 1p (A single fp16, B single fp16, 1 pass, 4 stages)
// OUT: 0 = fp32, 1 = bf16 hi/lo planes, 2 = single fp16 plane.
template<int BN_T, int OUT, int MODE>
__global__ __launch_bounds__(256,2) void mma_gemm(
    const bf16* __restrict__ Ah, const bf16* __restrict__ Al,
    const bf16* __restrict__ Bh, const bf16* __restrict__ Bl,
    float* __restrict__ Cf, bf16* __restrict__ Ch, bf16* __restrict__ Cl,
    int K, int lda, int ldb, int ldc, int zdiv,
    ll zA1, ll zA2, ll zB1, ll zB2, ll zC1, ll zC2,
    float alpha, int causal, int klimit)
{
    if (causal && blockIdx.x > blockIdx.y) return;
    constexpr int NST = (MODE==0) ? 3 : 4;
    constexpr int NPA = (MODE==0) ? 2 : 1;
    constexpr int NPB = (MODE==2) ? 1 : 2;
    constexpr int WN  = BN_T/32;
    constexpr int WM  = 8/WN;
    constexpr int WTM = 128/WM;
    constexpr int MF  = WTM/16;
    constexpr int NF  = 4;
    constexpr int SA  = 128*64;
    constexpr int SB  = BN_T*64;
    constexpr int STG = NPA*SA + NPB*SB;

    extern __shared__ char smc[];
    const uint32_t sbase = smem_u32(smc);

    const int tid = threadIdx.x, lane = tid & 31, wid = tid >> 5;
    const int wm = wid / WN, wn = wid % WN;
    const int grp = lane >> 2, tig = lane & 3;
    const int lrow = lane & 7, sub = lane >> 3;
    const int zl = blockIdx.z % zdiv, zh = blockIdx.z / zdiv;
    const ll n0 = (ll)blockIdx.x * BN_T;

    const int aRowB = wm*WTM + ((sub&1)<<3) + lrow;
    const int aKo   = (sub>>1)<<4;
    const int bRowB = wn*32 + ((sub>>1)<<3) + lrow;
    const int bKo   = (sub&1)<<4;

    const ll aoff = zl*zA1 + zh*zA2 + (ll)blockIdx.y*128*lda;
    const bf16* Ahb = Ah + aoff;
    const bf16* Alb = Al + aoff;
    const ll boff = zl*zB1 + zh*zB2 + n0*ldb;
    const bf16* Bhb = Bh + boff;
    const bf16* Blb = Bl + boff;

    int kEnd = K;
    if (klimit){ int kl = ((int)blockIdx.y + 1)*128; if (kl < kEnd) kEnd = kl; }
    const int nk = kEnd >> 5;

    float acc[MF][NF][4];
    #pragma unroll
    for (int i=0;i<MF;i++)
        #pragma unroll
        for (int j=0;j<NF;j++)
            #pragma unroll
            for (int c=0;c<4;c++) acc[i][j][c] = 0.f;

    const int row = tid >> 2, g = tid & 3;

    auto LOAD = [&](int kb){
        const int s = kb % NST;
        const uint32_t ub = sbase + (uint32_t)(s*STG);
        const ll koff = ((ll)kb << 5) + g*8;
        #pragma unroll
        for (int i=0;i<2;i++){
            int r = row + i*64;
            uint32_t o = swz((uint32_t)(r*64 + g*16));
            cp16(ub + o, Ahb + (ll)r*lda + koff);
            if (MODE==0) cp16(ub + SA + o, Alb + (ll)r*lda + koff);
        }
        const uint32_t bb = ub + NPA*SA;
        #pragma unroll
        for (int i=0;i<BN_T/64;i++){
            int r = row + i*64;
            uint32_t o = swz((uint32_t)(r*64 + g*16));
            cp16(bb + o, Bhb + (ll)r*ldb + koff);
            if (MODE!=2) cp16(bb + SB + o, Blb + (ll)r*ldb + koff);
        }
        cp_commit();
    };

    #pragma unroll
    for (int kb=0; kb<NST-1; kb++) if (kb < nk) LOAD(kb);

    for (int k=0; k<nk; k++){
        cp_wait<NST-2>();
        __syncthreads();
        if (k + NST - 1 < nk) LOAD(k + NST - 1);
        else cp_commit();

        const int s = k % NST;
        const uint32_t AH = sbase + (uint32_t)(s*STG);
        const uint32_t AL = AH + SA;
        const uint32_t BH = AH + NPA*SA;
        const uint32_t BL = BH + SB;

        #pragma unroll
        for (int kk=0; kk<2; kk++){
            const int ck = kk*32;
            uint32_t bh[2*NF], bl[2*NF];
            #pragma unroll
            for (int nfp=0; nfp<NF/2; nfp++){
                uint32_t bo = swz((uint32_t)((bRowB + nfp*16)*64 + ck + bKo));
                ldsm4(&bh[4*nfp], BH + bo);
                if (MODE!=2) ldsm4(&bl[4*nfp], BL + bo);
            }
            #pragma unroll
            for (int mf=0; mf<MF; mf++){
                uint32_t ao = swz((uint32_t)((aRowB + mf*16)*64 + ck + aKo));
                uint32_t ah[4];
                ldsm4(ah, AH + ao);
                if (MODE==2){
                    #pragma unroll
                    for (int nf=0; nf<NF; nf++) mma_f16(acc[mf][nf], ah, &bh[2*nf]);
                } else if (MODE==1){
                    #pragma unroll
                    for (int nf=0; nf<NF; nf++) mma_f16(acc[mf][nf], ah, &bh[2*nf]);
                    #pragma unroll
                    for (int nf=0; nf<NF; nf++) mma_f16(acc[mf][nf], ah, &bl[2*nf]);
                } else {
                    uint32_t al[4];
                    ldsm4(al, AL + ao);
                    #pragma unroll
                    for (int nf=0; nf<NF; nf++) mma_bf16(acc[mf][nf], ah, &bh[2*nf]);
                    #pragma unroll
                    for (int nf=0; nf<NF; nf++) mma_bf16(acc[mf][nf], ah, &bl[2*nf]);
                    #pragma unroll
                    for (int nf=0; nf<NF; nf++) mma_bf16(acc[mf][nf], al, &bh[2*nf]);
                }
            }
        }
    }

    // ---- epilogue ----
    const ll cbase = zl*zC1 + zh*zC2
                   + ((ll)blockIdx.y*128 + wm*WTM)*ldc + n0 + wn*32;
    #pragma unroll
    for (int mf=0; mf<MF; mf++){
        int r0 = mf*16 + grp;
        #pragma unroll
        for (int nf=0; nf<NF; nf++){
            int c = nf*8 + tig*2;
            #pragma unroll
            for (int half_=0; half_<2; half_++){
                ll off = cbase + (ll)(r0 + half_*8)*ldc + c;
                float v0 = acc[mf][nf][2*half_+0]*alpha;
                float v1 = acc[mf][nf][2*half_+1]*alpha;
                if (OUT == 1){
                    bf16 h0,l0,h1,l1;
                    split2(v0,h0,l0); split2(v1,h1,l1);
                    bf162 hp; hp.x=h0; hp.y=h1;
                    bf162 lp; lp.x=l0; lp.y=l1;
                    *(bf162*)(Ch + off) = hp;
                    *(bf162*)(Cl + off) = lp;
                } else if (OUT == 2){
                    __half2 hp;
                    hp.x = __float2half_rn(v0);
                    hp.y = __float2half_rn(v1);
                    *(__half2*)((half*)Ch + off) = hp;
                } else {
                    float2 o; o.x=v0; o.y=v1;
                    *(float2*)(Cf + off) = o;
                }
            }
        }
    }
}

// ---------------- causal softmax -> single fp16 probs ----------------
__global__ void softmax_kernel(){
    const int s = blockIdx.x;
    const ll z = blockIdx.y;
    const float* row = g_scores + (z*S_LEN + (ll)s)*S_LEN;
    half* pr = g_pr + (z*S_LEN + (ll)s)*S_LEN;
    const int n = s + 1;
    const int nend = ((s>>7)+1)<<7;
    const int tid = threadIdx.x;

    float e[16];
    float mx = -1e30f;
    #pragma unroll
    for (int i=0;i<16;i++){
        int t = tid + i*128;
        e[i] = (t < n) ? row[t] : -1e30f;
        mx = fmaxf(mx, e[i]);
    }
    mx = warpMax(mx);
    __shared__ float redm[4], reds[4];
    if ((tid&31)==0) redm[tid>>5] = mx;
    __syncthreads();
    mx = fmaxf(fmaxf(redm[0],redm[1]), fmaxf(redm[2],redm[3]));

    float sum = 0.f;
    #pragma unroll
    for (int i=0;i<16;i++){
        int t = tid + i*128;
        float v = (t < n) ? exp2f(e[i] - mx) : 0.f;
        e[i] = v;
        sum += v;
    }
    sum = warpSum(sum);
    if ((tid&31)==0) reds[tid>>5] = sum;
    __syncthreads();
    sum = reds[0]+reds[1]+reds[2]+reds[3];
    const float inv = 1.0f / sum;

    #pragma unroll
    for (int i=0;i<16;i++){
        int t = tid + i*128;
        if (t < nend) pr[t] = __float2half_rn(e[i]*inv);
    }
}

// ---------------- host side ----------------
// omode: 0 fp32, 1 bf16 hi/lo, 2 fp16 single ; mode: 1 fp16-2p, 2 fp16-1p
static void launch_g(int omode, int mode,
    const bf16* Ah, const bf16* Al, const bf16* Bh, const bf16* Bl,
    float* Cf, bf16* Ch, bf16* Cl,
    int M, int N, int K, int lda, int ldb, int ldc,
    int Z, int zdiv,
    ll zA1, ll zA2, ll zB1, ll zB2, ll zC1, ll zC2,
    float alpha, bool causal, bool klimit)
{
    dim3 grid(N/128, M/128, Z);
    int c = causal?1:0, kl = klimit?1:0;
    #define GO(O,M_) { \
        size_t sm = (size_t)((M_==0)?3:4) * ((((M_==0)?2:1) + ((M_==2)?1:2))*128*64); \
        cudaFuncSetAttribute(mma_gemm<128,O,M_>, cudaFuncAttributeMaxDynamicSharedMemorySize, (int)sm); \
        mma_gemm<128,O,M_><<<grid,256,sm>>>(Ah,Al,Bh,Bl,Cf,Ch,Cl,K,lda,ldb,ldc,zdiv,zA1,zA2,zB1,zB2,zC1,zC2,alpha,c,kl); \
        return; }
    if (mode==1 && omode==1) GO(1,1);
    if (mode==1 && omode==2) GO(2,1);
    if (mode==2 && omode==0) GO(0,2);
    if (mode==2 && omode==2) GO(2,2);
    #undef GO
}

#define SYM(p, s) cudaGetSymbolAddress((void**)&p, s)

extern "C" void kernel_launch(void* const* d_in, const int* in_sizes, int n_in,
                              void* d_out, int out_size)
{
    (void)in_sizes; (void)n_in; (void)out_size;
    const float* x      = (const float*)d_in[0];
    const float* angles = (const float*)d_in[1];
    const float* wq     = (const float*)d_in[2];
    const float* wkv_a  = (const float*)d_in[3];
    const float* wkv_b  = (const float*)d_in[4];
    const float* wo     = (const float*)d_in[5];
    const float* kvw    = (const float*)d_in[6];
    float* out = (float*)d_out;

    bf16 *kvh,*kvl;
    half *xsf,*wqf,*wafh,*wafl,*wbv,*wbTfh,*wbTfl,*wof;
    half *qsf,*ke,*keT,*qe,*pr,*ol,*os;
    float *sc;
    SYM(xsf,g_xs_f); SYM(wqf,g_wqf);
    SYM(wafh,g_waf_h); SYM(wafl,g_waf_l); SYM(wbv,g_wbv);
    SYM(wbTfh,g_wbTf_h); SYM(wbTfl,g_wbTf_l); SYM(wof,g_wof);
    SYM(qsf,g_qs_f); SYM(kvh,g_kvs_h); SYM(kvl,g_kvs_l);
    SYM(ke,g_ke); SYM(keT,g_keT);
    SYM(qe,g_qe); SYM(pr,g_pr);
    SYM(ol,g_ol); SYM(os,g_os);
    SYM(sc,g_scores);

    const double msc = 0.1*log(40.0) + 1.0;
    const float softmax_scale = (float)(pow((double)QD, -0.5)*msc*msc);
    const float score_alpha = (float)((double)softmax_scale * LOG2E);

    // 0) converts / splits
    {
        int n;
        n = NTOK*DIM/4;            cvt_f16<<<(n+255)/256,256>>>((const float4*)x, xsf, n);
        n = QOUT*DIM/4;            cvt_f16<<<(n+255)/256,256>>>((const float4*)wq, wqf, n);
        n = KVPAD*DIM/4;           split_waf_pad<<<(n+255)/256,256>>>((const float4*)wkv_a);
        n = NH*VDIM*KVR;           cvtV_f16<<<(n+255)/256,256>>>(wkv_b);
        n = DIM*NH*VDIM/4;         cvt_f16<<<(n+255)/256,256>>>((const float4*)wo, wof, n);
        n = NH*KVR*NOPE;           splitT_wkvb<<<(n+255)/256,256>>>(wkv_b);
    }
    rope_prep_kernel<<<(S_LEN*RHALF+127)/128, 128>>>(angles);

    // 1) q = x(fp16) @ wq(fp16)^T  (1-pass -> fp16 single)
    launch_g(2,2, (const bf16*)xsf, 0, (const bf16*)wqf, 0, 0, (bf16*)qsf, 0,
             NTOK, QOUT, DIM, DIM, DIM, QOUT, 1,1, 0,0,0,0,0,0, 1.f,false,false);

    // 2) kv = x(fp16) @ wkv_a(fp16 hi/lo)^T  (2-pass -> bf16 hi/lo, N padded to 640)
    launch_g(1,1, (const bf16*)xsf, 0, (const bf16*)wafh, (const bf16*)wafl, 0, kvh,kvl,
             NTOK, KVPAD, DIM, DIM, DIM, KVPAD, 1,1, 0,0,0,0,0,0, 1.f,false,false);

    // 3) keff (single fp16) + keT transpose
    prep_keff_kernel<<<NTOK, 128>>>(kvw);
    transpose_keT<<<dim3(S_LEN/32, DEFF/32, BATCH), dim3(32,8)>>>();

    // 4) rope(q_pe) -> qe fp16
    prep_qpe_kernel<<<NTOK, 512>>>();

    // 5) qe[...,0:512] = q_nope(fp16) @ wbT(fp16 hi/lo)  (2-pass -> fp16 single)
    launch_g(2,1, (const bf16*)qsf, 0, (const bf16*)wbTfh, (const bf16*)wbTfl, 0, (bf16*)qe, 0,
             S_LEN, KVR, NOPE, QOUT, NOPE, DEFF, BATCH*NH, NH,
             (ll)QD, (ll)S_LEN*QOUT, (ll)KVR*NOPE, 0,
             (ll)S_LEN*DEFF, (ll)NH*S_LEN*DEFF, 1.f,false,false);

    // 6) scores = scale * qe(fp16) @ ke(fp16)^T  (1-pass, causal block-skip)
    launch_g(0,2, (const bf16*)qe, 0, (const bf16*)ke, 0, sc, 0,0,
             S_LEN, S_LEN, DEFF, DEFF, DEFF, S_LEN, BATCH*NH, NH,
             (ll)S_LEN*DEFF, (ll)NH*S_LEN*DEFF, 0, (ll)S_LEN*DEFF,
             (ll)S_LEN*S_LEN, (ll)NH*S_LEN*S_LEN, score_alpha, true, false);

    // 7) softmax -> fp16 probs
    softmax_kernel<<<dim3(S_LEN, BATCH*NH), 128>>>();

    // 8) olat = probs(fp16) @ keT(fp16)^T -> fp16, 1-pass, K capped
    launch_g(2,2, (const bf16*)pr, 0, (const bf16*)keT, 0, 0, (bf16*)ol, 0,
             S_LEN, KVR, S_LEN, S_LEN, S_LEN, KVR, BATCH*NH, NH,
             (ll)S_LEN*S_LEN, (ll)NH*S_LEN*S_LEN, 0, (ll)DEFF*S_LEN,
             (ll)S_LEN*KVR, (ll)NH*S_LEN*KVR, 1.f, false, true);

    // 9) o = olat(fp16) @ wbv(fp16)^T -> fp16, 1-pass (per (b,h), K=512)
    launch_g(2,2, (const bf16*)ol, 0, (const bf16*)wbv, 0, 0, (bf16*)os, 0,
             S_LEN, VDIM, KVR, KVR, KVR, NH*VDIM, BATCH*NH, NH,
             (ll)S_LEN*KVR, (ll)NH*S_LEN*KVR, (ll)VDIM*KVR, 0,
             (ll)VDIM, (ll)S_LEN*NH*VDIM, 1.f, false, false);

    // 10) out = o(fp16) @ wo(fp16)^T -> fp32, 1-pass
    launch_g(0,2, (const bf16*)os, 0, (const bf16*)wof, 0, out, 0,0,
             NTOK, DIM, NH*VDIM, NH*VDIM, NH*VDIM, DIM, 1,1,
             0,0,0,0,0,0, 1.f,false,false);
}

// round 15
// speedup vs baseline: 2.5903x; 1.0011x over previous
#include <cuda_runtime.h>
#include <cuda_bf16.h>
#include <cuda_fp16.h>
#include <math.h>
#include <stdint.h>

// ---------------- problem constants ----------------
#define S_LEN 2048
#define BATCH 2
#define NTOK  (S_LEN*BATCH)     // 4096
#define NH    16
#define DIM   2048
#define NOPE  128
#define ROPE  64
#define RHALF 32
#define VDIM  128
#define KVR   512
#define QD    (NOPE+ROPE)       // 192
#define QOUT  (NH*QD)           // 3072
#define KVOUT (KVR+ROPE)        // 576
#define KVPAD 640               // kv-proj N padded to 5*128
#define DEFF  576
#define LOG2E 1.4426950408889634

typedef long long ll;
typedef __nv_bfloat16 bf16;
typedef __nv_bfloat162 bf162;

// ---------------- scratch ----------------
__device__ __align__(16) half g_xs_f [(size_t)NTOK*DIM];
__device__ __align__(16) half g_wqf  [(size_t)QOUT*DIM];
__device__ __align__(16) half g_waf_h[(size_t)KVPAD*DIM], g_waf_l[(size_t)KVPAD*DIM];
__device__ __align__(16) half g_wbv  [(size_t)NH*VDIM*KVR];
__device__ __align__(16) half g_wbTf_h[(size_t)NH*KVR*NOPE], g_wbTf_l[(size_t)NH*KVR*NOPE];
__device__ __align__(16) half g_wof  [(size_t)DIM*NH*VDIM];
__device__ __align__(16) half g_qs_f [(size_t)NTOK*QOUT];
__device__ __align__(16) bf16 g_kvs_h[(size_t)NTOK*KVPAD],  g_kvs_l[(size_t)NTOK*KVPAD];
__device__ __align__(16) half g_ke  [(size_t)NTOK*DEFF];
__device__ __align__(16) half g_keT [(size_t)BATCH*DEFF*S_LEN];
__device__ __align__(16) half g_qe  [(size_t)BATCH*NH*S_LEN*DEFF];
__device__ float g_scores[(size_t)BATCH*NH*S_LEN*S_LEN];
__device__ __align__(16) half g_pr   [(size_t)BATCH*NH*S_LEN*S_LEN];
__device__ __align__(16) half g_ol   [(size_t)BATCH*NH*S_LEN*KVR];
__device__ __align__(16) half g_os   [(size_t)NTOK*NH*VDIM];
__device__ float g_cos[S_LEN*RHALF];
__device__ float g_sin[S_LEN*RHALF];

// ---------------- helpers ----------------
__device__ __forceinline__ float warpMax(float v){
    #pragma unroll
    for (int o=16;o;o>>=1) v = fmaxf(v, __shfl_xor_sync(0xffffffffu, v, o));
    return v;
}
__device__ __forceinline__ float warpSum(float v){
    #pragma unroll
    for (int o=16;o;o>>=1) v += __shfl_xor_sync(0xffffffffu, v, o);
    return v;
}
__device__ __forceinline__ uint32_t smem_u32(const void* p){
    uint32_t a;
    asm("{ .reg .u64 t; cvta.to.shared.u64 t, %1; cvt.u32.u64 %0, t; }" : "=r"(a) : "l"(p));
    return a;
}
__device__ __forceinline__ void split2(float f, bf16& h, bf16& l){
    h = __float2bfloat16_rn(f);
    l = __float2bfloat16_rn(f - __bfloat162float(h));
}
__device__ __forceinline__ void split2h(float f, half& h, half& l){
    h = __float2half_rn(f);
    l = __float2half_rn(f - __half2float(h));
}
__device__ __forceinline__ float rejoin(bf16 h, bf16 l){
    return __bfloat162float(h) + __bfloat162float(l);
}
__device__ __forceinline__ void mma_bf16(float* d, const uint32_t* a, const uint32_t* b){
    asm volatile(
        "mma.sync.aligned.m16n8k16.row.col.f32.bf16.bf16.f32 "
        "{%0,%1,%2,%3}, {%4,%5,%6,%7}, {%8,%9}, {%0,%1,%2,%3};"
        : "+f"(d[0]), "+f"(d[1]), "+f"(d[2]), "+f"(d[3])
        : "r"(a[0]), "r"(a[1]), "r"(a[2]), "r"(a[3]), "r"(b[0]), "r"(b[1]));
}
__device__ __forceinline__ void mma_f16(float* d, const uint32_t* a, const uint32_t* b){
    asm volatile(
        "mma.sync.aligned.m16n8k16.row.col.f32.f16.f16.f32 "
        "{%0,%1,%2,%3}, {%4,%5,%6,%7}, {%8,%9}, {%0,%1,%2,%3};"
        : "+f"(d[0]), "+f"(d[1]), "+f"(d[2]), "+f"(d[3])
        : "r"(a[0]), "r"(a[1]), "r"(a[2]), "r"(a[3]), "r"(b[0]), "r"(b[1]));
}
__device__ __forceinline__ void ldsm4(uint32_t* r, uint32_t a){
    asm volatile("ldmatrix.sync.aligned.m8n8.x4.shared.b16 {%0,%1,%2,%3}, [%4];"
        : "=r"(r[0]), "=r"(r[1]), "=r"(r[2]), "=r"(r[3]) : "r"(a));
}
__device__ __forceinline__ void cp16(uint32_t dst, const void* src){
    asm volatile("cp.async.cg.shared.global [%0], [%1], 16;\n" :: "r"(dst), "l"(src) : "memory");
}
__device__ __forceinline__ void cp_commit(){ asm volatile("cp.async.commit_group;\n" ::: "memory"); }
template<int N>
__device__ __forceinline__ void cp_wait(){ asm volatile("cp.async.wait_group %0;\n" :: "n"(N) : "memory"); }

__device__ __forceinline__ uint32_t swz(uint32_t o){ return o ^ ((o>>3)&0x30u); }

// ---------------- fused convert/split/rope kernel ----------------
#define N4_X   (NTOK*DIM/4)
#define N4_WQ  (QOUT*DIM/4)
#define N4_WA  (KVPAD*DIM/4)
#define N4_WAV (KVOUT*DIM/4)
#define N4_WBV (NH*VDIM*KVR/4)
#define N4_WO  (DIM*NH*VDIM/4)
#define N_WBT  (NH*KVR*NOPE)
#define N_ROPE (S_LEN*RHALF)
#define N_CONV (N4_X + N4_WQ + N4_WA + N4_WBV + N4_WO + N_WBT + N_ROPE)

__global__ void mega_convert(const float4* __restrict__ x, const float4* __restrict__ wq,
                             const float4* __restrict__ wkv_a, const float* __restrict__ wkv_b,
                             const float4* __restrict__ wo, const float* __restrict__ ang)
{
    int idx = blockIdx.x*256 + threadIdx.x;
    if (idx < N4_X){
        float4 v = x[idx];
        __half2* dp = (__half2*)(g_xs_f + 4*(size_t)idx);
        __half2 a; a.x=__float2half_rn(v.x); a.y=__float2half_rn(v.y); dp[0]=a;
        __half2 b; b.x=__float2half_rn(v.z); b.y=__float2half_rn(v.w); dp[1]=b;
        return;
    }
    idx -= N4_X;
    if (idx < N4_WQ){
        float4 v = wq[idx];
        __half2* dp = (__half2*)(g_wqf + 4*(size_t)idx);
        __half2 a; a.x=__float2half_rn(v.x); a.y=__float2half_rn(v.y); dp[0]=a;
        __half2 b; b.x=__float2half_rn(v.z); b.y=__float2half_rn(v.w); dp[1]=b;
        return;
    }
    idx -= N4_WQ;
    if (idx < N4_WA){
        __half2 a,b,c,d;
        if (idx < N4_WAV){
            float4 v = wkv_a[idx];
            half h0,l0,h1,l1,h2,l2,h3,l3;
            split2h(v.x,h0,l0); split2h(v.y,h1,l1); split2h(v.z,h2,l2); split2h(v.w,h3,l3);
            a.x=h0; a.y=h1; b.x=h2; b.y=h3; c.x=l0; c.y=l1; d.x=l2; d.y=l3;
        } else {
            half z = __float2half_rn(0.f);
            a.x=z; a.y=z; b=a; c=a; d=a;
        }
        __half2* hp = (__half2*)(g_waf_h + 4*(size_t)idx);
        __half2* lp = (__half2*)(g_waf_l + 4*(size_t)idx);
        hp[0]=a; hp[1]=b; lp[0]=c; lp[1]=d;
        return;
    }
    idx -= N4_WA;
    if (idx < N4_WBV){
        int e = idx*4;
        int c = e % KVR, v = (e/KVR) % VDIM, h = e/(KVR*VDIM);
        const float4* src = (const float4*)(wkv_b + ((size_t)h*(NOPE+VDIM) + NOPE + v)*KVR + c);
        float4 w = src[0];
        __half2* dp = (__half2*)(g_wbv + 4*(size_t)idx);
        __half2 a; a.x=__float2half_rn(w.x); a.y=__float2half_rn(w.y); dp[0]=a;
        __half2 b; b.x=__float2half_rn(w.z); b.y=__float2half_rn(w.w); dp[1]=b;
        return;
    }
    idx -= N4_WBV;
    if (idx < N4_WO){
        float4 v = wo[idx];
        __half2* dp = (__half2*)(g_wof + 4*(size_t)idx);
        __half2 a; a.x=__float2half_rn(v.x); a.y=__float2half_rn(v.y); dp[0]=a;
        __half2 b; b.x=__float2half_rn(v.z); b.y=__float2half_rn(v.w); dp[1]=b;
        return;
    }
    idx -= N4_WO;
    if (idx < N_WBT){
        int d = idx % NOPE, c = (idx/NOPE) % KVR, h = idx/(NOPE*KVR);
        float v = wkv_b[((size_t)h*(NOPE+VDIM) + d)*KVR + c];
        split2h(v, g_wbTf_h[idx], g_wbTf_l[idx]);
        return;
    }
    idx -= N_WBT;
    if (idx < N_ROPE){
        float a = ang[idx];
        g_cos[idx] = cosf(a);
        g_sin[idx] = sinf(a);
    }
}

// ---------------- prep kernels ----------------
__global__ void prep_keff_kernel(const float* __restrict__ kvw){
    int t = blockIdx.x;
    int s = t % S_LEN;
    int tid = threadIdx.x;
    float v[4];
    #pragma unroll
    for (int j=0;j<4;j++){
        size_t idx = (size_t)t*KVPAD + 4*tid + j;
        v[j] = rejoin(g_kvs_h[idx], g_kvs_l[idx]);
    }
    float ss = v[0]*v[0]+v[1]*v[1]+v[2]*v[2]+v[3]*v[3];
    ss = warpSum(ss);
    __shared__ float red[4];
    if ((tid&31)==0) red[tid>>5] = ss;
    __syncthreads();
    float tot = red[0]+red[1]+red[2]+red[3];
    float r = rsqrtf(tot*(1.0f/KVR) + 1e-6f);
    #pragma unroll
    for (int j=0;j<4;j++){
        int c = 4*tid + j;
        g_ke[(size_t)t*DEFF + c] = __float2half_rn(v[j]*r*kvw[c]);
    }
    if (tid < RHALF){
        size_t pi = (size_t)t*KVPAD + KVR + 2*tid;
        float xr = rejoin(g_kvs_h[pi],   g_kvs_l[pi]);
        float xi = rejoin(g_kvs_h[pi+1], g_kvs_l[pi+1]);
        float c  = g_cos[s*RHALF+tid], sn = g_sin[s*RHALF+tid];
        size_t di = (size_t)t*DEFF + KVR + 2*tid;
        g_ke[di]   = __float2half_rn(xr*c - xi*sn);
        g_ke[di+1] = __float2half_rn(xr*sn + xi*c);
    }
}

// coalesced tiled transpose: ke (fp16, [tok][DEFF]) -> keT (fp16, [b][DEFF][S])
__global__ void transpose_keT(){
    __shared__ half th[32][33];
    int b = blockIdx.z;
    int c0 = blockIdx.y*32, s0 = blockIdx.x*32;
    int tx = threadIdx.x, ty = threadIdx.y;   // 32 x 8
    #pragma unroll
    for (int i=0;i<32;i+=8){
        th[ty+i][tx] = g_ke[(size_t)(b*S_LEN + s0 + ty + i)*DEFF + c0 + tx];
    }
    __syncthreads();
    #pragma unroll
    for (int i=0;i<32;i+=8){
        g_keT[((size_t)b*DEFF + c0 + ty + i)*S_LEN + s0 + tx] = th[tx][ty+i];
    }
}

// one block per token, 512 threads = 16 heads x 32 rope pairs; q stored fp16
__global__ void prep_qpe_kernel(){
    int t = blockIdx.x;
    int b = t / S_LEN, s = t % S_LEN;
    int h = threadIdx.x >> 5, i = threadIdx.x & 31;
    size_t si = (size_t)t*QOUT + h*QD + NOPE + 2*i;
    float xr = __half2float(g_qs_f[si]);
    float xi = __half2float(g_qs_f[si+1]);
    float c  = g_cos[s*RHALF+i], sn = g_sin[s*RHALF+i];
    size_t di = ((size_t)(b*NH+h)*S_LEN + s)*DEFF + KVR + 2*i;
    g_qe[di]   = __float2half_rn(xr*c - xi*sn);
    g_qe[di+1] = __float2half_rn(xr*sn + xi*c);
}

// ---------------- split GEMM with ldmatrix ----------------
// MODE 1: fp16 2p (A single fp16, B hi/lo fp16, 2 passes, 4 stages)
// MODE 2: fp16 1p (A single fp16, B single fp16, 1 pass, 4 stages)
// OUT: 0 = fp32, 1 = bf16 hi/lo planes, 2 = single fp16 plane.
// klimit also reverses the by mapping so long-K blocks start first.
template<int BN_T, int OUT, int MODE>
__global__ __launch_bounds__(256,2) void mma_gemm(
    const bf16* __restrict__ Ah, const bf16* __restrict__ Al,
    const bf16* __restrict__ Bh, const bf16* __restrict__ Bl,
    float* __restrict__ Cf, bf16* __restrict__ Ch, bf16* __restrict__ Cl,
    int K, int lda, int ldb, int ldc, int zdiv,
    ll zA1, ll zA2, ll zB1, ll zB2, ll zC1, ll zC2,
    float alpha, int causal, int klimit)
{
    const int byy = klimit ? ((int)gridDim.y - 1 - (int)blockIdx.y) : (int)blockIdx.y;
    if (causal && (int)blockIdx.x > byy) return;
    constexpr int NST = (MODE==0) ? 3 : 4;
    constexpr int NPA = (MODE==0) ? 2 : 1;
    constexpr int NPB = (MODE==2) ? 1 : 2;
    constexpr int WN  = BN_T/32;
    constexpr int WM  = 8/WN;
    constexpr int WTM = 128/WM;
    constexpr int MF  = WTM/16;
    constexpr int NF  = 4;
    constexpr int SA  = 128*64;
    constexpr int SB  = BN_T*64;
    constexpr int STG = NPA*SA + NPB*SB;

    extern __shared__ char smc[];
    const uint32_t sbase = smem_u32(smc);

    const int tid = threadIdx.x, lane = tid & 31, wid = tid >> 5;
    const int wm = wid / WN, wn = wid % WN;
    const int grp = lane >> 2, tig = lane & 3;
    const int lrow = lane & 7, sub = lane >> 3;
    const int zl = blockIdx.z % zdiv, zh = blockIdx.z / zdiv;
    const ll n0 = (ll)blockIdx.x * BN_T;

    const int aRowB = wm*WTM + ((sub&1)<<3) + lrow;
    const int aKo   = (sub>>1)<<4;
    const int bRowB = wn*32 + ((sub>>1)<<3) + lrow;
    const int bKo   = (sub&1)<<4;

    const ll aoff = zl*zA1 + zh*zA2 + (ll)byy*128*lda;
    const bf16* Ahb = Ah + aoff;
    const bf16* Alb = Al + aoff;
    const ll boff = zl*zB1 + zh*zB2 + n0*ldb;
    const bf16* Bhb = Bh + boff;
    const bf16* Blb = Bl + boff;

    int kEnd = K;
    if (klimit){ int kl = (byy + 1)*128; if (kl < kEnd) kEnd = kl; }
    const int nk = kEnd >> 5;

    float acc[MF][NF][4];
    #pragma unroll
    for (int i=0;i<MF;i++)
        #pragma unroll
        for (int j=0;j<NF;j++)
            #pragma unroll
            for (int c=0;c<4;c++) acc[i][j][c] = 0.f;

    const int row = tid >> 2, g = tid & 3;

    auto LOAD = [&](int kb){
        const int s = kb % NST;
        const uint32_t ub = sbase + (uint32_t)(s*STG);
        const ll koff = ((ll)kb << 5) + g*8;
        #pragma unroll
        for (int i=0;i<2;i++){
            int r = row + i*64;
            uint32_t o = swz((uint32_t)(r*64 + g*16));
            cp16(ub + o, Ahb + (ll)r*lda + koff);
            if (MODE==0) cp16(ub + SA + o, Alb + (ll)r*lda + koff);
        }
        const uint32_t bb = ub + NPA*SA;
        #pragma unroll
        for (int i=0;i<BN_T/64;i++){
            int r = row + i*64;
            uint32_t o = swz((uint32_t)(r*64 + g*16));
            cp16(bb + o, Bhb + (ll)r*ldb + koff);
            if (MODE!=2) cp16(bb + SB + o, Blb + (ll)r*ldb + koff);
        }
        cp_commit();
    };

    #pragma unroll
    for (int kb=0; kb<NST-1; kb++) if (kb < nk) LOAD(kb);

    for (int k=0; k<nk; k++){
        cp_wait<NST-2>();
        __syncthreads();
        if (k + NST - 1 < nk) LOAD(k + NST - 1);
        else cp_commit();

        const int s = k % NST;
        const uint32_t AH = sbase + (uint32_t)(s*STG);
        const uint32_t AL = AH + SA;
        const uint32_t BH = AH + NPA*SA;
        const uint32_t BL = BH + SB;

        #pragma unroll
        for (int kk=0; kk<2; kk++){
            const int ck = kk*32;
            uint32_t bh[2*NF], bl[2*NF];
            #pragma unroll
            for (int nfp=0; nfp<NF/2; nfp++){
                uint32_t bo = swz((uint32_t)((bRowB + nfp*16)*64 + ck + bKo));
                ldsm4(&bh[4*nfp], BH + bo);
                if (MODE!=2) ldsm4(&bl[4*nfp], BL + bo);
            }
            #pragma unroll
            for (int mf=0; mf<MF; mf++){
                uint32_t ao = swz((uint32_t)((aRowB + mf*16)*64 + ck + aKo));
                uint32_t ah[4];
                ldsm4(ah, AH + ao);
                if (MODE==2){
                    #pragma unroll
                    for (int nf=0; nf<NF; nf++) mma_f16(acc[mf][nf], ah, &bh[2*nf]);
                } else if (MODE==1){
                    #pragma unroll
                    for (int nf=0; nf<NF; nf++) mma_f16(acc[mf][nf], ah, &bh[2*nf]);
                    #pragma unroll
                    for (int nf=0; nf<NF; nf++) mma_f16(acc[mf][nf], ah, &bl[2*nf]);
                } else {
                    uint32_t al[4];
                    ldsm4(al, AL + ao);
                    #pragma unroll
                    for (int nf=0; nf<NF; nf++) mma_bf16(acc[mf][nf], ah, &bh[2*nf]);
                    #pragma unroll
                    for (int nf=0; nf<NF; nf++) mma_bf16(acc[mf][nf], ah, &bl[2*nf]);
                    #pragma unroll
                    for (int nf=0; nf<NF; nf++) mma_bf16(acc[mf][nf], al, &bh[2*nf]);
                }
            }
        }
    }

    // ---- epilogue ----
    const ll cbase = zl*zC1 + zh*zC2
                   + ((ll)byy*128 + wm*WTM)*ldc + n0 + wn*32;
    #pragma unroll
    for (int mf=0; mf<MF; mf++){
        int r0 = mf*16 + grp;
        #pragma unroll
        for (int nf=0; nf<NF; nf++){
            int c = nf*8 + tig*2;
            #pragma unroll
            for (int half_=0; half_<2; half_++){
                ll off = cbase + (ll)(r0 + half_*8)*ldc + c;
                float v0 = acc[mf][nf][2*half_+0]*alpha;
                float v1 = acc[mf][nf][2*half_+1]*alpha;
                if (OUT == 1){
                    bf16 h0,l0,h1,l1;
                    split2(v0,h0,l0); split2(v1,h1,l1);
                    bf162 hp; hp.x=h0; hp.y=h1;
                    bf162 lp; lp.x=l0; lp.y=l1;
                    *(bf162*)(Ch + off) = hp;
                    *(bf162*)(Cl + off) = lp;
                } else if (OUT == 2){
                    __half2 hp;
                    hp.x = __float2half_rn(v0);
                    hp.y = __float2half_rn(v1);
                    *(__half2*)((half*)Ch + off) = hp;
                } else {
                    float2 o; o.x=v0; o.y=v1;
                    *(float2*)(Cf + off) = o;
                }
            }
        }
    }
}

// ---------------- causal softmax (vectorized) -> single fp16 probs ----------------
__global__ void softmax_kernel(){
    const int s = blockIdx.x;
    const ll z = blockIdx.y;
    const float* row = g_scores + (z*S_LEN + (ll)s)*S_LEN;
    half* pr = g_pr + (z*S_LEN + (ll)s)*S_LEN;
    const int n = s + 1;
    const int nend = ((s>>7)+1)<<7;
    const int tid = threadIdx.x;

    float e[16];
    float mx = -1e30f;
    #pragma unroll
    for (int i=0;i<4;i++){
        int t4 = tid*4 + i*512;
        if (t4 < n){
            float4 v = *(const float4*)(row + t4);   // [n, nend) is valid memory (computed, masked later)
            e[4*i+0] = v.x;
            e[4*i+1] = (t4+1 < n) ? v.y : -1e30f;
            e[4*i+2] = (t4+2 < n) ? v.z : -1e30f;
            e[4*i+3] = (t4+3 < n) ? v.w : -1e30f;
        } else {
            e[4*i+0]=e[4*i+1]=e[4*i+2]=e[4*i+3] = -1e30f;
        }
        mx = fmaxf(mx, fmaxf(fmaxf(e[4*i],e[4*i+1]), fmaxf(e[4*i+2],e[4*i+3])));
    }
    mx = warpMax(mx);
    __shared__ float redm[4], reds[4];
    if ((tid&31)==0) redm[tid>>5] = mx;
    __syncthreads();
    mx = fmaxf(fmaxf(redm[0],redm[1]), fmaxf(redm[2],redm[3]));

    float sum = 0.f;
    #pragma unroll
    for (int i=0;i<16;i++){
        float v = (e[i] > -1e29f) ? exp2f(e[i] - mx) : 0.f;
        e[i] = v;
        sum += v;
    }
    sum = warpSum(sum);
    if ((tid&31)==0) reds[tid>>5] = sum;
    __syncthreads();
    sum = reds[0]+reds[1]+reds[2]+reds[3];
    const float inv = 1.0f / sum;

    #pragma unroll
    for (int i=0;i<4;i++){
        int t4 = tid*4 + i*512;
        if (t4 < nend){
            __half2 a, b;
            a.x = __float2half_rn(e[4*i+0]*inv);
            a.y = __float2half_rn(e[4*i+1]*inv);
            b.x = __float2half_rn(e[4*i+2]*inv);
            b.y = __float2half_rn(e[4*i+3]*inv);
            *(__half2*)(pr + t4)     = a;
            *(__half2*)(pr + t4 + 2) = b;
        }
    }
}

// ---------------- host side ----------------
// omode: 0 fp32, 1 bf16 hi/lo, 2 fp16 single ; mode: 1 fp16-2p, 2 fp16-1p
static void launch_g(int omode, int mode,
    const bf16* Ah, const bf16* Al, const bf16* Bh, const bf16* Bl,
    float* Cf, bf16* Ch, bf16* Cl,
    int M, int N, int K, int lda, int ldb, int ldc,
    int Z, int zdiv,
    ll zA1, ll zA2, ll zB1, ll zB2, ll zC1, ll zC2,
    float alpha, bool causal, bool klimit)
{
    dim3 grid(N/128, M/128, Z);
    int c = causal?1:0, kl = klimit?1:0;
    #define GO(O,M_) { \
        size_t sm = (size_t)((M_==0)?3:4) * ((((M_==0)?2:1) + ((M_==2)?1:2))*128*64); \
        cudaFuncSetAttribute(mma_gemm<128,O,M_>, cudaFuncAttributeMaxDynamicSharedMemorySize, (int)sm); \
        mma_gemm<128,O,M_><<<grid,256,sm>>>(Ah,Al,Bh,Bl,Cf,Ch,Cl,K,lda,ldb,ldc,zdiv,zA1,zA2,zB1,zB2,zC1,zC2,alpha,c,kl); \
        return; }
    if (mode==1 && omode==1) GO(1,1);
    if (mode==1 && omode==2) GO(2,1);
    if (mode==2 && omode==0) GO(0,2);
    if (mode==2 && omode==2) GO(2,2);
    #undef GO
}

#define SYM(p, s) cudaGetSymbolAddress((void**)&p, s)

extern "C" void kernel_launch(void* const* d_in, const int* in_sizes, int n_in,
                              void* d_out, int out_size)
{
    (void)in_sizes; (void)n_in; (void)out_size;
    const float* x      = (const float*)d_in[0];
    const float* angles = (const float*)d_in[1];
    const float* wq     = (const float*)d_in[2];
    const float* wkv_a  = (const float*)d_in[3];
    const float* wkv_b  = (const float*)d_in[4];
    const float* wo     = (const float*)d_in[5];
    const float* kvw    = (const float*)d_in[6];
    float* out = (float*)d_out;

    bf16 *kvh,*kvl;
    half *xsf,*wqf,*wafh,*wafl,*wbv,*wbTfh,*wbTfl,*wof;
    half *qsf,*ke,*keT,*qe,*pr,*ol,*os;
    float *sc;
    SYM(xsf,g_xs_f); SYM(wqf,g_wqf);
    SYM(wafh,g_waf_h); SYM(wafl,g_waf_l); SYM(wbv,g_wbv);
    SYM(wbTfh,g_wbTf_h); SYM(wbTfl,g_wbTf_l); SYM(wof,g_wof);
    SYM(qsf,g_qs_f); SYM(kvh,g_kvs_h); SYM(kvl,g_kvs_l);
    SYM(ke,g_ke); SYM(keT,g_keT);
    SYM(qe,g_qe); SYM(pr,g_pr);
    SYM(ol,g_ol); SYM(os,g_os);
    SYM(sc,g_scores);

    const double msc = 0.1*log(40.0) + 1.0;
    const float softmax_scale = (float)(pow((double)QD, -0.5)*msc*msc);
    const float score_alpha = (float)((double)softmax_scale * LOG2E);

    // 0) ONE fused convert/split/rope kernel
    mega_convert<<<(N_CONV+255)/256, 256>>>(
        (const float4*)x, (const float4*)wq, (const float4*)wkv_a, wkv_b, (const float4*)wo, angles);

    // 1) q = x(fp16) @ wq(fp16)^T  (1-pass -> fp16 single)
    launch_g(2,2, (const bf16*)xsf, 0, (const bf16*)wqf, 0, 0, (bf16*)qsf, 0,
             NTOK, QOUT, DIM, DIM, DIM, QOUT, 1,1, 0,0,0,0,0,0, 1.f,false,false);

    // 2) kv = x(fp16) @ wkv_a(fp16 hi/lo)^T  (2-pass -> bf16 hi/lo, N padded to 640)
    launch_g(1,1, (const bf16*)xsf, 0, (const bf16*)wafh, (const bf16*)wafl, 0, kvh,kvl,
             NTOK, KVPAD, DIM, DIM, DIM, KVPAD, 1,1, 0,0,0,0,0,0, 1.f,false,false);

    // 3) keff (single fp16) + keT transpose
    prep_keff_kernel<<<NTOK, 128>>>(kvw);
    transpose_keT<<<dim3(S_LEN/32, DEFF/32, BATCH), dim3(32,8)>>>();

    // 4) rope(q_pe) -> qe fp16
    prep_qpe_kernel<<<NTOK, 512>>>();

    // 5) qe[...,0:512] = q_nope(fp16) @ wbT(fp16 hi/lo)  (2-pass -> fp16 single)
    launch_g(2,1, (const bf16*)qsf, 0, (const bf16*)wbTfh, (const bf16*)wbTfl, 0, (bf16*)qe, 0,
             S_LEN, KVR, NOPE, QOUT, NOPE, DEFF, BATCH*NH, NH,
             (ll)QD, (ll)S_LEN*QOUT, (ll)KVR*NOPE, 0,
             (ll)S_LEN*DEFF, (ll)NH*S_LEN*DEFF, 1.f,false,false);

    // 6) scores = scale * qe(fp16) @ ke(fp16)^T  (1-pass, causal block-skip)
    launch_g(0,2, (const bf16*)qe, 0, (const bf16*)ke, 0, sc, 0,0,
             S_LEN, S_LEN, DEFF, DEFF, DEFF, S_LEN, BATCH*NH, NH,
             (ll)S_LEN*DEFF, (ll)NH*S_LEN*DEFF, 0, (ll)S_LEN*DEFF,
             (ll)S_LEN*S_LEN, (ll)NH*S_LEN*S_LEN, score_alpha, true, false);

    // 7) softmax -> fp16 probs (vectorized)
    softmax_kernel<<<dim3(S_LEN, BATCH*NH), 128>>>();

    // 8) olat = probs(fp16) @ keT(fp16)^T -> fp16, 1-pass, K capped, long-K-first
    launch_g(2,2, (const bf16*)pr, 0, (const bf16*)keT, 0, 0, (bf16*)ol, 0,
             S_LEN, KVR, S_LEN, S_LEN, S_LEN, KVR, BATCH*NH, NH,
             (ll)S_LEN*S_LEN, (ll)NH*S_LEN*S_LEN, 0, (ll)DEFF*S_LEN,
             (ll)S_LEN*KVR, (ll)NH*S_LEN*KVR, 1.f, false, true);

    // 9) o = olat(fp16) @ wbv(fp16)^T -> fp16, 1-pass (per (b,h), K=512)
    launch_g(2,2, (const bf16*)ol, 0, (const bf16*)wbv, 0, 0, (bf16*)os, 0,
             S_LEN, VDIM, KVR, KVR, KVR, NH*VDIM, BATCH*NH, NH,
             (ll)S_LEN*KVR, (ll)NH*S_LEN*KVR, (ll)VDIM*KVR, 0,
             (ll)VDIM, (ll)S_LEN*NH*VDIM, 1.f, false, false);

    // 10) out = o(fp16) @ wo(fp16)^T -> fp32, 1-pass
    launch_g(0,2, (const bf16*)os, 0, (const bf16*)wof, 0, out, 0,0,
             NTOK, DIM, NH*VDIM, NH*VDIM, NH*VDIM, DIM, 1,1,
             0,0,0,0,0,0, 1.f,false,false);
}